// round 3
// baseline (speedup 1.0000x reference)
#include <cuda_runtime.h>
#include <cuda_bf16.h>

namespace {
constexpr int T  = 1024;
constexpr int C  = 768;
constexpr int NH = 12;
constexpr int HD = 64;
constexpr int NE = 8;
constexpr int V  = 50257;
constexpr int C4 = 3072;
constexpr int P  = 2048;   // token-expert pairs (T * topK)
}

// ---------------- scratch (device globals; no allocation) ----------------
__device__ float g_x[T * C];
__device__ float g_xn[T * C];
__device__ float g_qkv[T * 3 * C];
__device__ float g_attno[T * C];
__device__ float g_h[P * C4];     // 25 MB
__device__ float g_y[P * C];
__device__ int   g_tope[P];
__device__ float g_tops[P];
__device__ int   g_tokpos[P];
__device__ int   g_pairtok[P];
__device__ int   g_off[NE + 1];

// ---------------- embed: x = wte[idx] + wpe ----------------
__global__ void embed_kernel(const int* __restrict__ idx,
                             const float* __restrict__ wte,
                             const float* __restrict__ wpe,
                             float* __restrict__ x)
{
    int t = blockIdx.x;
    int c = threadIdx.x * 4;
    int tok = idx[t];
    float4 a = *(const float4*)&wte[(long)tok * C + c];
    float4 b = *(const float4*)&wpe[(long)t * C + c];
    float4 r = make_float4(a.x + b.x, a.y + b.y, a.z + b.z, a.w + b.w);
    *(float4*)&x[(long)t * C + c] = r;
}

// ---------------- layernorm (gamma only, eps 1e-5) ----------------
__global__ __launch_bounds__(256) void layernorm_kernel(
    const float* __restrict__ in, float* __restrict__ out,
    const float* __restrict__ g, int rowbase)
{
    int row = rowbase + blockIdx.x;
    const float* x = in + (long)row * C;
    int tid = threadIdx.x;
    __shared__ float red[256];
    float v[3];
    float s = 0.f;
#pragma unroll
    for (int i = 0; i < 3; i++) { v[i] = x[tid + i * 256]; s += v[i]; }
    red[tid] = s; __syncthreads();
    for (int st = 128; st > 0; st >>= 1) { if (tid < st) red[tid] += red[tid + st]; __syncthreads(); }
    float mu = red[0] * (1.f / C);
    __syncthreads();
    float q = 0.f;
#pragma unroll
    for (int i = 0; i < 3; i++) { float d = v[i] - mu; q += d * d; }
    red[tid] = q; __syncthreads();
    for (int st = 128; st > 0; st >>= 1) { if (tid < st) red[tid] += red[tid + st]; __syncthreads(); }
    float var = red[0] * (1.f / C);
    float rstd = rsqrtf(var + 1e-5f);
#pragma unroll
    for (int i = 0; i < 3; i++) {
        int c = tid + i * 256;
        out[(long)row * C + c] = (v[i] - mu) * rstd * g[c];
    }
}

// ---------------- general / grouped SGEMM ----------------
// out[m, n] = sum_k A[row(m), k] * B[e][n, k]   (B row-major [N, K])
// offsets != null -> grouped-by-expert along blockIdx.z; gather != null -> A row indirection.
constexpr int BM = 64, BN = 64, BK = 16;

__global__ __launch_bounds__(256) void sgemm_kernel(
    const float* __restrict__ Abase, int lda,
    const float* __restrict__ Bbase, long bstride,
    int N, int K,
    float* Out, int ldo,
    const float* resid,
    const int* __restrict__ offsets,
    const int* __restrict__ gather,
    int M, int dogelu)
{
    int e = blockIdx.z;
    int rowbase = 0, cnt = M;
    if (offsets) { rowbase = offsets[e]; cnt = offsets[e + 1] - rowbase; }
    int m0 = blockIdx.y * BM;
    if (m0 >= cnt) return;
    int n0 = blockIdx.x * BN;
    const float* B = Bbase + (long)e * bstride;

    __shared__ __align__(16) float As[BK][BM + 4];
    __shared__ __align__(16) float Bs[BK][BN + 4];

    int tid = threadIdx.x;
    int lm[4], lk[4]; long aof[4], bof[4]; bool av[4];
#pragma unroll
    for (int i = 0; i < 4; i++) {
        int lin = tid + i * 256;
        int m = lin >> 4, kk = lin & 15;
        lm[i] = m; lk[i] = kk;
        int gm = m0 + m;
        av[i] = gm < cnt;
        int arow = 0;
        if (av[i]) arow = gather ? gather[rowbase + gm] : (rowbase + gm);
        aof[i] = (long)arow * lda + kk;
        bof[i] = (long)(n0 + m) * K + kk;
    }
    int tx = (tid & 15) * 4, ty = (tid >> 4) * 4;
    float acc[16];
#pragma unroll
    for (int i = 0; i < 16; i++) acc[i] = 0.f;

    for (int k0 = 0; k0 < K; k0 += BK) {
#pragma unroll
        for (int i = 0; i < 4; i++) {
            As[lk[i]][lm[i]] = av[i] ? Abase[aof[i] + k0] : 0.f;
            Bs[lk[i]][lm[i]] = B[bof[i] + k0];
        }
        __syncthreads();
#pragma unroll
        for (int kk = 0; kk < BK; kk++) {
            float4 a = *(const float4*)&As[kk][ty];
            float4 b = *(const float4*)&Bs[kk][tx];
            acc[0]  += a.x * b.x; acc[1]  += a.x * b.y; acc[2]  += a.x * b.z; acc[3]  += a.x * b.w;
            acc[4]  += a.y * b.x; acc[5]  += a.y * b.y; acc[6]  += a.y * b.z; acc[7]  += a.y * b.w;
            acc[8]  += a.z * b.x; acc[9]  += a.z * b.y; acc[10] += a.z * b.z; acc[11] += a.z * b.w;
            acc[12] += a.w * b.x; acc[13] += a.w * b.y; acc[14] += a.w * b.z; acc[15] += a.w * b.w;
        }
        __syncthreads();
    }
#pragma unroll
    for (int i = 0; i < 4; i++) {
        int gm = m0 + ty + i;
        if (gm >= cnt) continue;
        long orow = rowbase + gm;
        float4 r;
        float* pr = &r.x;
#pragma unroll
        for (int j = 0; j < 4; j++) {
            float vv = acc[i * 4 + j];
            if (dogelu) vv = 0.5f * vv * (1.f + erff(vv * 0.70710678118654752f));
            pr[j] = vv;
        }
        if (resid) {
            float4 rv = *(const float4*)&resid[orow * ldo + n0 + tx];
            r.x += rv.x; r.y += rv.y; r.z += rv.z; r.w += rv.w;
        }
        *(float4*)&Out[orow * ldo + n0 + tx] = r;
    }
}

// ---------------- flash-style causal attention ----------------
// block = (q-tile of 64, head); thread = one query row. K/V tiles in smem.
__global__ __launch_bounds__(64) void attn_kernel(const float* __restrict__ qkv,
                                                  float* __restrict__ out)
{
    int h  = blockIdx.y;
    int qt = blockIdx.x;
    int i  = threadIdx.x;
    int q  = qt * 64 + i;
    __shared__ __align__(16) float Ksh[64][68];
    __shared__ __align__(16) float Vsh[64][68];

    float qreg[64];
    {
        const float* qr = qkv + (long)q * (3 * C) + h * HD;
#pragma unroll
        for (int d = 0; d < 64; d += 4) {
            float4 t4 = *(const float4*)&qr[d];
            qreg[d] = t4.x; qreg[d + 1] = t4.y; qreg[d + 2] = t4.z; qreg[d + 3] = t4.w;
        }
    }
    float o[64];
#pragma unroll
    for (int d = 0; d < 64; d++) o[d] = 0.f;
    float mval = -1e30f, l = 0.f;

    int ntiles = qt + 1;
    for (int t = 0; t < ntiles; t++) {
        int j0 = t * 64;
        const float* kr = qkv + (long)(j0 + i) * (3 * C) + C + h * HD;
        const float* vr = qkv + (long)(j0 + i) * (3 * C) + 2 * C + h * HD;
#pragma unroll
        for (int d = 0; d < 64; d += 4) {
            *(float4*)&Ksh[i][d] = *(const float4*)&kr[d];
            *(float4*)&Vsh[i][d] = *(const float4*)&vr[d];
        }
        __syncthreads();
#pragma unroll
        for (int half = 0; half < 2; half++) {
            int jb = half * 32;
            int lim = q - j0 - jb;     // j' valid iff j' <= lim
            if (lim >= 0) {
                float sc[32]; float smax = -1e30f;
#pragma unroll
                for (int j = 0; j < 32; j++) {
                    float s = -1e30f;
                    if (j <= lim) {
                        s = 0.f;
                        const float* krow = Ksh[jb + j];
#pragma unroll
                        for (int d = 0; d < 64; d++) s += qreg[d] * krow[d];
                        s *= 0.125f;   // 1/sqrt(64)
                    }
                    sc[j] = s;
                    smax = fmaxf(smax, s);
                }
                float mnew = fmaxf(mval, smax);
                float corr = __expf(mval - mnew);
                l *= corr;
#pragma unroll
                for (int d = 0; d < 64; d++) o[d] *= corr;
#pragma unroll
                for (int j = 0; j < 32; j++) {
                    if (j <= lim) {
                        float p = __expf(sc[j] - mnew);
                        l += p;
                        const float* vrow = Vsh[jb + j];
#pragma unroll
                        for (int d = 0; d < 64; d += 4) {
                            float4 v4 = *(const float4*)&vrow[d];
                            o[d]     += p * v4.x;
                            o[d + 1] += p * v4.y;
                            o[d + 2] += p * v4.z;
                            o[d + 3] += p * v4.w;
                        }
                    }
                }
                mval = mnew;
            }
        }
        __syncthreads();
    }
    float inv = 1.f / l;
    float* op = out + (long)q * C + h * HD;
#pragma unroll
    for (int d = 0; d < 64; d++) op[d] = o[d] * inv;
}

// ---------------- MoE gate: logits + top-2 + softmax ----------------
__global__ __launch_bounds__(256) void gate_kernel(const float* __restrict__ xn,
                                                   const float* __restrict__ gw,
                                                   int* __restrict__ tope,
                                                   float* __restrict__ tops)
{
    int t = blockIdx.x;
    int w = threadIdx.x >> 5, lane = threadIdx.x & 31;
    const float* x  = xn + (long)t * C;
    const float* gr = gw + (long)w * C;
    float s = 0.f;
    for (int c = lane * 4; c < C; c += 128) {
        float4 a = *(const float4*)&x[c];
        float4 b = *(const float4*)&gr[c];
        s += a.x * b.x + a.y * b.y + a.z * b.z + a.w * b.w;
    }
#pragma unroll
    for (int off = 16; off; off >>= 1) s += __shfl_xor_sync(0xffffffffu, s, off);
    __shared__ float lg[NE];
    if (lane == 0) lg[w] = s;
    __syncthreads();
    if (threadIdx.x == 0) {
        int i0 = 0;
#pragma unroll
        for (int e2 = 1; e2 < NE; e2++) if (lg[e2] > lg[i0]) i0 = e2;
        int i1 = (i0 == 0) ? 1 : 0;
#pragma unroll
        for (int e2 = 0; e2 < NE; e2++) if (e2 != i0 && lg[e2] > lg[i1]) i1 = e2;
        float ex = __expf(lg[i1] - lg[i0]);
        float s0 = 1.f / (1.f + ex);
        tope[t * 2]     = i0; tope[t * 2 + 1] = i1;
        tops[t * 2]     = s0; tops[t * 2 + 1] = 1.f - s0;
    }
}

// ---------------- routing compaction (single block; int atomics only) --------
__global__ void scatter_kernel(const int* __restrict__ tope)
{
    __shared__ int cnt[NE];
    __shared__ int off[NE + 1];
    int tid = threadIdx.x;
    if (tid < NE) cnt[tid] = 0;
    __syncthreads();
    for (int p = tid; p < P; p += 256) atomicAdd(&cnt[tope[p]], 1);
    __syncthreads();
    if (tid == 0) {
        off[0] = 0;
        for (int e = 0; e < NE; e++) off[e + 1] = off[e] + cnt[e];
        for (int e = 0; e <= NE; e++) g_off[e] = off[e];
    }
    __syncthreads();
    if (tid < NE) cnt[tid] = off[tid];
    __syncthreads();
    for (int p = tid; p < P; p += 256) {
        int e2  = tope[p];
        int pos = atomicAdd(&cnt[e2], 1);
        g_pairtok[pos] = p >> 1;   // token index
        g_tokpos[p] = pos;
    }
}

// ---------------- MoE combine: x += s0*y[p0] + s1*y[p1] ----------------
__global__ __launch_bounds__(192) void combine_kernel(
    const float* __restrict__ ybuf, const float* __restrict__ tops,
    const int* __restrict__ tokpos, float* x)
{
    int t = blockIdx.x;
    int c = threadIdx.x * 4;
    int p0 = tokpos[t * 2], p1 = tokpos[t * 2 + 1];
    float w0 = tops[t * 2], w1 = tops[t * 2 + 1];
    float4 a  = *(const float4*)&ybuf[(long)p0 * C + c];
    float4 b  = *(const float4*)&ybuf[(long)p1 * C + c];
    float4 xv = *(float4*)&x[(long)t * C + c];
    xv.x += w0 * a.x + w1 * b.x;
    xv.y += w0 * a.y + w1 * b.y;
    xv.z += w0 * a.z + w1 * b.z;
    xv.w += w0 * a.w + w1 * b.w;
    *(float4*)&x[(long)t * C + c] = xv;
}

// ---------------- lm head: logits[v] = dot(x_last, wte[v]) ----------------
__global__ __launch_bounds__(256) void lmhead_kernel(
    const float* __restrict__ xn, const float* __restrict__ wte,
    float* __restrict__ out)
{
    __shared__ float4 xs[C / 4];
    const float* x = xn + (long)(T - 1) * C;
    for (int ii = threadIdx.x; ii < C / 4; ii += 256) xs[ii] = *(const float4*)&x[ii * 4];
    __syncthreads();
    int w = threadIdx.x >> 5, lane = threadIdx.x & 31;
    int v = blockIdx.x * 8 + w;
    if (v >= V) return;
    const float* wr = wte + (long)v * C;
    float s = 0.f;
    for (int c = lane; c < C / 4; c += 32) {
        float4 a = *(const float4*)&wr[c * 4];
        float4 b = xs[c];
        s += a.x * b.x + a.y * b.y + a.z * b.z + a.w * b.w;
    }
#pragma unroll
    for (int off = 16; off; off >>= 1) s += __shfl_xor_sync(0xffffffffu, s, off);
    if (lane == 0) out[v] = s;
}

// ---------------- launch ----------------
extern "C" void kernel_launch(void* const* d_in, const int* in_sizes, int n_in,
                              void* d_out, int out_size)
{
    const int*   idx   = (const int*)d_in[0];
    const float* wte   = (const float*)d_in[1];
    const float* wpe   = (const float*)d_in[2];
    const float* ln1g  = (const float*)d_in[3];
    const float* qkvw  = (const float*)d_in[4];
    const float* projw = (const float*)d_in[5];
    const float* ln2g  = (const float*)d_in[6];
    const float* gatew = (const float*)d_in[7];
    const float* w1    = (const float*)d_in[8];
    const float* w2    = (const float*)d_in[9];
    const float* lnfg  = (const float*)d_in[10];
    float* out = (float*)d_out;

    float *p_x, *p_xn, *p_qkv, *p_attno, *p_h, *p_y, *p_tops;
    int *p_tope, *p_tokpos, *p_pairtok, *p_off;
    cudaGetSymbolAddress((void**)&p_x,       g_x);
    cudaGetSymbolAddress((void**)&p_xn,      g_xn);
    cudaGetSymbolAddress((void**)&p_qkv,     g_qkv);
    cudaGetSymbolAddress((void**)&p_attno,   g_attno);
    cudaGetSymbolAddress((void**)&p_h,       g_h);
    cudaGetSymbolAddress((void**)&p_y,       g_y);
    cudaGetSymbolAddress((void**)&p_tops,    g_tops);
    cudaGetSymbolAddress((void**)&p_tope,    g_tope);
    cudaGetSymbolAddress((void**)&p_tokpos,  g_tokpos);
    cudaGetSymbolAddress((void**)&p_pairtok, g_pairtok);
    cudaGetSymbolAddress((void**)&p_off,     g_off);

    embed_kernel<<<T, C / 4>>>(idx, wte, wpe, p_x);

    for (int l = 0; l < 2; l++) {
        layernorm_kernel<<<T, 256>>>(p_x, p_xn, ln1g + (long)l * C, 0);
        sgemm_kernel<<<dim3(3 * C / BN, T / BM, 1), 256>>>(
            p_xn, C, qkvw + (long)l * 3 * C * C, 0, 3 * C, C,
            p_qkv, 3 * C, nullptr, nullptr, nullptr, T, 0);
        attn_kernel<<<dim3(T / 64, NH), 64>>>(p_qkv, p_attno);
        sgemm_kernel<<<dim3(C / BN, T / BM, 1), 256>>>(
            p_attno, C, projw + (long)l * C * C, 0, C, C,
            p_x, C, p_x, nullptr, nullptr, T, 0);

        layernorm_kernel<<<T, 256>>>(p_x, p_xn, ln2g + (long)l * C, 0);
        gate_kernel<<<T, 256>>>(p_xn, gatew + (long)l * NE * C, p_tope, p_tops);
        scatter_kernel<<<1, 256>>>(p_tope);
        sgemm_kernel<<<dim3(C4 / BN, T / BM, NE), 256>>>(
            p_xn, C, w1 + (long)l * NE * C4 * C, (long)C4 * C, C4, C,
            p_h, C4, nullptr, p_off, p_pairtok, 0, 1);
        sgemm_kernel<<<dim3(C / BN, T / BM, NE), 256>>>(
            p_h, C4, w2 + (long)l * NE * C * C4, (long)C * C4, C, C4,
            p_y, C, nullptr, p_off, nullptr, 0, 0);
        combine_kernel<<<T, C / 4>>>(p_y, p_tops, p_tokpos, p_x);
    }

    layernorm_kernel<<<1, 256>>>(p_x, p_xn, lnfg, T - 1);
    lmhead_kernel<<<(V + 7) / 8, 256>>>(p_xn, wte, out);
}

// round 4
// speedup vs baseline: 1.1483x; 1.1483x over previous
#include <cuda_runtime.h>
#include <cuda_bf16.h>

namespace {
constexpr int T  = 1024;
constexpr int C  = 768;
constexpr int NH = 12;
constexpr int HD = 64;
constexpr int NE = 8;
constexpr int V  = 50257;
constexpr int C4 = 3072;
constexpr int P  = 2048;   // token-expert pairs (T * topK)
}

// ---------------- scratch (device globals; no allocation) ----------------
__device__ float g_x[T * C];
__device__ float g_xn[T * C];
__device__ float g_qkv[T * 3 * C];
__device__ float g_attno[T * C];
__device__ float g_h[P * C4];     // 25 MB
__device__ float g_y[P * C];
__device__ int   g_tope[P];
__device__ float g_tops[P];
__device__ int   g_tokpos[P];
__device__ int   g_pairtok[P];
__device__ int   g_off[NE + 1];

// ---------------- embed: x = wte[idx] + wpe ----------------
__global__ void embed_kernel(const int* __restrict__ idx,
                             const float* __restrict__ wte,
                             const float* __restrict__ wpe,
                             float* __restrict__ x)
{
    int t = blockIdx.x;
    int c = threadIdx.x * 4;
    int tok = idx[t];
    float4 a = *(const float4*)&wte[(long)tok * C + c];
    float4 b = *(const float4*)&wpe[(long)t * C + c];
    float4 r = make_float4(a.x + b.x, a.y + b.y, a.z + b.z, a.w + b.w);
    *(float4*)&x[(long)t * C + c] = r;
}

// ---------------- layernorm (gamma only, eps 1e-5) ----------------
__global__ __launch_bounds__(256) void layernorm_kernel(
    const float* __restrict__ in, float* __restrict__ out,
    const float* __restrict__ g, int rowbase)
{
    int row = rowbase + blockIdx.x;
    const float* x = in + (long)row * C;
    int tid = threadIdx.x;
    __shared__ float red[256];
    float v[3];
    float s = 0.f;
#pragma unroll
    for (int i = 0; i < 3; i++) { v[i] = x[tid + i * 256]; s += v[i]; }
    red[tid] = s; __syncthreads();
    for (int st = 128; st > 0; st >>= 1) { if (tid < st) red[tid] += red[tid + st]; __syncthreads(); }
    float mu = red[0] * (1.f / C);
    __syncthreads();
    float q = 0.f;
#pragma unroll
    for (int i = 0; i < 3; i++) { float d = v[i] - mu; q += d * d; }
    red[tid] = q; __syncthreads();
    for (int st = 128; st > 0; st >>= 1) { if (tid < st) red[tid] += red[tid + st]; __syncthreads(); }
    float var = red[0] * (1.f / C);
    float rstd = rsqrtf(var + 1e-5f);
#pragma unroll
    for (int i = 0; i < 3; i++) {
        int c = tid + i * 256;
        out[(long)row * C + c] = (v[i] - mu) * rstd * g[c];
    }
}

// ---------------- general / grouped SGEMM ----------------
// out[m, n] = sum_k A[row(m), k] * B[e][n, k]   (B row-major [N, K])
// offsets != null -> grouped-by-expert along blockIdx.z; gather != null -> A row indirection.
constexpr int BM = 64, BN = 64, BK = 16;

__global__ __launch_bounds__(256) void sgemm_kernel(
    const float* __restrict__ Abase, int lda,
    const float* __restrict__ Bbase, long bstride,
    int N, int K,
    float* Out, int ldo,
    const float* resid,
    const int* __restrict__ offsets,
    const int* __restrict__ gather,
    int M, int dogelu)
{
    int e = blockIdx.z;
    int rowbase = 0, cnt = M;
    if (offsets) { rowbase = offsets[e]; cnt = offsets[e + 1] - rowbase; }
    int m0 = blockIdx.y * BM;
    if (m0 >= cnt) return;
    int n0 = blockIdx.x * BN;
    const float* B = Bbase + (long)e * bstride;

    __shared__ __align__(16) float As[BK][BM + 4];
    __shared__ __align__(16) float Bs[BK][BN + 4];

    int tid = threadIdx.x;
    int lm[4], lk[4]; long aof[4], bof[4]; bool av[4];
#pragma unroll
    for (int i = 0; i < 4; i++) {
        int lin = tid + i * 256;
        int m = lin >> 4, kk = lin & 15;
        lm[i] = m; lk[i] = kk;
        int gm = m0 + m;
        av[i] = gm < cnt;
        int arow = 0;
        if (av[i]) arow = gather ? gather[rowbase + gm] : (rowbase + gm);
        aof[i] = (long)arow * lda + kk;
        bof[i] = (long)(n0 + m) * K + kk;
    }
    int tx = (tid & 15) * 4, ty = (tid >> 4) * 4;
    float acc[16];
#pragma unroll
    for (int i = 0; i < 16; i++) acc[i] = 0.f;

    for (int k0 = 0; k0 < K; k0 += BK) {
#pragma unroll
        for (int i = 0; i < 4; i++) {
            As[lk[i]][lm[i]] = av[i] ? Abase[aof[i] + k0] : 0.f;
            Bs[lk[i]][lm[i]] = B[bof[i] + k0];
        }
        __syncthreads();
#pragma unroll
        for (int kk = 0; kk < BK; kk++) {
            float4 a = *(const float4*)&As[kk][ty];
            float4 b = *(const float4*)&Bs[kk][tx];
            acc[0]  += a.x * b.x; acc[1]  += a.x * b.y; acc[2]  += a.x * b.z; acc[3]  += a.x * b.w;
            acc[4]  += a.y * b.x; acc[5]  += a.y * b.y; acc[6]  += a.y * b.z; acc[7]  += a.y * b.w;
            acc[8]  += a.z * b.x; acc[9]  += a.z * b.y; acc[10] += a.z * b.z; acc[11] += a.z * b.w;
            acc[12] += a.w * b.x; acc[13] += a.w * b.y; acc[14] += a.w * b.z; acc[15] += a.w * b.w;
        }
        __syncthreads();
    }
#pragma unroll
    for (int i = 0; i < 4; i++) {
        int gm = m0 + ty + i;
        if (gm >= cnt) continue;
        long orow = rowbase + gm;
        float4 r;
        float* pr = &r.x;
#pragma unroll
        for (int j = 0; j < 4; j++) {
            float vv = acc[i * 4 + j];
            if (dogelu) vv = 0.5f * vv * (1.f + erff(vv * 0.70710678118654752f));
            pr[j] = vv;
        }
        if (resid) {
            float4 rv = *(const float4*)&resid[orow * ldo + n0 + tx];
            r.x += rv.x; r.y += rv.y; r.z += rv.z; r.w += rv.w;
        }
        *(float4*)&Out[orow * ldo + n0 + tx] = r;
    }
}

// ---------------- flash-style causal attention (4 threads per query) --------
// block = (q-tile of 32, head), 128 threads. Thread = (query, quarter of head dim).
// Scores via partial dot + 2 butterfly shuffles across the 4 d-parts.
__global__ __launch_bounds__(128) void attn_kernel(const float* __restrict__ qkv,
                                                   float* __restrict__ out)
{
    int h    = blockIdx.y;
    int qt   = blockIdx.x;          // 32-query tile
    int tid  = threadIdx.x;
    int qi   = tid >> 2;            // 0..31 query within tile
    int part = tid & 3;             // 0..3 quarter of head dim
    int q    = qt * 32 + qi;
    int warp = tid >> 5;
    int q_wmax = qt * 32 + warp * 8 + 7;   // max query handled by this warp

    __shared__ __align__(16) float Ksh[64][68];
    __shared__ __align__(16) float Vsh[64][68];

    float qreg[16];
    {
        const float* qr = qkv + (long)q * (3 * C) + h * HD + part * 16;
#pragma unroll
        for (int d = 0; d < 16; d += 4) {
            float4 t4 = *(const float4*)&qr[d];
            qreg[d] = t4.x; qreg[d + 1] = t4.y; qreg[d + 2] = t4.z; qreg[d + 3] = t4.w;
        }
    }
    float o[16];
#pragma unroll
    for (int d = 0; d < 16; d++) o[d] = 0.f;
    float mval = -1e30f, l = 0.f;

    // SMEM tile loader mapping: 2 threads per key row, 32 dims each
    int lrow = tid >> 1;
    int lhs  = (tid & 1) * 32;

    int ntiles = (qt * 32 + 31) / 64 + 1;   // block-uniform
    for (int t = 0; t < ntiles; t++) {
        int j0 = t * 64;
        {
            const float* kr = qkv + (long)(j0 + lrow) * (3 * C) + C     + h * HD + lhs;
            const float* vr = qkv + (long)(j0 + lrow) * (3 * C) + 2 * C + h * HD + lhs;
#pragma unroll
            for (int d = 0; d < 32; d += 4) {
                *(float4*)&Ksh[lrow][lhs + d] = *(const float4*)&kr[d];
                *(float4*)&Vsh[lrow][lhs + d] = *(const float4*)&vr[d];
            }
        }
        __syncthreads();

#pragma unroll
        for (int b = 0; b < 4; b++) {
            int jb = b * 16;
            if (q_wmax - j0 - jb < 0) break;     // warp-uniform exit
            int lim = q - j0 - jb;               // per-thread: key j valid iff j <= lim
            float sc[16];
            float bmax = -1e30f;
#pragma unroll
            for (int j = 0; j < 16; j++) {
                const float* krow = &Ksh[jb + j][part * 16];
                float s = 0.f;
#pragma unroll
                for (int d = 0; d < 16; d += 4) {
                    float4 k4 = *(const float4*)&krow[d];
                    s += qreg[d] * k4.x + qreg[d + 1] * k4.y
                       + qreg[d + 2] * k4.z + qreg[d + 3] * k4.w;
                }
                // combine the 4 d-parts (partners are lanes tid^1, tid^2: same warp)
                s += __shfl_xor_sync(0xffffffffu, s, 1);
                s += __shfl_xor_sync(0xffffffffu, s, 2);
                s = (j <= lim) ? s * 0.125f : -1e30f;   // 1/sqrt(64), causal mask
                sc[j] = s;
                bmax = fmaxf(bmax, s);
            }
            if (lim >= 0) {                      // this thread has >=1 valid key
                float mnew = fmaxf(mval, bmax);
                float corr = __expf(mval - mnew);
                l *= corr;
#pragma unroll
                for (int d = 0; d < 16; d++) o[d] *= corr;
#pragma unroll
                for (int j = 0; j < 16; j++) {
                    float p = __expf(sc[j] - mnew);
                    l += p;
                    const float* vrow = &Vsh[jb + j][part * 16];
#pragma unroll
                    for (int d = 0; d < 16; d += 4) {
                        float4 v4 = *(const float4*)&vrow[d];
                        o[d]     += p * v4.x;
                        o[d + 1] += p * v4.y;
                        o[d + 2] += p * v4.z;
                        o[d + 3] += p * v4.w;
                    }
                }
                mval = mnew;
            }
        }
        __syncthreads();
    }
    float inv = 1.f / l;
    float* op = out + (long)q * C + h * HD + part * 16;
#pragma unroll
    for (int d = 0; d < 16; d++) op[d] = o[d] * inv;
}

// ---------------- MoE gate: logits + top-2 + softmax ----------------
__global__ __launch_bounds__(256) void gate_kernel(const float* __restrict__ xn,
                                                   const float* __restrict__ gw,
                                                   int* __restrict__ tope,
                                                   float* __restrict__ tops)
{
    int t = blockIdx.x;
    int w = threadIdx.x >> 5, lane = threadIdx.x & 31;
    const float* x  = xn + (long)t * C;
    const float* gr = gw + (long)w * C;
    float s = 0.f;
    for (int c = lane * 4; c < C; c += 128) {
        float4 a = *(const float4*)&x[c];
        float4 b = *(const float4*)&gr[c];
        s += a.x * b.x + a.y * b.y + a.z * b.z + a.w * b.w;
    }
#pragma unroll
    for (int off = 16; off; off >>= 1) s += __shfl_xor_sync(0xffffffffu, s, off);
    __shared__ float lg[NE];
    if (lane == 0) lg[w] = s;
    __syncthreads();
    if (threadIdx.x == 0) {
        int i0 = 0;
#pragma unroll
        for (int e2 = 1; e2 < NE; e2++) if (lg[e2] > lg[i0]) i0 = e2;
        int i1 = (i0 == 0) ? 1 : 0;
#pragma unroll
        for (int e2 = 0; e2 < NE; e2++) if (e2 != i0 && lg[e2] > lg[i1]) i1 = e2;
        float ex = __expf(lg[i1] - lg[i0]);
        float s0 = 1.f / (1.f + ex);
        tope[t * 2]     = i0; tope[t * 2 + 1] = i1;
        tops[t * 2]     = s0; tops[t * 2 + 1] = 1.f - s0;
    }
}

// ---------------- routing compaction (single block; int atomics only) --------
__global__ void scatter_kernel(const int* __restrict__ tope)
{
    __shared__ int cnt[NE];
    __shared__ int off[NE + 1];
    int tid = threadIdx.x;
    if (tid < NE) cnt[tid] = 0;
    __syncthreads();
    for (int p = tid; p < P; p += 256) atomicAdd(&cnt[tope[p]], 1);
    __syncthreads();
    if (tid == 0) {
        off[0] = 0;
        for (int e = 0; e < NE; e++) off[e + 1] = off[e] + cnt[e];
        for (int e = 0; e <= NE; e++) g_off[e] = off[e];
    }
    __syncthreads();
    if (tid < NE) cnt[tid] = off[tid];
    __syncthreads();
    for (int p = tid; p < P; p += 256) {
        int e2  = tope[p];
        int pos = atomicAdd(&cnt[e2], 1);
        g_pairtok[pos] = p >> 1;   // token index
        g_tokpos[p] = pos;
    }
}

// ---------------- MoE combine: x += s0*y[p0] + s1*y[p1] ----------------
__global__ __launch_bounds__(192) void combine_kernel(
    const float* __restrict__ ybuf, const float* __restrict__ tops,
    const int* __restrict__ tokpos, float* x)
{
    int t = blockIdx.x;
    int c = threadIdx.x * 4;
    int p0 = tokpos[t * 2], p1 = tokpos[t * 2 + 1];
    float w0 = tops[t * 2], w1 = tops[t * 2 + 1];
    float4 a  = *(const float4*)&ybuf[(long)p0 * C + c];
    float4 b  = *(const float4*)&ybuf[(long)p1 * C + c];
    float4 xv = *(float4*)&x[(long)t * C + c];
    xv.x += w0 * a.x + w1 * b.x;
    xv.y += w0 * a.y + w1 * b.y;
    xv.z += w0 * a.z + w1 * b.z;
    xv.w += w0 * a.w + w1 * b.w;
    *(float4*)&x[(long)t * C + c] = xv;
}

// ---------------- lm head: logits[v] = dot(x_last, wte[v]) ----------------
__global__ __launch_bounds__(256) void lmhead_kernel(
    const float* __restrict__ xn, const float* __restrict__ wte,
    float* __restrict__ out)
{
    __shared__ float4 xs[C / 4];
    const float* x = xn + (long)(T - 1) * C;
    for (int ii = threadIdx.x; ii < C / 4; ii += 256) xs[ii] = *(const float4*)&x[ii * 4];
    __syncthreads();
    int w = threadIdx.x >> 5, lane = threadIdx.x & 31;
    int v = blockIdx.x * 8 + w;
    if (v >= V) return;
    const float* wr = wte + (long)v * C;
    float s = 0.f;
    for (int c = lane; c < C / 4; c += 32) {
        float4 a = *(const float4*)&wr[c * 4];
        float4 b = xs[c];
        s += a.x * b.x + a.y * b.y + a.z * b.z + a.w * b.w;
    }
#pragma unroll
    for (int off = 16; off; off >>= 1) s += __shfl_xor_sync(0xffffffffu, s, off);
    if (lane == 0) out[v] = s;
}

// ---------------- launch ----------------
extern "C" void kernel_launch(void* const* d_in, const int* in_sizes, int n_in,
                              void* d_out, int out_size)
{
    const int*   idx   = (const int*)d_in[0];
    const float* wte   = (const float*)d_in[1];
    const float* wpe   = (const float*)d_in[2];
    const float* ln1g  = (const float*)d_in[3];
    const float* qkvw  = (const float*)d_in[4];
    const float* projw = (const float*)d_in[5];
    const float* ln2g  = (const float*)d_in[6];
    const float* gatew = (const float*)d_in[7];
    const float* w1    = (const float*)d_in[8];
    const float* w2    = (const float*)d_in[9];
    const float* lnfg  = (const float*)d_in[10];
    float* out = (float*)d_out;

    float *p_x, *p_xn, *p_qkv, *p_attno, *p_h, *p_y, *p_tops;
    int *p_tope, *p_tokpos, *p_pairtok, *p_off;
    cudaGetSymbolAddress((void**)&p_x,       g_x);
    cudaGetSymbolAddress((void**)&p_xn,      g_xn);
    cudaGetSymbolAddress((void**)&p_qkv,     g_qkv);
    cudaGetSymbolAddress((void**)&p_attno,   g_attno);
    cudaGetSymbolAddress((void**)&p_h,       g_h);
    cudaGetSymbolAddress((void**)&p_y,       g_y);
    cudaGetSymbolAddress((void**)&p_tops,    g_tops);
    cudaGetSymbolAddress((void**)&p_tope,    g_tope);
    cudaGetSymbolAddress((void**)&p_tokpos,  g_tokpos);
    cudaGetSymbolAddress((void**)&p_pairtok, g_pairtok);
    cudaGetSymbolAddress((void**)&p_off,     g_off);

    embed_kernel<<<T, C / 4>>>(idx, wte, wpe, p_x);

    for (int l = 0; l < 2; l++) {
        layernorm_kernel<<<T, 256>>>(p_x, p_xn, ln1g + (long)l * C, 0);
        sgemm_kernel<<<dim3(3 * C / BN, T / BM, 1), 256>>>(
            p_xn, C, qkvw + (long)l * 3 * C * C, 0, 3 * C, C,
            p_qkv, 3 * C, nullptr, nullptr, nullptr, T, 0);
        attn_kernel<<<dim3(T / 32, NH), 128>>>(p_qkv, p_attno);
        sgemm_kernel<<<dim3(C / BN, T / BM, 1), 256>>>(
            p_attno, C, projw + (long)l * C * C, 0, C, C,
            p_x, C, p_x, nullptr, nullptr, T, 0);

        layernorm_kernel<<<T, 256>>>(p_x, p_xn, ln2g + (long)l * C, 0);
        gate_kernel<<<T, 256>>>(p_xn, gatew + (long)l * NE * C, p_tope, p_tops);
        scatter_kernel<<<1, 256>>>(p_tope);
        sgemm_kernel<<<dim3(C4 / BN, T / BM, NE), 256>>>(
            p_xn, C, w1 + (long)l * NE * C4 * C, (long)C4 * C, C4, C,
            p_h, C4, nullptr, p_off, p_pairtok, 0, 1);
        sgemm_kernel<<<dim3(C / BN, T / BM, NE), 256>>>(
            p_h, C4, w2 + (long)l * NE * C * C4, (long)C * C4, C, C4,
            p_y, C, nullptr, p_off, nullptr, 0, 0);
        combine_kernel<<<T, C / 4>>>(p_y, p_tops, p_tokpos, p_x);
    }

    layernorm_kernel<<<1, 256>>>(p_x, p_xn, lnfg, T - 1);
    lmhead_kernel<<<(V + 7) / 8, 256>>>(p_xn, wte, out);
}

// round 6
// speedup vs baseline: 1.2954x; 1.1282x over previous
#include <cuda_runtime.h>
#include <cuda_bf16.h>
#include <cstdint>

namespace {
constexpr int T  = 1024;
constexpr int C  = 768;
constexpr int NH = 12;
constexpr int HD = 64;
constexpr int NE = 8;
constexpr int V  = 50257;
constexpr int C4 = 3072;
constexpr int P  = 2048;   // token-expert pairs (T * topK)
}

// ---------------- scratch (device globals; no allocation) ----------------
__device__ float g_x[T * C];
__device__ float g_xn[T * C];
__device__ float g_qkv[T * 3 * C];
__device__ float g_attno[T * C];
__device__ float g_h[P * C4];     // 25 MB
__device__ float g_y[P * C];
__device__ int   g_tope[P];
__device__ float g_tops[P];
__device__ int   g_tokpos[P];
__device__ int   g_pairtok[P];
__device__ int   g_off[NE + 1];

// ---------------- embed: x = wte[idx] + wpe ----------------
__global__ void embed_kernel(const int* __restrict__ idx,
                             const float* __restrict__ wte,
                             const float* __restrict__ wpe,
                             float* __restrict__ x)
{
    int t = blockIdx.x;
    int c = threadIdx.x * 4;
    int tok = idx[t];
    float4 a = *(const float4*)&wte[(long)tok * C + c];
    float4 b = *(const float4*)&wpe[(long)t * C + c];
    float4 r = make_float4(a.x + b.x, a.y + b.y, a.z + b.z, a.w + b.w);
    *(float4*)&x[(long)t * C + c] = r;
}

// ---------------- layernorm (gamma only, eps 1e-5) ----------------
__global__ __launch_bounds__(256) void layernorm_kernel(
    const float* __restrict__ in, float* __restrict__ out,
    const float* __restrict__ g, int rowbase)
{
    int row = rowbase + blockIdx.x;
    const float* x = in + (long)row * C;
    int tid = threadIdx.x;
    __shared__ float red[256];
    float v[3];
    float s = 0.f;
#pragma unroll
    for (int i = 0; i < 3; i++) { v[i] = x[tid + i * 256]; s += v[i]; }
    red[tid] = s; __syncthreads();
    for (int st = 128; st > 0; st >>= 1) { if (tid < st) red[tid] += red[tid + st]; __syncthreads(); }
    float mu = red[0] * (1.f / C);
    __syncthreads();
    float q = 0.f;
#pragma unroll
    for (int i = 0; i < 3; i++) { float d = v[i] - mu; q += d * d; }
    red[tid] = q; __syncthreads();
    for (int st = 128; st > 0; st >>= 1) { if (tid < st) red[tid] += red[tid + st]; __syncthreads(); }
    float var = red[0] * (1.f / C);
    float rstd = rsqrtf(var + 1e-5f);
#pragma unroll
    for (int i = 0; i < 3; i++) {
        int c = tid + i * 256;
        out[(long)row * C + c] = (v[i] - mu) * rstd * g[c];
    }
}

// ---------------- 3xTF32 tensor-core GEMM (general / grouped) ----------------
// out[m, n] = sum_k A[row(m), k] * B[e][n, k]   (B row-major [N, K])
// Split precision: A = Ah + Al, B = Bh + Bl (tf32 each);
// C = Ah*Bh + Ah*Bl + Al*Bh  (error ~2^-42 per term, fp32-grade result).
constexpr int BM = 64, BN = 64, BK = 16;
constexpr int SSTR = 20;   // smem row stride (floats): conflict-free frag loads

__device__ __forceinline__ uint32_t f2tf32(float x) {
    uint32_t r;
    asm("cvt.rna.tf32.f32 %0, %1;" : "=r"(r) : "f"(x));
    return r;
}

__device__ __forceinline__ void mma_tf32(float* c, const uint32_t* a, const uint32_t* b) {
    asm volatile(
        "mma.sync.aligned.m16n8k8.row.col.f32.tf32.tf32.f32 "
        "{%0,%1,%2,%3}, {%4,%5,%6,%7}, {%8,%9}, {%0,%1,%2,%3};\n"
        : "+f"(c[0]), "+f"(c[1]), "+f"(c[2]), "+f"(c[3])
        : "r"(a[0]), "r"(a[1]), "r"(a[2]), "r"(a[3]),
          "r"(b[0]), "r"(b[1]));
}

__global__ __launch_bounds__(128) void sgemm_kernel(
    const float* __restrict__ Abase, int lda,
    const float* __restrict__ Bbase, long bstride,
    int N, int K,
    float* Out, int ldo,
    const float* resid,
    const int* __restrict__ offsets,
    const int* __restrict__ gather,
    int M, int dogelu)
{
    int e = blockIdx.z;
    int rowbase = 0, cnt = M;
    if (offsets) { rowbase = offsets[e]; cnt = offsets[e + 1] - rowbase; }
    int m0 = blockIdx.y * BM;
    if (m0 >= cnt) return;
    int n0 = blockIdx.x * BN;
    const float* B = Bbase + (long)e * bstride;

    __shared__ __align__(16) uint32_t Ah[BM][SSTR];
    __shared__ __align__(16) uint32_t Al[BM][SSTR];
    __shared__ __align__(16) uint32_t Bh[BN][SSTR];
    __shared__ __align__(16) uint32_t Bl[BN][SSTR];

    int tid  = threadIdx.x;
    int lane = tid & 31, warp = tid >> 5;
    int gid  = lane >> 2, tig = lane & 3;
    int wm   = (warp & 1) * 32;
    int wn   = (warp >> 1) * 32;

    // loader: 64 rows x 16 k-floats; 4 threads per row (float4 each)
    int lrow0 = tid >> 2;           // 0..31
    int lq    = (tid & 3) * 4;      // k offset 0/4/8/12
    long aof[2]; bool av[2]; long bof[2];
#pragma unroll
    for (int i = 0; i < 2; i++) {
        int row = lrow0 + i * 32;
        int gm  = m0 + row;
        av[i] = gm < cnt;
        int arow = 0;
        if (av[i]) arow = gather ? gather[rowbase + gm] : (rowbase + gm);
        aof[i] = (long)arow * lda + lq;
        bof[i] = (long)(n0 + row) * K + lq;
    }

    float c[2][4][4];
#pragma unroll
    for (int i = 0; i < 2; i++)
#pragma unroll
        for (int j = 0; j < 4; j++)
#pragma unroll
            for (int r = 0; r < 4; r++) c[i][j][r] = 0.f;

    for (int k0 = 0; k0 < K; k0 += BK) {
#pragma unroll
        for (int i = 0; i < 2; i++) {
            int row = lrow0 + i * 32;
            float4 a4 = av[i] ? *(const float4*)&Abase[aof[i] + k0]
                              : make_float4(0.f, 0.f, 0.f, 0.f);
            uint4 uh, ul;
            uh.x = f2tf32(a4.x); ul.x = f2tf32(a4.x - __uint_as_float(uh.x));
            uh.y = f2tf32(a4.y); ul.y = f2tf32(a4.y - __uint_as_float(uh.y));
            uh.z = f2tf32(a4.z); ul.z = f2tf32(a4.z - __uint_as_float(uh.z));
            uh.w = f2tf32(a4.w); ul.w = f2tf32(a4.w - __uint_as_float(uh.w));
            *(uint4*)&Ah[row][lq] = uh;
            *(uint4*)&Al[row][lq] = ul;
            float4 b4 = *(const float4*)&B[bof[i] + k0];
            uh.x = f2tf32(b4.x); ul.x = f2tf32(b4.x - __uint_as_float(uh.x));
            uh.y = f2tf32(b4.y); ul.y = f2tf32(b4.y - __uint_as_float(uh.y));
            uh.z = f2tf32(b4.z); ul.z = f2tf32(b4.z - __uint_as_float(uh.z));
            uh.w = f2tf32(b4.w); ul.w = f2tf32(b4.w - __uint_as_float(uh.w));
            *(uint4*)&Bh[row][lq] = uh;
            *(uint4*)&Bl[row][lq] = ul;
        }
        __syncthreads();
#pragma unroll
        for (int kk = 0; kk < BK; kk += 8) {
            uint32_t ah[2][4], al[2][4], bh[4][2], bl[4][2];
#pragma unroll
            for (int i = 0; i < 2; i++) {
                int r0 = wm + i * 16 + gid;
                ah[i][0] = Ah[r0][kk + tig];
                ah[i][1] = Ah[r0 + 8][kk + tig];
                ah[i][2] = Ah[r0][kk + tig + 4];
                ah[i][3] = Ah[r0 + 8][kk + tig + 4];
                al[i][0] = Al[r0][kk + tig];
                al[i][1] = Al[r0 + 8][kk + tig];
                al[i][2] = Al[r0][kk + tig + 4];
                al[i][3] = Al[r0 + 8][kk + tig + 4];
            }
#pragma unroll
            for (int j = 0; j < 4; j++) {
                int rn = wn + j * 8 + gid;
                bh[j][0] = Bh[rn][kk + tig];
                bh[j][1] = Bh[rn][kk + tig + 4];
                bl[j][0] = Bl[rn][kk + tig];
                bl[j][1] = Bl[rn][kk + tig + 4];
            }
#pragma unroll
            for (int i = 0; i < 2; i++)
#pragma unroll
                for (int j = 0; j < 4; j++) {
                    mma_tf32(c[i][j], al[i], bh[j]);   // small terms first
                    mma_tf32(c[i][j], ah[i], bl[j]);
                    mma_tf32(c[i][j], ah[i], bh[j]);
                }
        }
        __syncthreads();
    }

    // epilogue: c[i][j] = {(gid, 2tig), (gid, 2tig+1), (gid+8, 2tig), (gid+8, 2tig+1)}
#pragma unroll
    for (int i = 0; i < 2; i++) {
#pragma unroll
        for (int half = 0; half < 2; half++) {
            int gm = m0 + wm + i * 16 + gid + half * 8;
            if (gm >= cnt) continue;
            long orow = rowbase + gm;
#pragma unroll
            for (int j = 0; j < 4; j++) {
                int col = n0 + wn + j * 8 + 2 * tig;
                float v0 = c[i][j][half * 2];
                float v1 = c[i][j][half * 2 + 1];
                if (dogelu) {
                    v0 = 0.5f * v0 * (1.f + erff(v0 * 0.70710678118654752f));
                    v1 = 0.5f * v1 * (1.f + erff(v1 * 0.70710678118654752f));
                }
                if (resid) {
                    float2 rv = *(const float2*)&resid[orow * ldo + col];
                    v0 += rv.x; v1 += rv.y;
                }
                float2 r2 = make_float2(v0, v1);
                *(float2*)&Out[orow * ldo + col] = r2;
            }
        }
    }
}

// ---------------- flash-style causal attention (4 threads per query) --------
// block = (q-tile of 32, head), 128 threads. Thread = (query, quarter of head dim).
// Scores via partial dot + 2 butterfly shuffles across the 4 d-parts.
__global__ __launch_bounds__(128) void attn_kernel(const float* __restrict__ qkv,
                                                   float* __restrict__ out)
{
    int h    = blockIdx.y;
    int qt   = blockIdx.x;          // 32-query tile
    int tid  = threadIdx.x;
    int qi   = tid >> 2;            // 0..31 query within tile
    int part = tid & 3;             // 0..3 quarter of head dim
    int q    = qt * 32 + qi;
    int warp = tid >> 5;
    int q_wmax = qt * 32 + warp * 8 + 7;   // max query handled by this warp

    __shared__ __align__(16) float Ksh[64][68];
    __shared__ __align__(16) float Vsh[64][68];

    float qreg[16];
    {
        const float* qr = qkv + (long)q * (3 * C) + h * HD + part * 16;
#pragma unroll
        for (int d = 0; d < 16; d += 4) {
            float4 t4 = *(const float4*)&qr[d];
            qreg[d] = t4.x; qreg[d + 1] = t4.y; qreg[d + 2] = t4.z; qreg[d + 3] = t4.w;
        }
    }
    float o[16];
#pragma unroll
    for (int d = 0; d < 16; d++) o[d] = 0.f;
    float mval = -1e30f, l = 0.f;

    // SMEM tile loader mapping: 2 threads per key row, 32 dims each
    int lrow = tid >> 1;
    int lhs  = (tid & 1) * 32;

    int ntiles = (qt * 32 + 31) / 64 + 1;   // block-uniform
    for (int t = 0; t < ntiles; t++) {
        int j0 = t * 64;
        {
            const float* kr = qkv + (long)(j0 + lrow) * (3 * C) + C     + h * HD + lhs;
            const float* vr = qkv + (long)(j0 + lrow) * (3 * C) + 2 * C + h * HD + lhs;
#pragma unroll
            for (int d = 0; d < 32; d += 4) {
                *(float4*)&Ksh[lrow][lhs + d] = *(const float4*)&kr[d];
                *(float4*)&Vsh[lrow][lhs + d] = *(const float4*)&vr[d];
            }
        }
        __syncthreads();

#pragma unroll
        for (int b = 0; b < 4; b++) {
            int jb = b * 16;
            if (q_wmax - j0 - jb < 0) break;     // warp-uniform exit
            int lim = q - j0 - jb;               // per-thread: key j valid iff j <= lim
            float sc[16];
            float bmax = -1e30f;
#pragma unroll
            for (int j = 0; j < 16; j++) {
                const float* krow = &Ksh[jb + j][part * 16];
                float s = 0.f;
#pragma unroll
                for (int d = 0; d < 16; d += 4) {
                    float4 k4 = *(const float4*)&krow[d];
                    s += qreg[d] * k4.x + qreg[d + 1] * k4.y
                       + qreg[d + 2] * k4.z + qreg[d + 3] * k4.w;
                }
                // combine the 4 d-parts (partners are lanes tid^1, tid^2: same warp)
                s += __shfl_xor_sync(0xffffffffu, s, 1);
                s += __shfl_xor_sync(0xffffffffu, s, 2);
                s = (j <= lim) ? s * 0.125f : -1e30f;   // 1/sqrt(64), causal mask
                sc[j] = s;
                bmax = fmaxf(bmax, s);
            }
            if (lim >= 0) {                      // this thread has >=1 valid key
                float mnew = fmaxf(mval, bmax);
                float corr = __expf(mval - mnew);
                l *= corr;
#pragma unroll
                for (int d = 0; d < 16; d++) o[d] *= corr;
#pragma unroll
                for (int j = 0; j < 16; j++) {
                    float p = __expf(sc[j] - mnew);
                    l += p;
                    const float* vrow = &Vsh[jb + j][part * 16];
#pragma unroll
                    for (int d = 0; d < 16; d += 4) {
                        float4 v4 = *(const float4*)&vrow[d];
                        o[d]     += p * v4.x;
                        o[d + 1] += p * v4.y;
                        o[d + 2] += p * v4.z;
                        o[d + 3] += p * v4.w;
                    }
                }
                mval = mnew;
            }
        }
        __syncthreads();
    }
    float inv = 1.f / l;
    float* op = out + (long)q * C + h * HD + part * 16;
#pragma unroll
    for (int d = 0; d < 16; d++) op[d] = o[d] * inv;
}

// ---------------- MoE gate: logits + top-2 + softmax ----------------
__global__ __launch_bounds__(256) void gate_kernel(const float* __restrict__ xn,
                                                   const float* __restrict__ gw,
                                                   int* __restrict__ tope,
                                                   float* __restrict__ tops)
{
    int t = blockIdx.x;
    int w = threadIdx.x >> 5, lane = threadIdx.x & 31;
    const float* x  = xn + (long)t * C;
    const float* gr = gw + (long)w * C;
    float s = 0.f;
    for (int c = lane * 4; c < C; c += 128) {
        float4 a = *(const float4*)&x[c];
        float4 b = *(const float4*)&gr[c];
        s += a.x * b.x + a.y * b.y + a.z * b.z + a.w * b.w;
    }
#pragma unroll
    for (int off = 16; off; off >>= 1) s += __shfl_xor_sync(0xffffffffu, s, off);
    __shared__ float lg[NE];
    if (lane == 0) lg[w] = s;
    __syncthreads();
    if (threadIdx.x == 0) {
        int i0 = 0;
#pragma unroll
        for (int e2 = 1; e2 < NE; e2++) if (lg[e2] > lg[i0]) i0 = e2;
        int i1 = (i0 == 0) ? 1 : 0;
#pragma unroll
        for (int e2 = 0; e2 < NE; e2++) if (e2 != i0 && lg[e2] > lg[i1]) i1 = e2;
        float ex = __expf(lg[i1] - lg[i0]);
        float s0 = 1.f / (1.f + ex);
        tope[t * 2]     = i0; tope[t * 2 + 1] = i1;
        tops[t * 2]     = s0; tops[t * 2 + 1] = 1.f - s0;
    }
}

// ---------------- routing compaction (single block; int atomics only) --------
__global__ void scatter_kernel(const int* __restrict__ tope)
{
    __shared__ int cnt[NE];
    __shared__ int off[NE + 1];
    int tid = threadIdx.x;
    if (tid < NE) cnt[tid] = 0;
    __syncthreads();
    for (int p = tid; p < P; p += 256) atomicAdd(&cnt[tope[p]], 1);
    __syncthreads();
    if (tid == 0) {
        off[0] = 0;
        for (int e = 0; e < NE; e++) off[e + 1] = off[e] + cnt[e];
        for (int e = 0; e <= NE; e++) g_off[e] = off[e];
    }
    __syncthreads();
    if (tid < NE) cnt[tid] = off[tid];
    __syncthreads();
    for (int p = tid; p < P; p += 256) {
        int e2  = tope[p];
        int pos = atomicAdd(&cnt[e2], 1);
        g_pairtok[pos] = p >> 1;   // token index
        g_tokpos[p] = pos;
    }
}

// ---------------- MoE combine: x += s0*y[p0] + s1*y[p1] ----------------
__global__ __launch_bounds__(192) void combine_kernel(
    const float* __restrict__ ybuf, const float* __restrict__ tops,
    const int* __restrict__ tokpos, float* x)
{
    int t = blockIdx.x;
    int c = threadIdx.x * 4;
    int p0 = tokpos[t * 2], p1 = tokpos[t * 2 + 1];
    float w0 = tops[t * 2], w1 = tops[t * 2 + 1];
    float4 a  = *(const float4*)&ybuf[(long)p0 * C + c];
    float4 b  = *(const float4*)&ybuf[(long)p1 * C + c];
    float4 xv = *(float4*)&x[(long)t * C + c];
    xv.x += w0 * a.x + w1 * b.x;
    xv.y += w0 * a.y + w1 * b.y;
    xv.z += w0 * a.z + w1 * b.z;
    xv.w += w0 * a.w + w1 * b.w;
    *(float4*)&x[(long)t * C + c] = xv;
}

// ---------------- lm head: logits[v] = dot(x_last, wte[v]) ----------------
__global__ __launch_bounds__(256) void lmhead_kernel(
    const float* __restrict__ xn, const float* __restrict__ wte,
    float* __restrict__ out)
{
    __shared__ float4 xs[C / 4];
    const float* x = xn + (long)(T - 1) * C;
    for (int ii = threadIdx.x; ii < C / 4; ii += 256) xs[ii] = *(const float4*)&x[ii * 4];
    __syncthreads();
    int w = threadIdx.x >> 5, lane = threadIdx.x & 31;
    int v = blockIdx.x * 8 + w;
    if (v >= V) return;
    const float* wr = wte + (long)v * C;
    float s = 0.f;
    for (int c = lane; c < C / 4; c += 32) {
        float4 a = *(const float4*)&wr[c * 4];
        float4 b = xs[c];
        s += a.x * b.x + a.y * b.y + a.z * b.z + a.w * b.w;
    }
#pragma unroll
    for (int off = 16; off; off >>= 1) s += __shfl_xor_sync(0xffffffffu, s, off);
    if (lane == 0) out[v] = s;
}

// ---------------- launch ----------------
extern "C" void kernel_launch(void* const* d_in, const int* in_sizes, int n_in,
                              void* d_out, int out_size)
{
    const int*   idx   = (const int*)d_in[0];
    const float* wte   = (const float*)d_in[1];
    const float* wpe   = (const float*)d_in[2];
    const float* ln1g  = (const float*)d_in[3];
    const float* qkvw  = (const float*)d_in[4];
    const float* projw = (const float*)d_in[5];
    const float* ln2g  = (const float*)d_in[6];
    const float* gatew = (const float*)d_in[7];
    const float* w1    = (const float*)d_in[8];
    const float* w2    = (const float*)d_in[9];
    const float* lnfg  = (const float*)d_in[10];
    float* out = (float*)d_out;

    float *p_x, *p_xn, *p_qkv, *p_attno, *p_h, *p_y, *p_tops;
    int *p_tope, *p_tokpos, *p_pairtok, *p_off;
    cudaGetSymbolAddress((void**)&p_x,       g_x);
    cudaGetSymbolAddress((void**)&p_xn,      g_xn);
    cudaGetSymbolAddress((void**)&p_qkv,     g_qkv);
    cudaGetSymbolAddress((void**)&p_attno,   g_attno);
    cudaGetSymbolAddress((void**)&p_h,       g_h);
    cudaGetSymbolAddress((void**)&p_y,       g_y);
    cudaGetSymbolAddress((void**)&p_tops,    g_tops);
    cudaGetSymbolAddress((void**)&p_tope,    g_tope);
    cudaGetSymbolAddress((void**)&p_tokpos,  g_tokpos);
    cudaGetSymbolAddress((void**)&p_pairtok, g_pairtok);
    cudaGetSymbolAddress((void**)&p_off,     g_off);

    embed_kernel<<<T, C / 4>>>(idx, wte, wpe, p_x);

    for (int l = 0; l < 2; l++) {
        layernorm_kernel<<<T, 256>>>(p_x, p_xn, ln1g + (long)l * C, 0);
        sgemm_kernel<<<dim3(3 * C / BN, T / BM, 1), 128>>>(
            p_xn, C, qkvw + (long)l * 3 * C * C, 0, 3 * C, C,
            p_qkv, 3 * C, nullptr, nullptr, nullptr, T, 0);
        attn_kernel<<<dim3(T / 32, NH), 128>>>(p_qkv, p_attno);
        sgemm_kernel<<<dim3(C / BN, T / BM, 1), 128>>>(
            p_attno, C, projw + (long)l * C * C, 0, C, C,
            p_x, C, p_x, nullptr, nullptr, T, 0);

        layernorm_kernel<<<T, 256>>>(p_x, p_xn, ln2g + (long)l * C, 0);
        gate_kernel<<<T, 256>>>(p_xn, gatew + (long)l * NE * C, p_tope, p_tops);
        scatter_kernel<<<1, 256>>>(p_tope);
        sgemm_kernel<<<dim3(C4 / BN, T / BM, NE), 128>>>(
            p_xn, C, w1 + (long)l * NE * C4 * C, (long)C4 * C, C4, C,
            p_h, C4, nullptr, p_off, p_pairtok, 0, 1);
        sgemm_kernel<<<dim3(C / BN, T / BM, NE), 128>>>(
            p_h, C4, w2 + (long)l * NE * C * C4, (long)C * C4, C, C4,
            p_y, C, nullptr, p_off, nullptr, 0, 0);
        combine_kernel<<<T, C / 4>>>(p_y, p_tops, p_tokpos, p_x);
    }

    layernorm_kernel<<<1, 256>>>(p_x, p_xn, lnfg, T - 1);
    lmhead_kernel<<<(V + 7) / 8, 256>>>(p_xn, wte, out);
}

// round 7
// speedup vs baseline: 1.6517x; 1.2750x over previous
#include <cuda_runtime.h>
#include <cuda_bf16.h>
#include <cstdint>

namespace {
constexpr int T  = 1024;
constexpr int C  = 768;
constexpr int NH = 12;
constexpr int HD = 64;
constexpr int NE = 8;
constexpr int V  = 50257;
constexpr int C4 = 3072;
constexpr int P  = 2048;   // token-expert pairs (T * topK)
constexpr int ATTN_SMEM = (6 * 64 * 68 + 4 * 16 * 68) * 4;   // 121856 B
}

// ---------------- scratch (device globals; no allocation) ----------------
__device__ float g_x[T * C];
__device__ float g_xn[T * C];
__device__ float g_qkv[T * 3 * C];
__device__ float g_attno[T * C];
__device__ float g_h[P * C4];     // 25 MB
__device__ float g_y[P * C];
__device__ int   g_tope[P];
__device__ float g_tops[P];
__device__ int   g_tokpos[P];
__device__ int   g_pairtok[P];
__device__ int   g_off[NE + 1];

// ---------------- embed: x = wte[idx] + wpe ----------------
__global__ void embed_kernel(const int* __restrict__ idx,
                             const float* __restrict__ wte,
                             const float* __restrict__ wpe,
                             float* __restrict__ x)
{
    int t = blockIdx.x;
    int c = threadIdx.x * 4;
    int tok = idx[t];
    float4 a = *(const float4*)&wte[(long)tok * C + c];
    float4 b = *(const float4*)&wpe[(long)t * C + c];
    float4 r = make_float4(a.x + b.x, a.y + b.y, a.z + b.z, a.w + b.w);
    *(float4*)&x[(long)t * C + c] = r;
}

// ---------------- layernorm (gamma only, eps 1e-5) ----------------
__global__ __launch_bounds__(256) void layernorm_kernel(
    const float* __restrict__ in, float* __restrict__ out,
    const float* __restrict__ g, int rowbase)
{
    int row = rowbase + blockIdx.x;
    const float* x = in + (long)row * C;
    int tid = threadIdx.x;
    __shared__ float red[256];
    float v[3];
    float s = 0.f;
#pragma unroll
    for (int i = 0; i < 3; i++) { v[i] = x[tid + i * 256]; s += v[i]; }
    red[tid] = s; __syncthreads();
    for (int st = 128; st > 0; st >>= 1) { if (tid < st) red[tid] += red[tid + st]; __syncthreads(); }
    float mu = red[0] * (1.f / C);
    __syncthreads();
    float q = 0.f;
#pragma unroll
    for (int i = 0; i < 3; i++) { float d = v[i] - mu; q += d * d; }
    red[tid] = q; __syncthreads();
    for (int st = 128; st > 0; st >>= 1) { if (tid < st) red[tid] += red[tid + st]; __syncthreads(); }
    float var = red[0] * (1.f / C);
    float rstd = rsqrtf(var + 1e-5f);
#pragma unroll
    for (int i = 0; i < 3; i++) {
        int c = tid + i * 256;
        out[(long)row * C + c] = (v[i] - mu) * rstd * g[c];
    }
}

// ---------------- tf32 helpers ----------------
__device__ __forceinline__ uint32_t f2tf32(float x) {
    uint32_t r;
    asm("cvt.rna.tf32.f32 %0, %1;" : "=r"(r) : "f"(x));
    return r;
}

__device__ __forceinline__ void mma_tf32(float* c, const uint32_t* a, const uint32_t* b) {
    asm volatile(
        "mma.sync.aligned.m16n8k8.row.col.f32.tf32.tf32.f32 "
        "{%0,%1,%2,%3}, {%4,%5,%6,%7}, {%8,%9}, {%0,%1,%2,%3};\n"
        : "+f"(c[0]), "+f"(c[1]), "+f"(c[2]), "+f"(c[3])
        : "r"(a[0]), "r"(a[1]), "r"(a[2]), "r"(a[3]),
          "r"(b[0]), "r"(b[1]));
}

__device__ __forceinline__ void hilo(float x, float& h, float& l) {
    h = __uint_as_float(f2tf32(x));
    l = __uint_as_float(f2tf32(x - h));
}

// ---------------- 3xTF32 tensor-core GEMM (general / grouped) ----------------
// out[m, n] = sum_k A[row(m), k] * B[e][n, k]   (B row-major [N, K])
constexpr int BM = 64, BN = 64, BK = 16;
constexpr int SSTR = 20;   // smem row stride (floats): conflict-free frag loads

__global__ __launch_bounds__(128) void sgemm_kernel(
    const float* __restrict__ Abase, int lda,
    const float* __restrict__ Bbase, long bstride,
    int N, int K,
    float* Out, int ldo,
    const float* resid,
    const int* __restrict__ offsets,
    const int* __restrict__ gather,
    int M, int dogelu)
{
    int e = blockIdx.z;
    int rowbase = 0, cnt = M;
    if (offsets) { rowbase = offsets[e]; cnt = offsets[e + 1] - rowbase; }
    int m0 = blockIdx.y * BM;
    if (m0 >= cnt) return;
    int n0 = blockIdx.x * BN;
    const float* B = Bbase + (long)e * bstride;

    __shared__ __align__(16) uint32_t Ah[BM][SSTR];
    __shared__ __align__(16) uint32_t Al[BM][SSTR];
    __shared__ __align__(16) uint32_t Bh[BN][SSTR];
    __shared__ __align__(16) uint32_t Bl[BN][SSTR];

    int tid  = threadIdx.x;
    int lane = tid & 31, warp = tid >> 5;
    int gid  = lane >> 2, tig = lane & 3;
    int wm   = (warp & 1) * 32;
    int wn   = (warp >> 1) * 32;

    int lrow0 = tid >> 2;           // 0..31
    int lq    = (tid & 3) * 4;      // k offset 0/4/8/12
    long aof[2]; bool av[2]; long bof[2];
#pragma unroll
    for (int i = 0; i < 2; i++) {
        int row = lrow0 + i * 32;
        int gm  = m0 + row;
        av[i] = gm < cnt;
        int arow = 0;
        if (av[i]) arow = gather ? gather[rowbase + gm] : (rowbase + gm);
        aof[i] = (long)arow * lda + lq;
        bof[i] = (long)(n0 + row) * K + lq;
    }

    float c[2][4][4];
#pragma unroll
    for (int i = 0; i < 2; i++)
#pragma unroll
        for (int j = 0; j < 4; j++)
#pragma unroll
            for (int r = 0; r < 4; r++) c[i][j][r] = 0.f;

    for (int k0 = 0; k0 < K; k0 += BK) {
#pragma unroll
        for (int i = 0; i < 2; i++) {
            int row = lrow0 + i * 32;
            float4 a4 = av[i] ? *(const float4*)&Abase[aof[i] + k0]
                              : make_float4(0.f, 0.f, 0.f, 0.f);
            uint4 uh, ul;
            uh.x = f2tf32(a4.x); ul.x = f2tf32(a4.x - __uint_as_float(uh.x));
            uh.y = f2tf32(a4.y); ul.y = f2tf32(a4.y - __uint_as_float(uh.y));
            uh.z = f2tf32(a4.z); ul.z = f2tf32(a4.z - __uint_as_float(uh.z));
            uh.w = f2tf32(a4.w); ul.w = f2tf32(a4.w - __uint_as_float(uh.w));
            *(uint4*)&Ah[row][lq] = uh;
            *(uint4*)&Al[row][lq] = ul;
            float4 b4 = *(const float4*)&B[bof[i] + k0];
            uh.x = f2tf32(b4.x); ul.x = f2tf32(b4.x - __uint_as_float(uh.x));
            uh.y = f2tf32(b4.y); ul.y = f2tf32(b4.y - __uint_as_float(uh.y));
            uh.z = f2tf32(b4.z); ul.z = f2tf32(b4.z - __uint_as_float(uh.z));
            uh.w = f2tf32(b4.w); ul.w = f2tf32(b4.w - __uint_as_float(uh.w));
            *(uint4*)&Bh[row][lq] = uh;
            *(uint4*)&Bl[row][lq] = ul;
        }
        __syncthreads();
#pragma unroll
        for (int kk = 0; kk < BK; kk += 8) {
            uint32_t ah[2][4], al[2][4], bh[4][2], bl[4][2];
#pragma unroll
            for (int i = 0; i < 2; i++) {
                int r0 = wm + i * 16 + gid;
                ah[i][0] = Ah[r0][kk + tig];
                ah[i][1] = Ah[r0 + 8][kk + tig];
                ah[i][2] = Ah[r0][kk + tig + 4];
                ah[i][3] = Ah[r0 + 8][kk + tig + 4];
                al[i][0] = Al[r0][kk + tig];
                al[i][1] = Al[r0 + 8][kk + tig];
                al[i][2] = Al[r0][kk + tig + 4];
                al[i][3] = Al[r0 + 8][kk + tig + 4];
            }
#pragma unroll
            for (int j = 0; j < 4; j++) {
                int rn = wn + j * 8 + gid;
                bh[j][0] = Bh[rn][kk + tig];
                bh[j][1] = Bh[rn][kk + tig + 4];
                bl[j][0] = Bl[rn][kk + tig];
                bl[j][1] = Bl[rn][kk + tig + 4];
            }
#pragma unroll
            for (int i = 0; i < 2; i++)
#pragma unroll
                for (int j = 0; j < 4; j++) {
                    mma_tf32(c[i][j], al[i], bh[j]);   // small terms first
                    mma_tf32(c[i][j], ah[i], bl[j]);
                    mma_tf32(c[i][j], ah[i], bh[j]);
                }
        }
        __syncthreads();
    }

#pragma unroll
    for (int i = 0; i < 2; i++) {
#pragma unroll
        for (int half = 0; half < 2; half++) {
            int gm = m0 + wm + i * 16 + gid + half * 8;
            if (gm >= cnt) continue;
            long orow = rowbase + gm;
#pragma unroll
            for (int j = 0; j < 4; j++) {
                int col = n0 + wn + j * 8 + 2 * tig;
                float v0 = c[i][j][half * 2];
                float v1 = c[i][j][half * 2 + 1];
                if (dogelu) {
                    v0 = 0.5f * v0 * (1.f + erff(v0 * 0.70710678118654752f));
                    v1 = 0.5f * v1 * (1.f + erff(v1 * 0.70710678118654752f));
                }
                if (resid) {
                    float2 rv = *(const float2*)&resid[orow * ldo + col];
                    v0 += rv.x; v1 += rv.y;
                }
                float2 r2 = make_float2(v0, v1);
                *(float2*)&Out[orow * ldo + col] = r2;
            }
        }
    }
}

// ---------------- tensor-core flash attention (3xTF32) ----------------
// block = (64-query tile, head), 4 warps; warp w owns query rows 16w..16w+15.
// S = Q K^T via m16n8k8; online softmax in fragments; P via per-warp smem; P·V via MMA.
__global__ __launch_bounds__(128) void attn_kernel(const float* __restrict__ qkv,
                                                   float* __restrict__ out)
{
    extern __shared__ float sm[];
    float (*Qh)[68] = (float(*)[68])(sm);
    float (*Ql)[68] = (float(*)[68])(sm + 64 * 68);
    float (*Kh)[68] = (float(*)[68])(sm + 2 * 64 * 68);
    float (*Kl)[68] = (float(*)[68])(sm + 3 * 64 * 68);
    float (*Vh)[68] = (float(*)[68])(sm + 4 * 64 * 68);   // transposed [d][j]
    float (*Vl)[68] = (float(*)[68])(sm + 5 * 64 * 68);

    int h    = blockIdx.y;
    int qt   = (int)gridDim.x - 1 - (int)blockIdx.x;   // big tiles first
    int tid  = threadIdx.x;
    int warp = tid >> 5, lane = tid & 31;
    int gid  = lane >> 2, tig = lane & 3;

    float (*Psw)[68] = (float(*)[68])(sm + 6 * 64 * 68 + warp * 16 * 68);

    int lrow = tid >> 1;
    int lhs  = (tid & 1) * 32;

    // load Q tile (64 x 64) -> hi/lo
    {
        const float* qr = qkv + (long)(qt * 64 + lrow) * (3 * C) + h * HD + lhs;
#pragma unroll
        for (int d = 0; d < 32; d += 4) {
            float4 q4 = *(const float4*)&qr[d];
            float hh, ll;
            hilo(q4.x, hh, ll); Qh[lrow][lhs + d]     = hh; Ql[lrow][lhs + d]     = ll;
            hilo(q4.y, hh, ll); Qh[lrow][lhs + d + 1] = hh; Ql[lrow][lhs + d + 1] = ll;
            hilo(q4.z, hh, ll); Qh[lrow][lhs + d + 2] = hh; Ql[lrow][lhs + d + 2] = ll;
            hilo(q4.w, hh, ll); Qh[lrow][lhs + d + 3] = hh; Ql[lrow][lhs + d + 3] = ll;
        }
    }

    float o[8][4];
#pragma unroll
    for (int df = 0; df < 8; df++)
#pragma unroll
        for (int r = 0; r < 4; r++) o[df][r] = 0.f;
    float m0 = -1e30f, m1 = -1e30f, l0 = 0.f, l1 = 0.f;

    int rowg0 = qt * 64 + warp * 16 + gid;
    int rowg1 = rowg0 + 8;

    int ntiles = qt + 1;
    for (int t = 0; t < ntiles; t++) {
        int j0 = t * 64;
        __syncthreads();   // prev tile's MMA reads done (and Q ready at t=0)
        {
            const float* kr = qkv + (long)(j0 + lrow) * (3 * C) + C + h * HD + lhs;
            const float* vr = kr + C;
#pragma unroll
            for (int d = 0; d < 32; d += 4) {
                float4 k4 = *(const float4*)&kr[d];
                float hh, ll;
                hilo(k4.x, hh, ll); Kh[lrow][lhs + d]     = hh; Kl[lrow][lhs + d]     = ll;
                hilo(k4.y, hh, ll); Kh[lrow][lhs + d + 1] = hh; Kl[lrow][lhs + d + 1] = ll;
                hilo(k4.z, hh, ll); Kh[lrow][lhs + d + 2] = hh; Kl[lrow][lhs + d + 2] = ll;
                hilo(k4.w, hh, ll); Kh[lrow][lhs + d + 3] = hh; Kl[lrow][lhs + d + 3] = ll;
                float4 v4 = *(const float4*)&vr[d];
                hilo(v4.x, hh, ll); Vh[lhs + d][lrow]     = hh; Vl[lhs + d][lrow]     = ll;
                hilo(v4.y, hh, ll); Vh[lhs + d + 1][lrow] = hh; Vl[lhs + d + 1][lrow] = ll;
                hilo(v4.z, hh, ll); Vh[lhs + d + 2][lrow] = hh; Vl[lhs + d + 2][lrow] = ll;
                hilo(v4.w, hh, ll); Vh[lhs + d + 3][lrow] = hh; Vl[lhs + d + 3][lrow] = ll;
            }
        }
        __syncthreads();

        // ---- S = Q K^T (3xTF32) ----
        float S[8][4];
#pragma unroll
        for (int nf = 0; nf < 8; nf++)
#pragma unroll
            for (int r = 0; r < 4; r++) S[nf][r] = 0.f;

#pragma unroll
        for (int kk = 0; kk < 64; kk += 8) {
            int r0 = warp * 16 + gid;
            uint32_t qh[4], ql[4];
            qh[0] = __float_as_uint(Qh[r0][kk + tig]);
            qh[1] = __float_as_uint(Qh[r0 + 8][kk + tig]);
            qh[2] = __float_as_uint(Qh[r0][kk + tig + 4]);
            qh[3] = __float_as_uint(Qh[r0 + 8][kk + tig + 4]);
            ql[0] = __float_as_uint(Ql[r0][kk + tig]);
            ql[1] = __float_as_uint(Ql[r0 + 8][kk + tig]);
            ql[2] = __float_as_uint(Ql[r0][kk + tig + 4]);
            ql[3] = __float_as_uint(Ql[r0 + 8][kk + tig + 4]);
#pragma unroll
            for (int nf = 0; nf < 8; nf++) {
                int rn = nf * 8 + gid;
                uint32_t bh[2], bl[2];
                bh[0] = __float_as_uint(Kh[rn][kk + tig]);
                bh[1] = __float_as_uint(Kh[rn][kk + tig + 4]);
                bl[0] = __float_as_uint(Kl[rn][kk + tig]);
                bl[1] = __float_as_uint(Kl[rn][kk + tig + 4]);
                mma_tf32(S[nf], ql, bh);
                mma_tf32(S[nf], qh, bl);
                mma_tf32(S[nf], qh, bh);
            }
        }

        // ---- scale + causal mask + online softmax ----
        bool diag = (t == qt);
        float max0 = -1e30f, max1 = -1e30f;
#pragma unroll
        for (int nf = 0; nf < 8; nf++) {
            int colb = j0 + nf * 8 + 2 * tig;
            float s0 = S[nf][0] * 0.125f;
            float s1 = S[nf][1] * 0.125f;
            float s2 = S[nf][2] * 0.125f;
            float s3 = S[nf][3] * 0.125f;
            if (diag) {
                if (colb     > rowg0) s0 = -1e30f;
                if (colb + 1 > rowg0) s1 = -1e30f;
                if (colb     > rowg1) s2 = -1e30f;
                if (colb + 1 > rowg1) s3 = -1e30f;
            }
            S[nf][0] = s0; S[nf][1] = s1; S[nf][2] = s2; S[nf][3] = s3;
            max0 = fmaxf(max0, fmaxf(s0, s1));
            max1 = fmaxf(max1, fmaxf(s2, s3));
        }
        max0 = fmaxf(max0, __shfl_xor_sync(0xffffffffu, max0, 1));
        max0 = fmaxf(max0, __shfl_xor_sync(0xffffffffu, max0, 2));
        max1 = fmaxf(max1, __shfl_xor_sync(0xffffffffu, max1, 1));
        max1 = fmaxf(max1, __shfl_xor_sync(0xffffffffu, max1, 2));

        float mn0 = fmaxf(m0, max0), mn1 = fmaxf(m1, max1);
        float corr0 = __expf(m0 - mn0), corr1 = __expf(m1 - mn1);
        float ls0 = 0.f, ls1 = 0.f;
#pragma unroll
        for (int nf = 0; nf < 8; nf++) {
            int cb = nf * 8 + 2 * tig;
            float p0 = __expf(S[nf][0] - mn0);
            float p1 = __expf(S[nf][1] - mn0);
            float p2 = __expf(S[nf][2] - mn1);
            float p3 = __expf(S[nf][3] - mn1);
            ls0 += p0 + p1; ls1 += p2 + p3;
            Psw[gid][cb]     = p0; Psw[gid][cb + 1]     = p1;
            Psw[gid + 8][cb] = p2; Psw[gid + 8][cb + 1] = p3;
        }
        ls0 += __shfl_xor_sync(0xffffffffu, ls0, 1);
        ls0 += __shfl_xor_sync(0xffffffffu, ls0, 2);
        ls1 += __shfl_xor_sync(0xffffffffu, ls1, 1);
        ls1 += __shfl_xor_sync(0xffffffffu, ls1, 2);
        l0 = l0 * corr0 + ls0;
        l1 = l1 * corr1 + ls1;
        m0 = mn0; m1 = mn1;

#pragma unroll
        for (int df = 0; df < 8; df++) {
            o[df][0] *= corr0; o[df][1] *= corr0;
            o[df][2] *= corr1; o[df][3] *= corr1;
        }
        __syncwarp();

        // ---- o += P V (3xTF32); A = P (rows = warp's own), B = V^T ----
#pragma unroll
        for (int kk = 0; kk < 64; kk += 8) {
            uint32_t ph[4], pl[4];
            float pv;
            pv = Psw[gid][kk + tig];
            ph[0] = f2tf32(pv); pl[0] = f2tf32(pv - __uint_as_float(ph[0]));
            pv = Psw[gid + 8][kk + tig];
            ph[1] = f2tf32(pv); pl[1] = f2tf32(pv - __uint_as_float(ph[1]));
            pv = Psw[gid][kk + tig + 4];
            ph[2] = f2tf32(pv); pl[2] = f2tf32(pv - __uint_as_float(ph[2]));
            pv = Psw[gid + 8][kk + tig + 4];
            ph[3] = f2tf32(pv); pl[3] = f2tf32(pv - __uint_as_float(ph[3]));
#pragma unroll
            for (int df = 0; df < 8; df++) {
                int dn = df * 8 + gid;
                uint32_t vh[2], vl[2];
                vh[0] = __float_as_uint(Vh[dn][kk + tig]);
                vh[1] = __float_as_uint(Vh[dn][kk + tig + 4]);
                vl[0] = __float_as_uint(Vl[dn][kk + tig]);
                vl[1] = __float_as_uint(Vl[dn][kk + tig + 4]);
                mma_tf32(o[df], pl, vh);
                mma_tf32(o[df], ph, vl);
                mma_tf32(o[df], ph, vh);
            }
        }
    }

    float inv0 = 1.f / l0, inv1 = 1.f / l1;
    float* op0 = out + (long)rowg0 * C + h * HD;
    float* op1 = out + (long)rowg1 * C + h * HD;
#pragma unroll
    for (int df = 0; df < 8; df++) {
        int colb = df * 8 + 2 * tig;
        *(float2*)&op0[colb] = make_float2(o[df][0] * inv0, o[df][1] * inv0);
        *(float2*)&op1[colb] = make_float2(o[df][2] * inv1, o[df][3] * inv1);
    }
}

// ---------------- MoE gate: logits + top-2 + softmax ----------------
__global__ __launch_bounds__(256) void gate_kernel(const float* __restrict__ xn,
                                                   const float* __restrict__ gw,
                                                   int* __restrict__ tope,
                                                   float* __restrict__ tops)
{
    int t = blockIdx.x;
    int w = threadIdx.x >> 5, lane = threadIdx.x & 31;
    const float* x  = xn + (long)t * C;
    const float* gr = gw + (long)w * C;
    float s = 0.f;
    for (int c = lane * 4; c < C; c += 128) {
        float4 a = *(const float4*)&x[c];
        float4 b = *(const float4*)&gr[c];
        s += a.x * b.x + a.y * b.y + a.z * b.z + a.w * b.w;
    }
#pragma unroll
    for (int off = 16; off; off >>= 1) s += __shfl_xor_sync(0xffffffffu, s, off);
    __shared__ float lg[NE];
    if (lane == 0) lg[w] = s;
    __syncthreads();
    if (threadIdx.x == 0) {
        int i0 = 0;
#pragma unroll
        for (int e2 = 1; e2 < NE; e2++) if (lg[e2] > lg[i0]) i0 = e2;
        int i1 = (i0 == 0) ? 1 : 0;
#pragma unroll
        for (int e2 = 0; e2 < NE; e2++) if (e2 != i0 && lg[e2] > lg[i1]) i1 = e2;
        float ex = __expf(lg[i1] - lg[i0]);
        float s0 = 1.f / (1.f + ex);
        tope[t * 2]     = i0; tope[t * 2 + 1] = i1;
        tops[t * 2]     = s0; tops[t * 2 + 1] = 1.f - s0;
    }
}

// ---------------- routing compaction (single block; int atomics only) --------
__global__ void scatter_kernel(const int* __restrict__ tope)
{
    __shared__ int cnt[NE];
    __shared__ int off[NE + 1];
    int tid = threadIdx.x;
    if (tid < NE) cnt[tid] = 0;
    __syncthreads();
    for (int p = tid; p < P; p += 256) atomicAdd(&cnt[tope[p]], 1);
    __syncthreads();
    if (tid == 0) {
        off[0] = 0;
        for (int e = 0; e < NE; e++) off[e + 1] = off[e] + cnt[e];
        for (int e = 0; e <= NE; e++) g_off[e] = off[e];
    }
    __syncthreads();
    if (tid < NE) cnt[tid] = off[tid];
    __syncthreads();
    for (int p = tid; p < P; p += 256) {
        int e2  = tope[p];
        int pos = atomicAdd(&cnt[e2], 1);
        g_pairtok[pos] = p >> 1;   // token index
        g_tokpos[p] = pos;
    }
}

// ---------------- MoE combine: x += s0*y[p0] + s1*y[p1] ----------------
__global__ __launch_bounds__(192) void combine_kernel(
    const float* __restrict__ ybuf, const float* __restrict__ tops,
    const int* __restrict__ tokpos, float* x)
{
    int t = blockIdx.x;
    int c = threadIdx.x * 4;
    int p0 = tokpos[t * 2], p1 = tokpos[t * 2 + 1];
    float w0 = tops[t * 2], w1 = tops[t * 2 + 1];
    float4 a  = *(const float4*)&ybuf[(long)p0 * C + c];
    float4 b  = *(const float4*)&ybuf[(long)p1 * C + c];
    float4 xv = *(float4*)&x[(long)t * C + c];
    xv.x += w0 * a.x + w1 * b.x;
    xv.y += w0 * a.y + w1 * b.y;
    xv.z += w0 * a.z + w1 * b.z;
    xv.w += w0 * a.w + w1 * b.w;
    *(float4*)&x[(long)t * C + c] = xv;
}

// ---------------- lm head: logits[v] = dot(x_last, wte[v]) ----------------
__global__ __launch_bounds__(256) void lmhead_kernel(
    const float* __restrict__ xn, const float* __restrict__ wte,
    float* __restrict__ out)
{
    __shared__ float4 xs[C / 4];
    const float* x = xn + (long)(T - 1) * C;
    for (int ii = threadIdx.x; ii < C / 4; ii += 256) xs[ii] = *(const float4*)&x[ii * 4];
    __syncthreads();
    int w = threadIdx.x >> 5, lane = threadIdx.x & 31;
    int v = blockIdx.x * 8 + w;
    if (v >= V) return;
    const float* wr = wte + (long)v * C;
    float s = 0.f;
    for (int c = lane; c < C / 4; c += 32) {
        float4 a = *(const float4*)&wr[c * 4];
        float4 b = xs[c];
        s += a.x * b.x + a.y * b.y + a.z * b.z + a.w * b.w;
    }
#pragma unroll
    for (int off = 16; off; off >>= 1) s += __shfl_xor_sync(0xffffffffu, s, off);
    if (lane == 0) out[v] = s;
}

// ---------------- launch ----------------
extern "C" void kernel_launch(void* const* d_in, const int* in_sizes, int n_in,
                              void* d_out, int out_size)
{
    const int*   idx   = (const int*)d_in[0];
    const float* wte   = (const float*)d_in[1];
    const float* wpe   = (const float*)d_in[2];
    const float* ln1g  = (const float*)d_in[3];
    const float* qkvw  = (const float*)d_in[4];
    const float* projw = (const float*)d_in[5];
    const float* ln2g  = (const float*)d_in[6];
    const float* gatew = (const float*)d_in[7];
    const float* w1    = (const float*)d_in[8];
    const float* w2    = (const float*)d_in[9];
    const float* lnfg  = (const float*)d_in[10];
    float* out = (float*)d_out;

    float *p_x, *p_xn, *p_qkv, *p_attno, *p_h, *p_y, *p_tops;
    int *p_tope, *p_tokpos, *p_pairtok, *p_off;
    cudaGetSymbolAddress((void**)&p_x,       g_x);
    cudaGetSymbolAddress((void**)&p_xn,      g_xn);
    cudaGetSymbolAddress((void**)&p_qkv,     g_qkv);
    cudaGetSymbolAddress((void**)&p_attno,   g_attno);
    cudaGetSymbolAddress((void**)&p_h,       g_h);
    cudaGetSymbolAddress((void**)&p_y,       g_y);
    cudaGetSymbolAddress((void**)&p_tops,    g_tops);
    cudaGetSymbolAddress((void**)&p_tope,    g_tope);
    cudaGetSymbolAddress((void**)&p_tokpos,  g_tokpos);
    cudaGetSymbolAddress((void**)&p_pairtok, g_pairtok);
    cudaGetSymbolAddress((void**)&p_off,     g_off);

    cudaFuncSetAttribute(attn_kernel,
                         cudaFuncAttributeMaxDynamicSharedMemorySize, ATTN_SMEM);

    embed_kernel<<<T, C / 4>>>(idx, wte, wpe, p_x);

    for (int l = 0; l < 2; l++) {
        layernorm_kernel<<<T, 256>>>(p_x, p_xn, ln1g + (long)l * C, 0);
        sgemm_kernel<<<dim3(3 * C / BN, T / BM, 1), 128>>>(
            p_xn, C, qkvw + (long)l * 3 * C * C, 0, 3 * C, C,
            p_qkv, 3 * C, nullptr, nullptr, nullptr, T, 0);
        attn_kernel<<<dim3(T / 64, NH), 128, ATTN_SMEM>>>(p_qkv, p_attno);
        sgemm_kernel<<<dim3(C / BN, T / BM, 1), 128>>>(
            p_attno, C, projw + (long)l * C * C, 0, C, C,
            p_x, C, p_x, nullptr, nullptr, T, 0);

        layernorm_kernel<<<T, 256>>>(p_x, p_xn, ln2g + (long)l * C, 0);
        gate_kernel<<<T, 256>>>(p_xn, gatew + (long)l * NE * C, p_tope, p_tops);
        scatter_kernel<<<1, 256>>>(p_tope);
        sgemm_kernel<<<dim3(C4 / BN, T / BM, NE), 128>>>(
            p_xn, C, w1 + (long)l * NE * C4 * C, (long)C4 * C, C4, C,
            p_h, C4, nullptr, p_off, p_pairtok, 0, 1);
        sgemm_kernel<<<dim3(C / BN, T / BM, NE), 128>>>(
            p_h, C4, w2 + (long)l * NE * C * C4, (long)C * C4, C, C4,
            p_y, C, nullptr, p_off, nullptr, 0, 0);
        combine_kernel<<<T, C / 4>>>(p_y, p_tops, p_tokpos, p_x);
    }

    layernorm_kernel<<<1, 256>>>(p_x, p_xn, lnfg, T - 1);
    lmhead_kernel<<<(V + 7) / 8, 256>>>(p_xn, wte, out);
}

// round 8
// speedup vs baseline: 1.8567x; 1.1241x over previous
#include <cuda_runtime.h>
#include <cuda_bf16.h>
#include <cstdint>

namespace {
constexpr int T  = 1024;
constexpr int C  = 768;
constexpr int NH = 12;
constexpr int HD = 64;
constexpr int NE = 8;
constexpr int V  = 50257;
constexpr int C4 = 3072;
constexpr int P  = 2048;   // token-expert pairs (T * topK)
constexpr int ATTN_SMEM = (6 * 64 * 68 + 4 * 16 * 68) * 4;   // 121856 B
}

// ---------------- scratch (device globals; no allocation) ----------------
__device__ float g_x[T * C];
__device__ float g_xn[T * C];
__device__ float g_qkv[T * 3 * C];
__device__ float g_attno[T * C];
__device__ float g_h[P * C4];     // 25 MB
__device__ float g_y[P * C];
__device__ int   g_tope[P];
__device__ float g_tops[P];
__device__ int   g_tokpos[P];
__device__ int   g_pairtok[P];
__device__ int   g_off[NE + 1];

// ---------------- embed: x = wte[idx] + wpe ----------------
__global__ void embed_kernel(const int* __restrict__ idx,
                             const float* __restrict__ wte,
                             const float* __restrict__ wpe,
                             float* __restrict__ x)
{
    int t = blockIdx.x;
    int c = threadIdx.x * 4;
    int tok = idx[t];
    float4 a = *(const float4*)&wte[(long)tok * C + c];
    float4 b = *(const float4*)&wpe[(long)t * C + c];
    float4 r = make_float4(a.x + b.x, a.y + b.y, a.z + b.z, a.w + b.w);
    *(float4*)&x[(long)t * C + c] = r;
}

// ---------------- layernorm (gamma only, eps 1e-5) ----------------
__global__ __launch_bounds__(256) void layernorm_kernel(
    const float* __restrict__ in, float* __restrict__ out,
    const float* __restrict__ g, int rowbase)
{
    int row = rowbase + blockIdx.x;
    const float* x = in + (long)row * C;
    int tid = threadIdx.x;
    __shared__ float red[256];
    float v[3];
    float s = 0.f;
#pragma unroll
    for (int i = 0; i < 3; i++) { v[i] = x[tid + i * 256]; s += v[i]; }
    red[tid] = s; __syncthreads();
    for (int st = 128; st > 0; st >>= 1) { if (tid < st) red[tid] += red[tid + st]; __syncthreads(); }
    float mu = red[0] * (1.f / C);
    __syncthreads();
    float q = 0.f;
#pragma unroll
    for (int i = 0; i < 3; i++) { float d = v[i] - mu; q += d * d; }
    red[tid] = q; __syncthreads();
    for (int st = 128; st > 0; st >>= 1) { if (tid < st) red[tid] += red[tid + st]; __syncthreads(); }
    float var = red[0] * (1.f / C);
    float rstd = rsqrtf(var + 1e-5f);
#pragma unroll
    for (int i = 0; i < 3; i++) {
        int c = tid + i * 256;
        out[(long)row * C + c] = (v[i] - mu) * rstd * g[c];
    }
}

// ---------------- tf32 helpers ----------------
__device__ __forceinline__ uint32_t f2tf32(float x) {
    uint32_t r;
    asm("cvt.rna.tf32.f32 %0, %1;" : "=r"(r) : "f"(x));
    return r;
}

__device__ __forceinline__ void mma_tf32(float* c, const uint32_t* a, const uint32_t* b) {
    asm volatile(
        "mma.sync.aligned.m16n8k8.row.col.f32.tf32.tf32.f32 "
        "{%0,%1,%2,%3}, {%4,%5,%6,%7}, {%8,%9}, {%0,%1,%2,%3};\n"
        : "+f"(c[0]), "+f"(c[1]), "+f"(c[2]), "+f"(c[3])
        : "r"(a[0]), "r"(a[1]), "r"(a[2]), "r"(a[3]),
          "r"(b[0]), "r"(b[1]));
}

__device__ __forceinline__ void hilo(float x, float& h, float& l) {
    h = __uint_as_float(f2tf32(x));
    l = __uint_as_float(f2tf32(x - h));
}

// ---------------- 3xTF32 tensor-core GEMM (128x128 tiles, prefetch) --------
// out[m, n] = sum_k A[row(m), k] * B[e][n, k]   (B row-major [N, K])
// offsets != null -> grouped-by-expert along blockIdx.z; gather != null -> A row indirection.
constexpr int BM = 128, BN = 128, BK = 16;
constexpr int SSTR = 20;   // smem row stride (words): conflict-free frag loads

__global__ __launch_bounds__(256) void sgemm_kernel(
    const float* __restrict__ Abase, int lda,
    const float* __restrict__ Bbase, long bstride,
    int N, int K,
    float* Out, int ldo,
    const float* resid,
    const int* __restrict__ offsets,
    const int* __restrict__ gather,
    int M, int dogelu)
{
    int e = blockIdx.z;
    int rowbase = 0, cnt = M;
    if (offsets) { rowbase = offsets[e]; cnt = offsets[e + 1] - rowbase; }
    int m0 = blockIdx.y * BM;
    if (m0 >= cnt) return;
    int n0 = blockIdx.x * BN;
    const float* B = Bbase + (long)e * bstride;

    __shared__ __align__(16) uint32_t Ah[BM][SSTR];
    __shared__ __align__(16) uint32_t Al[BM][SSTR];
    __shared__ __align__(16) uint32_t Bh[BN][SSTR];
    __shared__ __align__(16) uint32_t Bl[BN][SSTR];

    int tid  = threadIdx.x;
    int lane = tid & 31, warp = tid >> 5;
    int gid  = lane >> 2, tig = lane & 3;
    int wm   = (warp & 1) * 64;      // warp tile: 64 (m) x 32 (n)
    int wn   = (warp >> 1) * 32;

    // loader: 128 rows x 16 k-floats per operand; 4 threads per row (float4 each), 2 passes
    int lrow0 = tid >> 2;           // 0..63
    int lq    = (tid & 3) * 4;      // k offset 0/4/8/12
    long aof[2]; bool av[2]; long bof[2];
#pragma unroll
    for (int i = 0; i < 2; i++) {
        int row = lrow0 + i * 64;
        int gm  = m0 + row;
        av[i] = gm < cnt;
        int arow = 0;
        if (av[i]) arow = gather ? gather[rowbase + gm] : (rowbase + gm);
        aof[i] = (long)arow * lda + lq;
        bof[i] = (long)(n0 + row) * K + lq;
    }

    float c[4][4][4];
#pragma unroll
    for (int i = 0; i < 4; i++)
#pragma unroll
        for (int j = 0; j < 4; j++)
#pragma unroll
            for (int r = 0; r < 4; r++) c[i][j][r] = 0.f;

    // prefetch k0 = 0
    float4 pa[2], pb[2];
#pragma unroll
    for (int i = 0; i < 2; i++) {
        pa[i] = av[i] ? *(const float4*)&Abase[aof[i]] : make_float4(0.f, 0.f, 0.f, 0.f);
        pb[i] = *(const float4*)&B[bof[i]];
    }

    for (int k0 = 0; k0 < K; k0 += BK) {
        // convert + store current tile
#pragma unroll
        for (int i = 0; i < 2; i++) {
            int row = lrow0 + i * 64;
            uint4 uh, ul;
            uh.x = f2tf32(pa[i].x); ul.x = f2tf32(pa[i].x - __uint_as_float(uh.x));
            uh.y = f2tf32(pa[i].y); ul.y = f2tf32(pa[i].y - __uint_as_float(uh.y));
            uh.z = f2tf32(pa[i].z); ul.z = f2tf32(pa[i].z - __uint_as_float(uh.z));
            uh.w = f2tf32(pa[i].w); ul.w = f2tf32(pa[i].w - __uint_as_float(uh.w));
            *(uint4*)&Ah[row][lq] = uh;
            *(uint4*)&Al[row][lq] = ul;
            uh.x = f2tf32(pb[i].x); ul.x = f2tf32(pb[i].x - __uint_as_float(uh.x));
            uh.y = f2tf32(pb[i].y); ul.y = f2tf32(pb[i].y - __uint_as_float(uh.y));
            uh.z = f2tf32(pb[i].z); ul.z = f2tf32(pb[i].z - __uint_as_float(uh.z));
            uh.w = f2tf32(pb[i].w); ul.w = f2tf32(pb[i].w - __uint_as_float(uh.w));
            *(uint4*)&Bh[row][lq] = uh;
            *(uint4*)&Bl[row][lq] = ul;
        }
        __syncthreads();

        // prefetch next tile into registers (latency hidden by MMAs below)
        int kn = k0 + BK;
        if (kn < K) {
#pragma unroll
            for (int i = 0; i < 2; i++) {
                pa[i] = av[i] ? *(const float4*)&Abase[aof[i] + kn]
                              : make_float4(0.f, 0.f, 0.f, 0.f);
                pb[i] = *(const float4*)&B[bof[i] + kn];
            }
        }

#pragma unroll
        for (int kk = 0; kk < BK; kk += 8) {
            uint32_t ah[4][4], al[4][4], bh[4][2], bl[4][2];
#pragma unroll
            for (int i = 0; i < 4; i++) {
                int r0 = wm + i * 16 + gid;
                ah[i][0] = Ah[r0][kk + tig];
                ah[i][1] = Ah[r0 + 8][kk + tig];
                ah[i][2] = Ah[r0][kk + tig + 4];
                ah[i][3] = Ah[r0 + 8][kk + tig + 4];
                al[i][0] = Al[r0][kk + tig];
                al[i][1] = Al[r0 + 8][kk + tig];
                al[i][2] = Al[r0][kk + tig + 4];
                al[i][3] = Al[r0 + 8][kk + tig + 4];
            }
#pragma unroll
            for (int j = 0; j < 4; j++) {
                int rn = wn + j * 8 + gid;
                bh[j][0] = Bh[rn][kk + tig];
                bh[j][1] = Bh[rn][kk + tig + 4];
                bl[j][0] = Bl[rn][kk + tig];
                bl[j][1] = Bl[rn][kk + tig + 4];
            }
#pragma unroll
            for (int i = 0; i < 4; i++)
#pragma unroll
                for (int j = 0; j < 4; j++) {
                    mma_tf32(c[i][j], al[i], bh[j]);   // small terms first
                    mma_tf32(c[i][j], ah[i], bl[j]);
                    mma_tf32(c[i][j], ah[i], bh[j]);
                }
        }
        __syncthreads();
    }

    // epilogue: c[i][j] = {(gid, 2tig), (gid, 2tig+1), (gid+8, 2tig), (gid+8, 2tig+1)}
#pragma unroll
    for (int i = 0; i < 4; i++) {
#pragma unroll
        for (int half = 0; half < 2; half++) {
            int gm = m0 + wm + i * 16 + gid + half * 8;
            if (gm >= cnt) continue;
            long orow = rowbase + gm;
#pragma unroll
            for (int j = 0; j < 4; j++) {
                int col = n0 + wn + j * 8 + 2 * tig;
                float v0 = c[i][j][half * 2];
                float v1 = c[i][j][half * 2 + 1];
                if (dogelu) {
                    v0 = 0.5f * v0 * (1.f + erff(v0 * 0.70710678118654752f));
                    v1 = 0.5f * v1 * (1.f + erff(v1 * 0.70710678118654752f));
                }
                if (resid) {
                    float2 rv = *(const float2*)&resid[orow * ldo + col];
                    v0 += rv.x; v1 += rv.y;
                }
                float2 r2 = make_float2(v0, v1);
                *(float2*)&Out[orow * ldo + col] = r2;
            }
        }
    }
}

// ---------------- tensor-core flash attention (3xTF32) ----------------
// block = (64-query tile, head), 4 warps; warp w owns query rows 16w..16w+15.
__global__ __launch_bounds__(128) void attn_kernel(const float* __restrict__ qkv,
                                                   float* __restrict__ out)
{
    extern __shared__ float sm[];
    float (*Qh)[68] = (float(*)[68])(sm);
    float (*Ql)[68] = (float(*)[68])(sm + 64 * 68);
    float (*Kh)[68] = (float(*)[68])(sm + 2 * 64 * 68);
    float (*Kl)[68] = (float(*)[68])(sm + 3 * 64 * 68);
    float (*Vh)[68] = (float(*)[68])(sm + 4 * 64 * 68);   // transposed [d][j]
    float (*Vl)[68] = (float(*)[68])(sm + 5 * 64 * 68);

    int h    = blockIdx.y;
    int qt   = (int)gridDim.x - 1 - (int)blockIdx.x;   // big tiles first
    int tid  = threadIdx.x;
    int warp = tid >> 5, lane = tid & 31;
    int gid  = lane >> 2, tig = lane & 3;

    float (*Psw)[68] = (float(*)[68])(sm + 6 * 64 * 68 + warp * 16 * 68);

    int lrow = tid >> 1;
    int lhs  = (tid & 1) * 32;

    // load Q tile (64 x 64) -> hi/lo
    {
        const float* qr = qkv + (long)(qt * 64 + lrow) * (3 * C) + h * HD + lhs;
#pragma unroll
        for (int d = 0; d < 32; d += 4) {
            float4 q4 = *(const float4*)&qr[d];
            float hh, ll;
            hilo(q4.x, hh, ll); Qh[lrow][lhs + d]     = hh; Ql[lrow][lhs + d]     = ll;
            hilo(q4.y, hh, ll); Qh[lrow][lhs + d + 1] = hh; Ql[lrow][lhs + d + 1] = ll;
            hilo(q4.z, hh, ll); Qh[lrow][lhs + d + 2] = hh; Ql[lrow][lhs + d + 2] = ll;
            hilo(q4.w, hh, ll); Qh[lrow][lhs + d + 3] = hh; Ql[lrow][lhs + d + 3] = ll;
        }
    }

    float o[8][4];
#pragma unroll
    for (int df = 0; df < 8; df++)
#pragma unroll
        for (int r = 0; r < 4; r++) o[df][r] = 0.f;
    float m0 = -1e30f, m1 = -1e30f, l0 = 0.f, l1 = 0.f;

    int rowg0 = qt * 64 + warp * 16 + gid;
    int rowg1 = rowg0 + 8;

    int ntiles = qt + 1;
    for (int t = 0; t < ntiles; t++) {
        int j0 = t * 64;
        __syncthreads();   // prev tile's MMA reads done (and Q ready at t=0)
        {
            const float* kr = qkv + (long)(j0 + lrow) * (3 * C) + C + h * HD + lhs;
            const float* vr = kr + C;
#pragma unroll
            for (int d = 0; d < 32; d += 4) {
                float4 k4 = *(const float4*)&kr[d];
                float hh, ll;
                hilo(k4.x, hh, ll); Kh[lrow][lhs + d]     = hh; Kl[lrow][lhs + d]     = ll;
                hilo(k4.y, hh, ll); Kh[lrow][lhs + d + 1] = hh; Kl[lrow][lhs + d + 1] = ll;
                hilo(k4.z, hh, ll); Kh[lrow][lhs + d + 2] = hh; Kl[lrow][lhs + d + 2] = ll;
                hilo(k4.w, hh, ll); Kh[lrow][lhs + d + 3] = hh; Kl[lrow][lhs + d + 3] = ll;
                float4 v4 = *(const float4*)&vr[d];
                hilo(v4.x, hh, ll); Vh[lhs + d][lrow]     = hh; Vl[lhs + d][lrow]     = ll;
                hilo(v4.y, hh, ll); Vh[lhs + d + 1][lrow] = hh; Vl[lhs + d + 1][lrow] = ll;
                hilo(v4.z, hh, ll); Vh[lhs + d + 2][lrow] = hh; Vl[lhs + d + 2][lrow] = ll;
                hilo(v4.w, hh, ll); Vh[lhs + d + 3][lrow] = hh; Vl[lhs + d + 3][lrow] = ll;
            }
        }
        __syncthreads();

        // ---- S = Q K^T (3xTF32) ----
        float S[8][4];
#pragma unroll
        for (int nf = 0; nf < 8; nf++)
#pragma unroll
            for (int r = 0; r < 4; r++) S[nf][r] = 0.f;

#pragma unroll
        for (int kk = 0; kk < 64; kk += 8) {
            int r0 = warp * 16 + gid;
            uint32_t qh[4], ql[4];
            qh[0] = __float_as_uint(Qh[r0][kk + tig]);
            qh[1] = __float_as_uint(Qh[r0 + 8][kk + tig]);
            qh[2] = __float_as_uint(Qh[r0][kk + tig + 4]);
            qh[3] = __float_as_uint(Qh[r0 + 8][kk + tig + 4]);
            ql[0] = __float_as_uint(Ql[r0][kk + tig]);
            ql[1] = __float_as_uint(Ql[r0 + 8][kk + tig]);
            ql[2] = __float_as_uint(Ql[r0][kk + tig + 4]);
            ql[3] = __float_as_uint(Ql[r0 + 8][kk + tig + 4]);
#pragma unroll
            for (int nf = 0; nf < 8; nf++) {
                int rn = nf * 8 + gid;
                uint32_t bh[2], bl[2];
                bh[0] = __float_as_uint(Kh[rn][kk + tig]);
                bh[1] = __float_as_uint(Kh[rn][kk + tig + 4]);
                bl[0] = __float_as_uint(Kl[rn][kk + tig]);
                bl[1] = __float_as_uint(Kl[rn][kk + tig + 4]);
                mma_tf32(S[nf], ql, bh);
                mma_tf32(S[nf], qh, bl);
                mma_tf32(S[nf], qh, bh);
            }
        }

        // ---- scale + causal mask + online softmax ----
        bool diag = (t == qt);
        float max0 = -1e30f, max1 = -1e30f;
#pragma unroll
        for (int nf = 0; nf < 8; nf++) {
            int colb = j0 + nf * 8 + 2 * tig;
            float s0 = S[nf][0] * 0.125f;
            float s1 = S[nf][1] * 0.125f;
            float s2 = S[nf][2] * 0.125f;
            float s3 = S[nf][3] * 0.125f;
            if (diag) {
                if (colb     > rowg0) s0 = -1e30f;
                if (colb + 1 > rowg0) s1 = -1e30f;
                if (colb     > rowg1) s2 = -1e30f;
                if (colb + 1 > rowg1) s3 = -1e30f;
            }
            S[nf][0] = s0; S[nf][1] = s1; S[nf][2] = s2; S[nf][3] = s3;
            max0 = fmaxf(max0, fmaxf(s0, s1));
            max1 = fmaxf(max1, fmaxf(s2, s3));
        }
        max0 = fmaxf(max0, __shfl_xor_sync(0xffffffffu, max0, 1));
        max0 = fmaxf(max0, __shfl_xor_sync(0xffffffffu, max0, 2));
        max1 = fmaxf(max1, __shfl_xor_sync(0xffffffffu, max1, 1));
        max1 = fmaxf(max1, __shfl_xor_sync(0xffffffffu, max1, 2));

        float mn0 = fmaxf(m0, max0), mn1 = fmaxf(m1, max1);
        float corr0 = __expf(m0 - mn0), corr1 = __expf(m1 - mn1);
        float ls0 = 0.f, ls1 = 0.f;
#pragma unroll
        for (int nf = 0; nf < 8; nf++) {
            int cb = nf * 8 + 2 * tig;
            float p0 = __expf(S[nf][0] - mn0);
            float p1 = __expf(S[nf][1] - mn0);
            float p2 = __expf(S[nf][2] - mn1);
            float p3 = __expf(S[nf][3] - mn1);
            ls0 += p0 + p1; ls1 += p2 + p3;
            Psw[gid][cb]     = p0; Psw[gid][cb + 1]     = p1;
            Psw[gid + 8][cb] = p2; Psw[gid + 8][cb + 1] = p3;
        }
        ls0 += __shfl_xor_sync(0xffffffffu, ls0, 1);
        ls0 += __shfl_xor_sync(0xffffffffu, ls0, 2);
        ls1 += __shfl_xor_sync(0xffffffffu, ls1, 1);
        ls1 += __shfl_xor_sync(0xffffffffu, ls1, 2);
        l0 = l0 * corr0 + ls0;
        l1 = l1 * corr1 + ls1;
        m0 = mn0; m1 = mn1;

#pragma unroll
        for (int df = 0; df < 8; df++) {
            o[df][0] *= corr0; o[df][1] *= corr0;
            o[df][2] *= corr1; o[df][3] *= corr1;
        }
        __syncwarp();

        // ---- o += P V (3xTF32); A = P (rows = warp's own), B = V^T ----
#pragma unroll
        for (int kk = 0; kk < 64; kk += 8) {
            uint32_t ph[4], pl[4];
            float pv;
            pv = Psw[gid][kk + tig];
            ph[0] = f2tf32(pv); pl[0] = f2tf32(pv - __uint_as_float(ph[0]));
            pv = Psw[gid + 8][kk + tig];
            ph[1] = f2tf32(pv); pl[1] = f2tf32(pv - __uint_as_float(ph[1]));
            pv = Psw[gid][kk + tig + 4];
            ph[2] = f2tf32(pv); pl[2] = f2tf32(pv - __uint_as_float(ph[2]));
            pv = Psw[gid + 8][kk + tig + 4];
            ph[3] = f2tf32(pv); pl[3] = f2tf32(pv - __uint_as_float(ph[3]));
#pragma unroll
            for (int df = 0; df < 8; df++) {
                int dn = df * 8 + gid;
                uint32_t vh[2], vl[2];
                vh[0] = __float_as_uint(Vh[dn][kk + tig]);
                vh[1] = __float_as_uint(Vh[dn][kk + tig + 4]);
                vl[0] = __float_as_uint(Vl[dn][kk + tig]);
                vl[1] = __float_as_uint(Vl[dn][kk + tig + 4]);
                mma_tf32(o[df], pl, vh);
                mma_tf32(o[df], ph, vl);
                mma_tf32(o[df], ph, vh);
            }
        }
    }

    float inv0 = 1.f / l0, inv1 = 1.f / l1;
    float* op0 = out + (long)rowg0 * C + h * HD;
    float* op1 = out + (long)rowg1 * C + h * HD;
#pragma unroll
    for (int df = 0; df < 8; df++) {
        int colb = df * 8 + 2 * tig;
        *(float2*)&op0[colb] = make_float2(o[df][0] * inv0, o[df][1] * inv0);
        *(float2*)&op1[colb] = make_float2(o[df][2] * inv1, o[df][3] * inv1);
    }
}

// ---------------- MoE gate: logits + top-2 + softmax ----------------
__global__ __launch_bounds__(256) void gate_kernel(const float* __restrict__ xn,
                                                   const float* __restrict__ gw,
                                                   int* __restrict__ tope,
                                                   float* __restrict__ tops)
{
    int t = blockIdx.x;
    int w = threadIdx.x >> 5, lane = threadIdx.x & 31;
    const float* x  = xn + (long)t * C;
    const float* gr = gw + (long)w * C;
    float s = 0.f;
    for (int c = lane * 4; c < C; c += 128) {
        float4 a = *(const float4*)&x[c];
        float4 b = *(const float4*)&gr[c];
        s += a.x * b.x + a.y * b.y + a.z * b.z + a.w * b.w;
    }
#pragma unroll
    for (int off = 16; off; off >>= 1) s += __shfl_xor_sync(0xffffffffu, s, off);
    __shared__ float lg[NE];
    if (lane == 0) lg[w] = s;
    __syncthreads();
    if (threadIdx.x == 0) {
        int i0 = 0;
#pragma unroll
        for (int e2 = 1; e2 < NE; e2++) if (lg[e2] > lg[i0]) i0 = e2;
        int i1 = (i0 == 0) ? 1 : 0;
#pragma unroll
        for (int e2 = 0; e2 < NE; e2++) if (e2 != i0 && lg[e2] > lg[i1]) i1 = e2;
        float ex = __expf(lg[i1] - lg[i0]);
        float s0 = 1.f / (1.f + ex);
        tope[t * 2]     = i0; tope[t * 2 + 1] = i1;
        tops[t * 2]     = s0; tops[t * 2 + 1] = 1.f - s0;
    }
}

// ---------------- routing compaction (single block; int atomics only) --------
__global__ void scatter_kernel(const int* __restrict__ tope)
{
    __shared__ int cnt[NE];
    __shared__ int off[NE + 1];
    int tid = threadIdx.x;
    if (tid < NE) cnt[tid] = 0;
    __syncthreads();
    for (int p = tid; p < P; p += 256) atomicAdd(&cnt[tope[p]], 1);
    __syncthreads();
    if (tid == 0) {
        off[0] = 0;
        for (int e = 0; e < NE; e++) off[e + 1] = off[e] + cnt[e];
        for (int e = 0; e <= NE; e++) g_off[e] = off[e];
    }
    __syncthreads();
    if (tid < NE) cnt[tid] = off[tid];
    __syncthreads();
    for (int p = tid; p < P; p += 256) {
        int e2  = tope[p];
        int pos = atomicAdd(&cnt[e2], 1);
        g_pairtok[pos] = p >> 1;   // token index
        g_tokpos[p] = pos;
    }
}

// ---------------- MoE combine: x += s0*y[p0] + s1*y[p1] ----------------
__global__ __launch_bounds__(192) void combine_kernel(
    const float* __restrict__ ybuf, const float* __restrict__ tops,
    const int* __restrict__ tokpos, float* x)
{
    int t = blockIdx.x;
    int c = threadIdx.x * 4;
    int p0 = tokpos[t * 2], p1 = tokpos[t * 2 + 1];
    float w0 = tops[t * 2], w1 = tops[t * 2 + 1];
    float4 a  = *(const float4*)&ybuf[(long)p0 * C + c];
    float4 b  = *(const float4*)&ybuf[(long)p1 * C + c];
    float4 xv = *(float4*)&x[(long)t * C + c];
    xv.x += w0 * a.x + w1 * b.x;
    xv.y += w0 * a.y + w1 * b.y;
    xv.z += w0 * a.z + w1 * b.z;
    xv.w += w0 * a.w + w1 * b.w;
    *(float4*)&x[(long)t * C + c] = xv;
}

// ---------------- lm head: logits[v] = dot(x_last, wte[v]) ----------------
__global__ __launch_bounds__(256) void lmhead_kernel(
    const float* __restrict__ xn, const float* __restrict__ wte,
    float* __restrict__ out)
{
    __shared__ float4 xs[C / 4];
    const float* x = xn + (long)(T - 1) * C;
    for (int ii = threadIdx.x; ii < C / 4; ii += 256) xs[ii] = *(const float4*)&x[ii * 4];
    __syncthreads();
    int w = threadIdx.x >> 5, lane = threadIdx.x & 31;
    int v = blockIdx.x * 8 + w;
    if (v >= V) return;
    const float* wr = wte + (long)v * C;
    float s = 0.f;
    for (int c = lane; c < C / 4; c += 32) {
        float4 a = *(const float4*)&wr[c * 4];
        float4 b = xs[c];
        s += a.x * b.x + a.y * b.y + a.z * b.z + a.w * b.w;
    }
#pragma unroll
    for (int off = 16; off; off >>= 1) s += __shfl_xor_sync(0xffffffffu, s, off);
    if (lane == 0) out[v] = s;
}

// ---------------- launch ----------------
extern "C" void kernel_launch(void* const* d_in, const int* in_sizes, int n_in,
                              void* d_out, int out_size)
{
    const int*   idx   = (const int*)d_in[0];
    const float* wte   = (const float*)d_in[1];
    const float* wpe   = (const float*)d_in[2];
    const float* ln1g  = (const float*)d_in[3];
    const float* qkvw  = (const float*)d_in[4];
    const float* projw = (const float*)d_in[5];
    const float* ln2g  = (const float*)d_in[6];
    const float* gatew = (const float*)d_in[7];
    const float* w1    = (const float*)d_in[8];
    const float* w2    = (const float*)d_in[9];
    const float* lnfg  = (const float*)d_in[10];
    float* out = (float*)d_out;

    float *p_x, *p_xn, *p_qkv, *p_attno, *p_h, *p_y, *p_tops;
    int *p_tope, *p_tokpos, *p_pairtok, *p_off;
    cudaGetSymbolAddress((void**)&p_x,       g_x);
    cudaGetSymbolAddress((void**)&p_xn,      g_xn);
    cudaGetSymbolAddress((void**)&p_qkv,     g_qkv);
    cudaGetSymbolAddress((void**)&p_attno,   g_attno);
    cudaGetSymbolAddress((void**)&p_h,       g_h);
    cudaGetSymbolAddress((void**)&p_y,       g_y);
    cudaGetSymbolAddress((void**)&p_tops,    g_tops);
    cudaGetSymbolAddress((void**)&p_tope,    g_tope);
    cudaGetSymbolAddress((void**)&p_tokpos,  g_tokpos);
    cudaGetSymbolAddress((void**)&p_pairtok, g_pairtok);
    cudaGetSymbolAddress((void**)&p_off,     g_off);

    cudaFuncSetAttribute(attn_kernel,
                         cudaFuncAttributeMaxDynamicSharedMemorySize, ATTN_SMEM);

    embed_kernel<<<T, C / 4>>>(idx, wte, wpe, p_x);

    for (int l = 0; l < 2; l++) {
        layernorm_kernel<<<T, 256>>>(p_x, p_xn, ln1g + (long)l * C, 0);
        sgemm_kernel<<<dim3(3 * C / BN, T / BM, 1), 256>>>(
            p_xn, C, qkvw + (long)l * 3 * C * C, 0, 3 * C, C,
            p_qkv, 3 * C, nullptr, nullptr, nullptr, T, 0);
        attn_kernel<<<dim3(T / 64, NH), 128, ATTN_SMEM>>>(p_qkv, p_attno);
        sgemm_kernel<<<dim3(C / BN, T / BM, 1), 256>>>(
            p_attno, C, projw + (long)l * C * C, 0, C, C,
            p_x, C, p_x, nullptr, nullptr, T, 0);

        layernorm_kernel<<<T, 256>>>(p_x, p_xn, ln2g + (long)l * C, 0);
        gate_kernel<<<T, 256>>>(p_xn, gatew + (long)l * NE * C, p_tope, p_tops);
        scatter_kernel<<<1, 256>>>(p_tope);
        sgemm_kernel<<<dim3(C4 / BN, P / BM, NE), 256>>>(
            p_xn, C, w1 + (long)l * NE * C4 * C, (long)C4 * C, C4, C,
            p_h, C4, nullptr, p_off, p_pairtok, 0, 1);
        sgemm_kernel<<<dim3(C / BN, P / BM, NE), 256>>>(
            p_h, C4, w2 + (long)l * NE * C * C4, (long)C * C4, C, C4,
            p_y, C, nullptr, p_off, nullptr, 0, 0);
        combine_kernel<<<T, C / 4>>>(p_y, p_tops, p_tokpos, p_x);
    }

    layernorm_kernel<<<1, 256>>>(p_x, p_xn, lnfg, T - 1);
    lmhead_kernel<<<(V + 7) / 8, 256>>>(p_xn, wte, out);
}

// round 11
// speedup vs baseline: 2.4996x; 1.3463x over previous
#include <cuda_runtime.h>
#include <cuda_bf16.h>
#include <cstdint>

namespace {
constexpr int T  = 1024;
constexpr int C  = 768;
constexpr int NH = 12;
constexpr int HD = 64;
constexpr int NE = 8;
constexpr int V  = 50257;
constexpr int C4 = 3072;
constexpr int P  = 2048;   // token-expert pairs (T * topK)
constexpr int ATTN_SMEM = (6 * 64 * 68 + 4 * 16 * 68) * 4;   // 121856 B
}

// ---------------- scratch (device globals; no allocation) ----------------
__device__ float g_x[T * C];
__device__ float g_xn[T * C];
__device__ float g_qkv[T * 3 * C];
__device__ float g_attno[T * C];
__device__ float g_h[P * C4];     // 25 MB
__device__ float g_y[P * C];
__device__ int   g_tope[P];
__device__ float g_tops[P];
__device__ int   g_tokpos[P];
__device__ int   g_pairtok[P];
__device__ int   g_off[NE + 1];

// ---------------- embed: x = wte[idx] + wpe ----------------
__global__ void embed_kernel(const int* __restrict__ idx,
                             const float* __restrict__ wte,
                             const float* __restrict__ wpe,
                             float* __restrict__ x)
{
    int t = blockIdx.x;
    int c = threadIdx.x * 4;
    int tok = idx[t];
    float4 a = *(const float4*)&wte[(long)tok * C + c];
    float4 b = *(const float4*)&wpe[(long)t * C + c];
    float4 r = make_float4(a.x + b.x, a.y + b.y, a.z + b.z, a.w + b.w);
    *(float4*)&x[(long)t * C + c] = r;
}

// ---------------- layernorm (gamma only, eps 1e-5) ----------------
__global__ __launch_bounds__(256) void layernorm_kernel(
    const float* __restrict__ in, float* __restrict__ out,
    const float* __restrict__ g, int rowbase)
{
    int row = rowbase + blockIdx.x;
    const float* x = in + (long)row * C;
    int tid = threadIdx.x;
    __shared__ float red[256];
    float v[3];
    float s = 0.f;
#pragma unroll
    for (int i = 0; i < 3; i++) { v[i] = x[tid + i * 256]; s += v[i]; }
    red[tid] = s; __syncthreads();
    for (int st = 128; st > 0; st >>= 1) { if (tid < st) red[tid] += red[tid + st]; __syncthreads(); }
    float mu = red[0] * (1.f / C);
    __syncthreads();
    float q = 0.f;
#pragma unroll
    for (int i = 0; i < 3; i++) { float d = v[i] - mu; q += d * d; }
    red[tid] = q; __syncthreads();
    for (int st = 128; st > 0; st >>= 1) { if (tid < st) red[tid] += red[tid + st]; __syncthreads(); }
    float var = red[0] * (1.f / C);
    float rstd = rsqrtf(var + 1e-5f);
#pragma unroll
    for (int i = 0; i < 3; i++) {
        int c = tid + i * 256;
        out[(long)row * C + c] = (v[i] - mu) * rstd * g[c];
    }
}

// ---------------- tf32 helpers (attention kernel) ----------------
__device__ __forceinline__ uint32_t f2tf32(float x) {
    uint32_t r;
    asm("cvt.rna.tf32.f32 %0, %1;" : "=r"(r) : "f"(x));
    return r;
}

__device__ __forceinline__ void mma_tf32(float* c, const uint32_t* a, const uint32_t* b) {
    asm volatile(
        "mma.sync.aligned.m16n8k8.row.col.f32.tf32.tf32.f32 "
        "{%0,%1,%2,%3}, {%4,%5,%6,%7}, {%8,%9}, {%0,%1,%2,%3};\n"
        : "+f"(c[0]), "+f"(c[1]), "+f"(c[2]), "+f"(c[3])
        : "r"(a[0]), "r"(a[1]), "r"(a[2]), "r"(a[3]),
          "r"(b[0]), "r"(b[1]));
}

__device__ __forceinline__ void hilo(float x, float& h, float& l) {
    h = __uint_as_float(f2tf32(x));
    l = __uint_as_float(f2tf32(x - h));
}

// ---------------- bf16 split helpers (GEMM) ----------------
__device__ __forceinline__ void mma_bf16(float* c, const uint32_t* a, const uint32_t* b) {
    asm volatile(
        "mma.sync.aligned.m16n8k16.row.col.f32.bf16.bf16.f32 "
        "{%0,%1,%2,%3}, {%4,%5,%6,%7}, {%8,%9}, {%0,%1,%2,%3};\n"
        : "+f"(c[0]), "+f"(c[1]), "+f"(c[2]), "+f"(c[3])
        : "r"(a[0]), "r"(a[1]), "r"(a[2]), "r"(a[3]),
          "r"(b[0]), "r"(b[1]));
}

// split two adjacent k floats into packed bf16x2 hi and lo words (x0 -> low half)
__device__ __forceinline__ void bsplit2(float x0, float x1, uint32_t& wh, uint32_t& wl) {
    __nv_bfloat16 h0 = __float2bfloat16(x0);
    __nv_bfloat16 h1 = __float2bfloat16(x1);
    __nv_bfloat16 l0 = __float2bfloat16(x0 - __bfloat162float(h0));
    __nv_bfloat16 l1 = __float2bfloat16(x1 - __bfloat162float(h1));
    wh = ((uint32_t)__bfloat16_as_ushort(h1) << 16) | __bfloat16_as_ushort(h0);
    wl = ((uint32_t)__bfloat16_as_ushort(l1) << 16) | __bfloat16_as_ushort(l0);
}

// ---------------- split-bf16 tensor-core GEMM (128x128 tiles, prefetch) -----
// out[m, n] = sum_k A[row(m), k] * B[e][n, k]   (B row-major [N, K])
// A = Ah + Al, B = Bh + Bl (bf16 each); C = Al*Bh + Ah*Bl + Ah*Bh.
// offsets != null -> grouped-by-expert along blockIdx.z; gather != null -> A row indirection.
constexpr int BM = 128, BN = 128, BKF = 32;   // k floats per stage (16 words)
constexpr int SSTR = 20;   // smem row stride (words): conflict-free frag loads

__global__ __launch_bounds__(256) void sgemm_kernel(
    const float* __restrict__ Abase, int lda,
    const float* __restrict__ Bbase, long bstride,
    int N, int K,
    float* Out, int ldo,
    const float* resid,
    const int* __restrict__ offsets,
    const int* __restrict__ gather,
    int M, int dogelu)
{
    int e = blockIdx.z;
    int rowbase = 0, cnt = M;
    if (offsets) { rowbase = offsets[e]; cnt = offsets[e + 1] - rowbase; }
    int m0 = blockIdx.y * BM;
    if (m0 >= cnt) return;
    int n0 = blockIdx.x * BN;
    const float* B = Bbase + (long)e * bstride;

    __shared__ __align__(16) uint32_t Ah[BM][SSTR];
    __shared__ __align__(16) uint32_t Al[BM][SSTR];
    __shared__ __align__(16) uint32_t Bh[BN][SSTR];
    __shared__ __align__(16) uint32_t Bl[BN][SSTR];

    int tid  = threadIdx.x;
    int lane = tid & 31, warp = tid >> 5;
    int gid  = lane >> 2, tig = lane & 3;
    int wm   = (warp & 1) * 64;      // warp tile: 64 (m) x 32 (n)
    int wn   = (warp >> 1) * 32;

    // loader: 128 rows x 32 k-floats per operand; 4 threads per row (8 floats each), 2 passes
    int lrow0 = tid >> 2;           // 0..63
    int lw    = (tid & 3) * 4;      // word offset 0/4/8/12
    int lf    = lw * 2;             // float offset 0/8/16/24
    long aof[2]; bool av[2]; long bof[2];
#pragma unroll
    for (int i = 0; i < 2; i++) {
        int row = lrow0 + i * 64;
        int gm  = m0 + row;
        av[i] = gm < cnt;
        int arow = 0;
        if (av[i]) arow = gather ? gather[rowbase + gm] : (rowbase + gm);
        aof[i] = (long)arow * lda + lf;
        bof[i] = (long)(n0 + row) * K + lf;
    }

    float c[4][4][4];
#pragma unroll
    for (int i = 0; i < 4; i++)
#pragma unroll
        for (int j = 0; j < 4; j++)
#pragma unroll
            for (int r = 0; r < 4; r++) c[i][j][r] = 0.f;

    // prefetch k0 = 0
    float4 pa[2][2], pb[2][2];
#pragma unroll
    for (int i = 0; i < 2; i++) {
        if (av[i]) {
            pa[i][0] = *(const float4*)&Abase[aof[i]];
            pa[i][1] = *(const float4*)&Abase[aof[i] + 4];
        } else {
            pa[i][0] = pa[i][1] = make_float4(0.f, 0.f, 0.f, 0.f);
        }
        pb[i][0] = *(const float4*)&B[bof[i]];
        pb[i][1] = *(const float4*)&B[bof[i] + 4];
    }

    for (int k0 = 0; k0 < K; k0 += BKF) {
        // convert + store current stage
#pragma unroll
        for (int i = 0; i < 2; i++) {
            int row = lrow0 + i * 64;
            uint4 uh, ul;
            bsplit2(pa[i][0].x, pa[i][0].y, uh.x, ul.x);
            bsplit2(pa[i][0].z, pa[i][0].w, uh.y, ul.y);
            bsplit2(pa[i][1].x, pa[i][1].y, uh.z, ul.z);
            bsplit2(pa[i][1].z, pa[i][1].w, uh.w, ul.w);
            *(uint4*)&Ah[row][lw] = uh;
            *(uint4*)&Al[row][lw] = ul;
            bsplit2(pb[i][0].x, pb[i][0].y, uh.x, ul.x);
            bsplit2(pb[i][0].z, pb[i][0].w, uh.y, ul.y);
            bsplit2(pb[i][1].x, pb[i][1].y, uh.z, ul.z);
            bsplit2(pb[i][1].z, pb[i][1].w, uh.w, ul.w);
            *(uint4*)&Bh[row][lw] = uh;
            *(uint4*)&Bl[row][lw] = ul;
        }
        __syncthreads();

        // prefetch next stage into registers (latency hidden by MMAs below)
        int kn = k0 + BKF;
        if (kn < K) {
#pragma unroll
            for (int i = 0; i < 2; i++) {
                if (av[i]) {
                    pa[i][0] = *(const float4*)&Abase[aof[i] + kn];
                    pa[i][1] = *(const float4*)&Abase[aof[i] + kn + 4];
                }
                pb[i][0] = *(const float4*)&B[bof[i] + kn];
                pb[i][1] = *(const float4*)&B[bof[i] + kn + 4];
            }
        }

        // two k16 MMA steps (word offsets 0 and 8)
#pragma unroll
        for (int kk = 0; kk < 16; kk += 8) {
            uint32_t ah[4][4], al[4][4], bh[4][2], bl[4][2];
#pragma unroll
            for (int i = 0; i < 4; i++) {
                int r0 = wm + i * 16 + gid;
                ah[i][0] = Ah[r0][kk + tig];
                ah[i][1] = Ah[r0 + 8][kk + tig];
                ah[i][2] = Ah[r0][kk + tig + 4];
                ah[i][3] = Ah[r0 + 8][kk + tig + 4];
                al[i][0] = Al[r0][kk + tig];
                al[i][1] = Al[r0 + 8][kk + tig];
                al[i][2] = Al[r0][kk + tig + 4];
                al[i][3] = Al[r0 + 8][kk + tig + 4];
            }
#pragma unroll
            for (int j = 0; j < 4; j++) {
                int rn = wn + j * 8 + gid;
                bh[j][0] = Bh[rn][kk + tig];
                bh[j][1] = Bh[rn][kk + tig + 4];
                bl[j][0] = Bl[rn][kk + tig];
                bl[j][1] = Bl[rn][kk + tig + 4];
            }
#pragma unroll
            for (int i = 0; i < 4; i++)
#pragma unroll
                for (int j = 0; j < 4; j++) {
                    mma_bf16(c[i][j], al[i], bh[j]);   // small terms first
                    mma_bf16(c[i][j], ah[i], bl[j]);
                    mma_bf16(c[i][j], ah[i], bh[j]);
                }
        }
        __syncthreads();
    }

    // epilogue: c[i][j] = {(gid, 2tig), (gid, 2tig+1), (gid+8, 2tig), (gid+8, 2tig+1)}
#pragma unroll
    for (int i = 0; i < 4; i++) {
#pragma unroll
        for (int half = 0; half < 2; half++) {
            int gm = m0 + wm + i * 16 + gid + half * 8;
            if (gm >= cnt) continue;
            long orow = rowbase + gm;
#pragma unroll
            for (int j = 0; j < 4; j++) {
                int col = n0 + wn + j * 8 + 2 * tig;
                float v0 = c[i][j][half * 2];
                float v1 = c[i][j][half * 2 + 1];
                if (dogelu) {
                    v0 = 0.5f * v0 * (1.f + erff(v0 * 0.70710678118654752f));
                    v1 = 0.5f * v1 * (1.f + erff(v1 * 0.70710678118654752f));
                }
                if (resid) {
                    float2 rv = *(const float2*)&resid[orow * ldo + col];
                    v0 += rv.x; v1 += rv.y;
                }
                float2 r2 = make_float2(v0, v1);
                *(float2*)&Out[orow * ldo + col] = r2;
            }
        }
    }
}

// ---------------- tensor-core flash attention (3xTF32) ----------------
// block = (64-query tile, head), 4 warps; warp w owns query rows 16w..16w+15.
__global__ __launch_bounds__(128) void attn_kernel(const float* __restrict__ qkv,
                                                   float* __restrict__ out)
{
    extern __shared__ float sm[];
    float (*Qh)[68] = (float(*)[68])(sm);
    float (*Ql)[68] = (float(*)[68])(sm + 64 * 68);
    float (*Kh)[68] = (float(*)[68])(sm + 2 * 64 * 68);
    float (*Kl)[68] = (float(*)[68])(sm + 3 * 64 * 68);
    float (*Vh)[68] = (float(*)[68])(sm + 4 * 64 * 68);   // transposed [d][j]
    float (*Vl)[68] = (float(*)[68])(sm + 5 * 64 * 68);

    int h    = blockIdx.y;
    int qt   = (int)gridDim.x - 1 - (int)blockIdx.x;   // big tiles first
    int tid  = threadIdx.x;
    int warp = tid >> 5, lane = tid & 31;
    int gid  = lane >> 2, tig = lane & 3;

    float (*Psw)[68] = (float(*)[68])(sm + 6 * 64 * 68 + warp * 16 * 68);

    int lrow = tid >> 1;
    int lhs  = (tid & 1) * 32;

    // load Q tile (64 x 64) -> hi/lo
    {
        const float* qr = qkv + (long)(qt * 64 + lrow) * (3 * C) + h * HD + lhs;
#pragma unroll
        for (int d = 0; d < 32; d += 4) {
            float4 q4 = *(const float4*)&qr[d];
            float hh, ll;
            hilo(q4.x, hh, ll); Qh[lrow][lhs + d]     = hh; Ql[lrow][lhs + d]     = ll;
            hilo(q4.y, hh, ll); Qh[lrow][lhs + d + 1] = hh; Ql[lrow][lhs + d + 1] = ll;
            hilo(q4.z, hh, ll); Qh[lrow][lhs + d + 2] = hh; Ql[lrow][lhs + d + 2] = ll;
            hilo(q4.w, hh, ll); Qh[lrow][lhs + d + 3] = hh; Ql[lrow][lhs + d + 3] = ll;
        }
    }

    float o[8][4];
#pragma unroll
    for (int df = 0; df < 8; df++)
#pragma unroll
        for (int r = 0; r < 4; r++) o[df][r] = 0.f;
    float m0 = -1e30f, m1 = -1e30f, l0 = 0.f, l1 = 0.f;

    int rowg0 = qt * 64 + warp * 16 + gid;
    int rowg1 = rowg0 + 8;

    int ntiles = qt + 1;
    for (int t = 0; t < ntiles; t++) {
        int j0 = t * 64;
        __syncthreads();   // prev tile's MMA reads done (and Q ready at t=0)
        {
            const float* kr = qkv + (long)(j0 + lrow) * (3 * C) + C + h * HD + lhs;
            const float* vr = kr + C;
#pragma unroll
            for (int d = 0; d < 32; d += 4) {
                float4 k4 = *(const float4*)&kr[d];
                float hh, ll;
                hilo(k4.x, hh, ll); Kh[lrow][lhs + d]     = hh; Kl[lrow][lhs + d]     = ll;
                hilo(k4.y, hh, ll); Kh[lrow][lhs + d + 1] = hh; Kl[lrow][lhs + d + 1] = ll;
                hilo(k4.z, hh, ll); Kh[lrow][lhs + d + 2] = hh; Kl[lrow][lhs + d + 2] = ll;
                hilo(k4.w, hh, ll); Kh[lrow][lhs + d + 3] = hh; Kl[lrow][lhs + d + 3] = ll;
                float4 v4 = *(const float4*)&vr[d];
                hilo(v4.x, hh, ll); Vh[lhs + d][lrow]     = hh; Vl[lhs + d][lrow]     = ll;
                hilo(v4.y, hh, ll); Vh[lhs + d + 1][lrow] = hh; Vl[lhs + d + 1][lrow] = ll;
                hilo(v4.z, hh, ll); Vh[lhs + d + 2][lrow] = hh; Vl[lhs + d + 2][lrow] = ll;
                hilo(v4.w, hh, ll); Vh[lhs + d + 3][lrow] = hh; Vl[lhs + d + 3][lrow] = ll;
            }
        }
        __syncthreads();

        // ---- S = Q K^T (3xTF32) ----
        float S[8][4];
#pragma unroll
        for (int nf = 0; nf < 8; nf++)
#pragma unroll
            for (int r = 0; r < 4; r++) S[nf][r] = 0.f;

#pragma unroll
        for (int kk = 0; kk < 64; kk += 8) {
            int r0 = warp * 16 + gid;
            uint32_t qh[4], ql[4];
            qh[0] = __float_as_uint(Qh[r0][kk + tig]);
            qh[1] = __float_as_uint(Qh[r0 + 8][kk + tig]);
            qh[2] = __float_as_uint(Qh[r0][kk + tig + 4]);
            qh[3] = __float_as_uint(Qh[r0 + 8][kk + tig + 4]);
            ql[0] = __float_as_uint(Ql[r0][kk + tig]);
            ql[1] = __float_as_uint(Ql[r0 + 8][kk + tig]);
            ql[2] = __float_as_uint(Ql[r0][kk + tig + 4]);
            ql[3] = __float_as_uint(Ql[r0 + 8][kk + tig + 4]);
#pragma unroll
            for (int nf = 0; nf < 8; nf++) {
                int rn = nf * 8 + gid;
                uint32_t bh[2], bl[2];
                bh[0] = __float_as_uint(Kh[rn][kk + tig]);
                bh[1] = __float_as_uint(Kh[rn][kk + tig + 4]);
                bl[0] = __float_as_uint(Kl[rn][kk + tig]);
                bl[1] = __float_as_uint(Kl[rn][kk + tig + 4]);
                mma_tf32(S[nf], ql, bh);
                mma_tf32(S[nf], qh, bl);
                mma_tf32(S[nf], qh, bh);
            }
        }

        // ---- scale + causal mask + online softmax ----
        bool diag = (t == qt);
        float max0 = -1e30f, max1 = -1e30f;
#pragma unroll
        for (int nf = 0; nf < 8; nf++) {
            int colb = j0 + nf * 8 + 2 * tig;
            float s0 = S[nf][0] * 0.125f;
            float s1 = S[nf][1] * 0.125f;
            float s2 = S[nf][2] * 0.125f;
            float s3 = S[nf][3] * 0.125f;
            if (diag) {
                if (colb     > rowg0) s0 = -1e30f;
                if (colb + 1 > rowg0) s1 = -1e30f;
                if (colb     > rowg1) s2 = -1e30f;
                if (colb + 1 > rowg1) s3 = -1e30f;
            }
            S[nf][0] = s0; S[nf][1] = s1; S[nf][2] = s2; S[nf][3] = s3;
            max0 = fmaxf(max0, fmaxf(s0, s1));
            max1 = fmaxf(max1, fmaxf(s2, s3));
        }
        max0 = fmaxf(max0, __shfl_xor_sync(0xffffffffu, max0, 1));
        max0 = fmaxf(max0, __shfl_xor_sync(0xffffffffu, max0, 2));
        max1 = fmaxf(max1, __shfl_xor_sync(0xffffffffu, max1, 1));
        max1 = fmaxf(max1, __shfl_xor_sync(0xffffffffu, max1, 2));

        float mn0 = fmaxf(m0, max0), mn1 = fmaxf(m1, max1);
        float corr0 = __expf(m0 - mn0), corr1 = __expf(m1 - mn1);
        float ls0 = 0.f, ls1 = 0.f;
#pragma unroll
        for (int nf = 0; nf < 8; nf++) {
            int cb = nf * 8 + 2 * tig;
            float p0 = __expf(S[nf][0] - mn0);
            float p1 = __expf(S[nf][1] - mn0);
            float p2 = __expf(S[nf][2] - mn1);
            float p3 = __expf(S[nf][3] - mn1);
            ls0 += p0 + p1; ls1 += p2 + p3;
            Psw[gid][cb]     = p0; Psw[gid][cb + 1]     = p1;
            Psw[gid + 8][cb] = p2; Psw[gid + 8][cb + 1] = p3;
        }
        ls0 += __shfl_xor_sync(0xffffffffu, ls0, 1);
        ls0 += __shfl_xor_sync(0xffffffffu, ls0, 2);
        ls1 += __shfl_xor_sync(0xffffffffu, ls1, 1);
        ls1 += __shfl_xor_sync(0xffffffffu, ls1, 2);
        l0 = l0 * corr0 + ls0;
        l1 = l1 * corr1 + ls1;
        m0 = mn0; m1 = mn1;

#pragma unroll
        for (int df = 0; df < 8; df++) {
            o[df][0] *= corr0; o[df][1] *= corr0;
            o[df][2] *= corr1; o[df][3] *= corr1;
        }
        __syncwarp();

        // ---- o += P V (3xTF32); A = P (rows = warp's own), B = V^T ----
#pragma unroll
        for (int kk = 0; kk < 64; kk += 8) {
            uint32_t ph[4], pl[4];
            float pv;
            pv = Psw[gid][kk + tig];
            ph[0] = f2tf32(pv); pl[0] = f2tf32(pv - __uint_as_float(ph[0]));
            pv = Psw[gid + 8][kk + tig];
            ph[1] = f2tf32(pv); pl[1] = f2tf32(pv - __uint_as_float(ph[1]));
            pv = Psw[gid][kk + tig + 4];
            ph[2] = f2tf32(pv); pl[2] = f2tf32(pv - __uint_as_float(ph[2]));
            pv = Psw[gid + 8][kk + tig + 4];
            ph[3] = f2tf32(pv); pl[3] = f2tf32(pv - __uint_as_float(ph[3]));
#pragma unroll
            for (int df = 0; df < 8; df++) {
                int dn = df * 8 + gid;
                uint32_t vh[2], vl[2];
                vh[0] = __float_as_uint(Vh[dn][kk + tig]);
                vh[1] = __float_as_uint(Vh[dn][kk + tig + 4]);
                vl[0] = __float_as_uint(Vl[dn][kk + tig]);
                vl[1] = __float_as_uint(Vl[dn][kk + tig + 4]);
                mma_tf32(o[df], pl, vh);
                mma_tf32(o[df], ph, vl);
                mma_tf32(o[df], ph, vh);
            }
        }
    }

    float inv0 = 1.f / l0, inv1 = 1.f / l1;
    float* op0 = out + (long)rowg0 * C + h * HD;
    float* op1 = out + (long)rowg1 * C + h * HD;
#pragma unroll
    for (int df = 0; df < 8; df++) {
        int colb = df * 8 + 2 * tig;
        *(float2*)&op0[colb] = make_float2(o[df][0] * inv0, o[df][1] * inv0);
        *(float2*)&op1[colb] = make_float2(o[df][2] * inv1, o[df][3] * inv1);
    }
}

// ---------------- MoE gate: logits + top-2 + softmax ----------------
__global__ __launch_bounds__(256) void gate_kernel(const float* __restrict__ xn,
                                                   const float* __restrict__ gw,
                                                   int* __restrict__ tope,
                                                   float* __restrict__ tops)
{
    int t = blockIdx.x;
    int w = threadIdx.x >> 5, lane = threadIdx.x & 31;
    const float* x  = xn + (long)t * C;
    const float* gr = gw + (long)w * C;
    float s = 0.f;
    for (int c = lane * 4; c < C; c += 128) {
        float4 a = *(const float4*)&x[c];
        float4 b = *(const float4*)&gr[c];
        s += a.x * b.x + a.y * b.y + a.z * b.z + a.w * b.w;
    }
#pragma unroll
    for (int off = 16; off; off >>= 1) s += __shfl_xor_sync(0xffffffffu, s, off);
    __shared__ float lg[NE];
    if (lane == 0) lg[w] = s;
    __syncthreads();
    if (threadIdx.x == 0) {
        int i0 = 0;
#pragma unroll
        for (int e2 = 1; e2 < NE; e2++) if (lg[e2] > lg[i0]) i0 = e2;
        int i1 = (i0 == 0) ? 1 : 0;
#pragma unroll
        for (int e2 = 0; e2 < NE; e2++) if (e2 != i0 && lg[e2] > lg[i1]) i1 = e2;
        float ex = __expf(lg[i1] - lg[i0]);
        float s0 = 1.f / (1.f + ex);
        tope[t * 2]     = i0; tope[t * 2 + 1] = i1;
        tops[t * 2]     = s0; tops[t * 2 + 1] = 1.f - s0;
    }
}

// ---------------- routing compaction (single block; int atomics only) --------
__global__ void scatter_kernel(const int* __restrict__ tope)
{
    __shared__ int cnt[NE];
    __shared__ int off[NE + 1];
    int tid = threadIdx.x;
    if (tid < NE) cnt[tid] = 0;
    __syncthreads();
    for (int p = tid; p < P; p += 256) atomicAdd(&cnt[tope[p]], 1);
    __syncthreads();
    if (tid == 0) {
        off[0] = 0;
        for (int e = 0; e < NE; e++) off[e + 1] = off[e] + cnt[e];
        for (int e = 0; e <= NE; e++) g_off[e] = off[e];
    }
    __syncthreads();
    if (tid < NE) cnt[tid] = off[tid];
    __syncthreads();
    for (int p = tid; p < P; p += 256) {
        int e2  = tope[p];
        int pos = atomicAdd(&cnt[e2], 1);
        g_pairtok[pos] = p >> 1;   // token index
        g_tokpos[p] = pos;
    }
}

// ---------------- MoE combine: x += s0*y[p0] + s1*y[p1] ----------------
__global__ __launch_bounds__(192) void combine_kernel(
    const float* __restrict__ ybuf, const float* __restrict__ tops,
    const int* __restrict__ tokpos, float* x)
{
    int t = blockIdx.x;
    int c = threadIdx.x * 4;
    int p0 = tokpos[t * 2], p1 = tokpos[t * 2 + 1];
    float w0 = tops[t * 2], w1 = tops[t * 2 + 1];
    float4 a  = *(const float4*)&ybuf[(long)p0 * C + c];
    float4 b  = *(const float4*)&ybuf[(long)p1 * C + c];
    float4 xv = *(float4*)&x[(long)t * C + c];
    xv.x += w0 * a.x + w1 * b.x;
    xv.y += w0 * a.y + w1 * b.y;
    xv.z += w0 * a.z + w1 * b.z;
    xv.w += w0 * a.w + w1 * b.w;
    *(float4*)&x[(long)t * C + c] = xv;
}

// ---------------- lm head: logits[v] = dot(x_last, wte[v]) ----------------
__global__ __launch_bounds__(256) void lmhead_kernel(
    const float* __restrict__ xn, const float* __restrict__ wte,
    float* __restrict__ out)
{
    __shared__ float4 xs[C / 4];
    const float* x = xn + (long)(T - 1) * C;
    for (int ii = threadIdx.x; ii < C / 4; ii += 256) xs[ii] = *(const float4*)&x[ii * 4];
    __syncthreads();
    int w = threadIdx.x >> 5, lane = threadIdx.x & 31;
    int v = blockIdx.x * 8 + w;
    if (v >= V) return;
    const float* wr = wte + (long)v * C;
    float s = 0.f;
    for (int c = lane; c < C / 4; c += 32) {
        float4 a = *(const float4*)&wr[c * 4];
        float4 b = xs[c];
        s += a.x * b.x + a.y * b.y + a.z * b.z + a.w * b.w;
    }
#pragma unroll
    for (int off = 16; off; off >>= 1) s += __shfl_xor_sync(0xffffffffu, s, off);
    if (lane == 0) out[v] = s;
}

// ---------------- launch ----------------
extern "C" void kernel_launch(void* const* d_in, const int* in_sizes, int n_in,
                              void* d_out, int out_size)
{
    const int*   idx   = (const int*)d_in[0];
    const float* wte   = (const float*)d_in[1];
    const float* wpe   = (const float*)d_in[2];
    const float* ln1g  = (const float*)d_in[3];
    const float* qkvw  = (const float*)d_in[4];
    const float* projw = (const float*)d_in[5];
    const float* ln2g  = (const float*)d_in[6];
    const float* gatew = (const float*)d_in[7];
    const float* w1    = (const float*)d_in[8];
    const float* w2    = (const float*)d_in[9];
    const float* lnfg  = (const float*)d_in[10];
    float* out = (float*)d_out;

    float *p_x, *p_xn, *p_qkv, *p_attno, *p_h, *p_y, *p_tops;
    int *p_tope, *p_tokpos, *p_pairtok, *p_off;
    cudaGetSymbolAddress((void**)&p_x,       g_x);
    cudaGetSymbolAddress((void**)&p_xn,      g_xn);
    cudaGetSymbolAddress((void**)&p_qkv,     g_qkv);
    cudaGetSymbolAddress((void**)&p_attno,   g_attno);
    cudaGetSymbolAddress((void**)&p_h,       g_h);
    cudaGetSymbolAddress((void**)&p_y,       g_y);
    cudaGetSymbolAddress((void**)&p_tops,    g_tops);
    cudaGetSymbolAddress((void**)&p_tope,    g_tope);
    cudaGetSymbolAddress((void**)&p_tokpos,  g_tokpos);
    cudaGetSymbolAddress((void**)&p_pairtok, g_pairtok);
    cudaGetSymbolAddress((void**)&p_off,     g_off);

    cudaFuncSetAttribute(attn_kernel,
                         cudaFuncAttributeMaxDynamicSharedMemorySize, ATTN_SMEM);

    embed_kernel<<<T, C / 4>>>(idx, wte, wpe, p_x);

    for (int l = 0; l < 2; l++) {
        layernorm_kernel<<<T, 256>>>(p_x, p_xn, ln1g + (long)l * C, 0);
        sgemm_kernel<<<dim3(3 * C / BN, T / BM, 1), 256>>>(
            p_xn, C, qkvw + (long)l * 3 * C * C, 0, 3 * C, C,
            p_qkv, 3 * C, nullptr, nullptr, nullptr, T, 0);
        attn_kernel<<<dim3(T / 64, NH), 128, ATTN_SMEM>>>(p_qkv, p_attno);
        sgemm_kernel<<<dim3(C / BN, T / BM, 1), 256>>>(
            p_attno, C, projw + (long)l * C * C, 0, C, C,
            p_x, C, p_x, nullptr, nullptr, T, 0);

        layernorm_kernel<<<T, 256>>>(p_x, p_xn, ln2g + (long)l * C, 0);
        gate_kernel<<<T, 256>>>(p_xn, gatew + (long)l * NE * C, p_tope, p_tops);
        scatter_kernel<<<1, 256>>>(p_tope);
        sgemm_kernel<<<dim3(C4 / BN, P / BM, NE), 256>>>(
            p_xn, C, w1 + (long)l * NE * C4 * C, (long)C4 * C, C4, C,
            p_h, C4, nullptr, p_off, p_pairtok, 0, 1);
        sgemm_kernel<<<dim3(C / BN, P / BM, NE), 256>>>(
            p_h, C4, w2 + (long)l * NE * C * C4, (long)C * C4, C, C4,
            p_y, C, nullptr, p_off, nullptr, 0, 0);
        combine_kernel<<<T, C / 4>>>(p_y, p_tops, p_tokpos, p_x);
    }

    layernorm_kernel<<<1, 256>>>(p_x, p_xn, lnfg, T - 1);
    lmhead_kernel<<<(V + 7) / 8, 256>>>(p_xn, wte, out);
}

// round 14
// speedup vs baseline: 3.2054x; 1.2824x over previous
#include <cuda_runtime.h>
#include <cuda_bf16.h>
#include <cstdint>

namespace {
constexpr int T  = 1024;
constexpr int C  = 768;
constexpr int NH = 12;
constexpr int HD = 64;
constexpr int NE = 8;
constexpr int V  = 50257;
constexpr int C4 = 3072;
constexpr int P  = 2048;   // token-expert pairs (T * topK)
// bf16 attn smem: 6 tile buffers [64][36] words + 8 P buffers [16][36] words
constexpr int ATTN_SMEM = (6 * 64 * 36 + 8 * 16 * 36) * 4;   // 73728 B
}

// ---------------- scratch (device globals; no allocation) ----------------
__device__ float g_x[T * C];
__device__ float g_xn[T * C];
__device__ float g_qkv[T * 3 * C];
__device__ float g_attno[T * C];
__device__ float g_h[P * C4];     // 25 MB
__device__ float g_y[P * C];
__device__ int   g_tope[P];
__device__ float g_tops[P];
__device__ int   g_tokpos[P];
__device__ int   g_pairtok[P];
__device__ int   g_off[NE + 1];

// ---------------- embed: x = wte[idx] + wpe ----------------
__global__ void embed_kernel(const int* __restrict__ idx,
                             const float* __restrict__ wte,
                             const float* __restrict__ wpe,
                             float* __restrict__ x)
{
    int t = blockIdx.x;
    int c = threadIdx.x * 4;
    int tok = idx[t];
    float4 a = *(const float4*)&wte[(long)tok * C + c];
    float4 b = *(const float4*)&wpe[(long)t * C + c];
    float4 r = make_float4(a.x + b.x, a.y + b.y, a.z + b.z, a.w + b.w);
    *(float4*)&x[(long)t * C + c] = r;
}

// ---------------- layernorm (gamma only, eps 1e-5) ----------------
__global__ __launch_bounds__(256) void layernorm_kernel(
    const float* __restrict__ in, float* __restrict__ out,
    const float* __restrict__ g, int rowbase)
{
    int row = rowbase + blockIdx.x;
    const float* x = in + (long)row * C;
    int tid = threadIdx.x;
    __shared__ float red[256];
    float v[3];
    float s = 0.f;
#pragma unroll
    for (int i = 0; i < 3; i++) { v[i] = x[tid + i * 256]; s += v[i]; }
    red[tid] = s; __syncthreads();
    for (int st = 128; st > 0; st >>= 1) { if (tid < st) red[tid] += red[tid + st]; __syncthreads(); }
    float mu = red[0] * (1.f / C);
    __syncthreads();
    float q = 0.f;
#pragma unroll
    for (int i = 0; i < 3; i++) { float d = v[i] - mu; q += d * d; }
    red[tid] = q; __syncthreads();
    for (int st = 128; st > 0; st >>= 1) { if (tid < st) red[tid] += red[tid + st]; __syncthreads(); }
    float var = red[0] * (1.f / C);
    float rstd = rsqrtf(var + 1e-5f);
#pragma unroll
    for (int i = 0; i < 3; i++) {
        int c = tid + i * 256;
        out[(long)row * C + c] = (v[i] - mu) * rstd * g[c];
    }
}

// ---------------- bf16 split helpers ----------------
__device__ __forceinline__ void mma_bf16(float* c, const uint32_t* a, const uint32_t* b) {
    asm volatile(
        "mma.sync.aligned.m16n8k16.row.col.f32.bf16.bf16.f32 "
        "{%0,%1,%2,%3}, {%4,%5,%6,%7}, {%8,%9}, {%0,%1,%2,%3};\n"
        : "+f"(c[0]), "+f"(c[1]), "+f"(c[2]), "+f"(c[3])
        : "r"(a[0]), "r"(a[1]), "r"(a[2]), "r"(a[3]),
          "r"(b[0]), "r"(b[1]));
}

// Fast split of two adjacent k floats into packed bf16x2 hi and lo words.
// hi = truncated high 16 bits (1 PRMT for the pair); lo = x - hi (exact), packed by cvt.
// x0 -> low half of word, x1 -> high half.
__device__ __forceinline__ void bsplit2_fast(float x0, float x1, uint32_t& wh, uint32_t& wl) {
    uint32_t u0 = __float_as_uint(x0), u1 = __float_as_uint(x1);
    uint32_t h;
    asm("prmt.b32 %0, %1, %2, 0x7632;" : "=r"(h) : "r"(u0), "r"(u1));
    float l0 = x0 - __uint_as_float(u0 & 0xffff0000u);
    float l1 = x1 - __uint_as_float(u1 & 0xffff0000u);
    uint32_t l;
    asm("cvt.rn.bf16x2.f32 %0, %1, %2;" : "=r"(l) : "f"(l1), "f"(l0));
    wh = h; wl = l;
}

// ---------------- split-bf16 tensor-core GEMM (128x128 tiles, prefetch) -----
// out[m, n] = sum_k A[row(m), k] * B[e][n, k]   (B row-major [N, K])
// A = Ah + Al, B = Bh + Bl (bf16 each); C = Al*Bh + Ah*Bl + Ah*Bh.
// offsets != null -> grouped-by-expert along blockIdx.z; gather != null -> A row indirection.
constexpr int BM = 128, BN = 128, BKF = 32;   // k floats per stage (16 words)
constexpr int SSTR = 20;   // smem row stride (words): conflict-free frag loads

__global__ __launch_bounds__(256) void sgemm_kernel(
    const float* __restrict__ Abase, int lda,
    const float* __restrict__ Bbase, long bstride,
    int N, int K,
    float* Out, int ldo,
    const float* resid,
    const int* __restrict__ offsets,
    const int* __restrict__ gather,
    int M, int dogelu)
{
    int e = blockIdx.z;
    int rowbase = 0, cnt = M;
    if (offsets) { rowbase = offsets[e]; cnt = offsets[e + 1] - rowbase; }
    int m0 = blockIdx.y * BM;
    if (m0 >= cnt) return;
    int n0 = blockIdx.x * BN;
    const float* B = Bbase + (long)e * bstride;

    __shared__ __align__(16) uint32_t Ah[BM][SSTR];
    __shared__ __align__(16) uint32_t Al[BM][SSTR];
    __shared__ __align__(16) uint32_t Bh[BN][SSTR];
    __shared__ __align__(16) uint32_t Bl[BN][SSTR];

    int tid  = threadIdx.x;
    int lane = tid & 31, warp = tid >> 5;
    int gid  = lane >> 2, tig = lane & 3;
    int wm   = (warp & 1) * 64;      // warp tile: 64 (m) x 32 (n)
    int wn   = (warp >> 1) * 32;

    // loader: 128 rows x 32 k-floats per operand; 4 threads per row (8 floats each), 2 passes
    int lrow0 = tid >> 2;           // 0..63
    int lw    = (tid & 3) * 4;      // word offset 0/4/8/12
    int lf    = lw * 2;             // float offset 0/8/16/24
    long aof[2]; bool av[2]; long bof[2];
#pragma unroll
    for (int i = 0; i < 2; i++) {
        int row = lrow0 + i * 64;
        int gm  = m0 + row;
        av[i] = gm < cnt;
        int arow = 0;
        if (av[i]) arow = gather ? gather[rowbase + gm] : (rowbase + gm);
        aof[i] = (long)arow * lda + lf;
        bof[i] = (long)(n0 + row) * K + lf;
    }

    float c[4][4][4];
#pragma unroll
    for (int i = 0; i < 4; i++)
#pragma unroll
        for (int j = 0; j < 4; j++)
#pragma unroll
            for (int r = 0; r < 4; r++) c[i][j][r] = 0.f;

    // prefetch k0 = 0
    float4 pa[2][2], pb[2][2];
#pragma unroll
    for (int i = 0; i < 2; i++) {
        if (av[i]) {
            pa[i][0] = *(const float4*)&Abase[aof[i]];
            pa[i][1] = *(const float4*)&Abase[aof[i] + 4];
        } else {
            pa[i][0] = pa[i][1] = make_float4(0.f, 0.f, 0.f, 0.f);
        }
        pb[i][0] = *(const float4*)&B[bof[i]];
        pb[i][1] = *(const float4*)&B[bof[i] + 4];
    }

    for (int k0 = 0; k0 < K; k0 += BKF) {
        // convert + store current stage
#pragma unroll
        for (int i = 0; i < 2; i++) {
            int row = lrow0 + i * 64;
            uint4 uh, ul;
            bsplit2_fast(pa[i][0].x, pa[i][0].y, uh.x, ul.x);
            bsplit2_fast(pa[i][0].z, pa[i][0].w, uh.y, ul.y);
            bsplit2_fast(pa[i][1].x, pa[i][1].y, uh.z, ul.z);
            bsplit2_fast(pa[i][1].z, pa[i][1].w, uh.w, ul.w);
            *(uint4*)&Ah[row][lw] = uh;
            *(uint4*)&Al[row][lw] = ul;
            bsplit2_fast(pb[i][0].x, pb[i][0].y, uh.x, ul.x);
            bsplit2_fast(pb[i][0].z, pb[i][0].w, uh.y, ul.y);
            bsplit2_fast(pb[i][1].x, pb[i][1].y, uh.z, ul.z);
            bsplit2_fast(pb[i][1].z, pb[i][1].w, uh.w, ul.w);
            *(uint4*)&Bh[row][lw] = uh;
            *(uint4*)&Bl[row][lw] = ul;
        }
        __syncthreads();

        // prefetch next stage into registers (latency hidden by MMAs below)
        int kn = k0 + BKF;
        if (kn < K) {
#pragma unroll
            for (int i = 0; i < 2; i++) {
                if (av[i]) {
                    pa[i][0] = *(const float4*)&Abase[aof[i] + kn];
                    pa[i][1] = *(const float4*)&Abase[aof[i] + kn + 4];
                }
                pb[i][0] = *(const float4*)&B[bof[i] + kn];
                pb[i][1] = *(const float4*)&B[bof[i] + kn + 4];
            }
        }

        // two k16 MMA steps (word offsets 0 and 8)
#pragma unroll
        for (int kk = 0; kk < 16; kk += 8) {
            uint32_t ah[4][4], al[4][4], bh[4][2], bl[4][2];
#pragma unroll
            for (int i = 0; i < 4; i++) {
                int r0 = wm + i * 16 + gid;
                ah[i][0] = Ah[r0][kk + tig];
                ah[i][1] = Ah[r0 + 8][kk + tig];
                ah[i][2] = Ah[r0][kk + tig + 4];
                ah[i][3] = Ah[r0 + 8][kk + tig + 4];
                al[i][0] = Al[r0][kk + tig];
                al[i][1] = Al[r0 + 8][kk + tig];
                al[i][2] = Al[r0][kk + tig + 4];
                al[i][3] = Al[r0 + 8][kk + tig + 4];
            }
#pragma unroll
            for (int j = 0; j < 4; j++) {
                int rn = wn + j * 8 + gid;
                bh[j][0] = Bh[rn][kk + tig];
                bh[j][1] = Bh[rn][kk + tig + 4];
                bl[j][0] = Bl[rn][kk + tig];
                bl[j][1] = Bl[rn][kk + tig + 4];
            }
#pragma unroll
            for (int i = 0; i < 4; i++)
#pragma unroll
                for (int j = 0; j < 4; j++) {
                    mma_bf16(c[i][j], al[i], bh[j]);   // small terms first
                    mma_bf16(c[i][j], ah[i], bl[j]);
                    mma_bf16(c[i][j], ah[i], bh[j]);
                }
        }
        __syncthreads();
    }

    // epilogue: c[i][j] = {(gid, 2tig), (gid, 2tig+1), (gid+8, 2tig), (gid+8, 2tig+1)}
#pragma unroll
    for (int i = 0; i < 4; i++) {
#pragma unroll
        for (int half = 0; half < 2; half++) {
            int gm = m0 + wm + i * 16 + gid + half * 8;
            if (gm >= cnt) continue;
            long orow = rowbase + gm;
#pragma unroll
            for (int j = 0; j < 4; j++) {
                int col = n0 + wn + j * 8 + 2 * tig;
                float v0 = c[i][j][half * 2];
                float v1 = c[i][j][half * 2 + 1];
                if (dogelu) {
                    v0 = 0.5f * v0 * (1.f + erff(v0 * 0.70710678118654752f));
                    v1 = 0.5f * v1 * (1.f + erff(v1 * 0.70710678118654752f));
                }
                if (resid) {
                    float2 rv = *(const float2*)&resid[orow * ldo + col];
                    v0 += rv.x; v1 += rv.y;
                }
                float2 r2 = make_float2(v0, v1);
                *(float2*)&Out[orow * ldo + col] = r2;
            }
        }
    }
}

// ---------------- tensor-core flash attention (split-bf16) ----------------
// block = (64-query tile, head), 4 warps; warp w owns query rows 16w..16w+15.
// All smem packed bf16x2 hi/lo; S and P·V via m16n8k16 with 2-term compensation.
constexpr int ASTR = 36;   // word stride: uint4-aligned, conflict-free frag loads

__global__ __launch_bounds__(128) void attn_kernel(const float* __restrict__ qkv,
                                                   float* __restrict__ out)
{
    extern __shared__ uint32_t smw[];
    uint32_t* Qh = smw;                 // [64][ASTR]
    uint32_t* Ql = Qh + 64 * ASTR;
    uint32_t* Kh = Ql + 64 * ASTR;
    uint32_t* Kl = Kh + 64 * ASTR;
    uint32_t* Vh = Kl + 64 * ASTR;      // transposed [d][j-pair word]
    uint32_t* Vl = Vh + 64 * ASTR;

    int h    = blockIdx.y;
    int qt   = (int)gridDim.x - 1 - (int)blockIdx.x;   // big tiles first
    int tid  = threadIdx.x;
    int warp = tid >> 5, lane = tid & 31;
    int gid  = lane >> 2, tig = lane & 3;

    uint32_t* Ph = Vl + 64 * ASTR + warp * (16 * ASTR);              // [16][ASTR]
    uint32_t* Pl = Vl + 64 * ASTR + 4 * (16 * ASTR) + warp * (16 * ASTR);

    // load Q tile (64 x 64) -> packed hi/lo
    {
        int row  = tid >> 1;
        int half = tid & 1;
        const float* qr = qkv + (long)(qt * 64 + row) * (3 * C) + h * HD + half * 32;
#pragma unroll
        for (int d = 0; d < 32; d += 8) {
            float4 a = *(const float4*)&qr[d];
            float4 b = *(const float4*)&qr[d + 4];
            uint4 uh, ul;
            bsplit2_fast(a.x, a.y, uh.x, ul.x);
            bsplit2_fast(a.z, a.w, uh.y, ul.y);
            bsplit2_fast(b.x, b.y, uh.z, ul.z);
            bsplit2_fast(b.z, b.w, uh.w, ul.w);
            int w = half * 16 + d / 2;
            *(uint4*)&Qh[row * ASTR + w] = uh;
            *(uint4*)&Ql[row * ASTR + w] = ul;
        }
    }

    float o[8][4];
#pragma unroll
    for (int df = 0; df < 8; df++)
#pragma unroll
        for (int r = 0; r < 4; r++) o[df][r] = 0.f;
    float m0 = -1e30f, m1 = -1e30f, l0 = 0.f, l1 = 0.f;

    int rowg0 = qt * 64 + warp * 16 + gid;
    int rowg1 = rowg0 + 8;

    int ntiles = qt + 1;
    for (int t = 0; t < ntiles; t++) {
        int j0 = t * 64;
        __syncthreads();   // prev tile's MMA reads done (and Q ready at t=0)
        {
            // K: 2 threads per row, 32 dims each
            int row  = tid >> 1;
            int half = tid & 1;
            const float* kr = qkv + (long)(j0 + row) * (3 * C) + C + h * HD + half * 32;
#pragma unroll
            for (int d = 0; d < 32; d += 8) {
                float4 a = *(const float4*)&kr[d];
                float4 b = *(const float4*)&kr[d + 4];
                uint4 uh, ul;
                bsplit2_fast(a.x, a.y, uh.x, ul.x);
                bsplit2_fast(a.z, a.w, uh.y, ul.y);
                bsplit2_fast(b.x, b.y, uh.z, ul.z);
                bsplit2_fast(b.z, b.w, uh.w, ul.w);
                int w = half * 16 + d / 2;
                *(uint4*)&Kh[row * ASTR + w] = uh;
                *(uint4*)&Kl[row * ASTR + w] = ul;
            }
            // V transposed: thread owns j-pair jp, dim group a4 (+16i)
            int jp = tid >> 2;            // 0..31 -> keys 2jp, 2jp+1
            int a4 = (tid & 3) * 4;
            const float* v0 = qkv + (long)(j0 + 2 * jp) * (3 * C) + 2 * C + h * HD;
            const float* v1 = v0 + 3 * C;
#pragma unroll
            for (int i = 0; i < 4; i++) {
                int db = a4 + i * 16;
                float4 x = *(const float4*)&v0[db];
                float4 y = *(const float4*)&v1[db];
                uint32_t wh, wl;
                bsplit2_fast(x.x, y.x, wh, wl); Vh[(db + 0) * ASTR + jp] = wh; Vl[(db + 0) * ASTR + jp] = wl;
                bsplit2_fast(x.y, y.y, wh, wl); Vh[(db + 1) * ASTR + jp] = wh; Vl[(db + 1) * ASTR + jp] = wl;
                bsplit2_fast(x.z, y.z, wh, wl); Vh[(db + 2) * ASTR + jp] = wh; Vl[(db + 2) * ASTR + jp] = wl;
                bsplit2_fast(x.w, y.w, wh, wl); Vh[(db + 3) * ASTR + jp] = wh; Vl[(db + 3) * ASTR + jp] = wl;
            }
        }
        __syncthreads();

        // ---- S = Q K^T (split-bf16) ----
        float S[8][4];
#pragma unroll
        for (int nf = 0; nf < 8; nf++)
#pragma unroll
            for (int r = 0; r < 4; r++) S[nf][r] = 0.f;

        int r0 = warp * 16 + gid;
#pragma unroll
        for (int ch = 0; ch < 4; ch++) {
            int kk = ch * 8;
            uint32_t qh[4], ql[4];
            qh[0] = Qh[r0 * ASTR + kk + tig];
            qh[1] = Qh[(r0 + 8) * ASTR + kk + tig];
            qh[2] = Qh[r0 * ASTR + kk + tig + 4];
            qh[3] = Qh[(r0 + 8) * ASTR + kk + tig + 4];
            ql[0] = Ql[r0 * ASTR + kk + tig];
            ql[1] = Ql[(r0 + 8) * ASTR + kk + tig];
            ql[2] = Ql[r0 * ASTR + kk + tig + 4];
            ql[3] = Ql[(r0 + 8) * ASTR + kk + tig + 4];
#pragma unroll
            for (int nf = 0; nf < 8; nf++) {
                int rn = nf * 8 + gid;
                uint32_t bh[2], bl[2];
                bh[0] = Kh[rn * ASTR + kk + tig];
                bh[1] = Kh[rn * ASTR + kk + tig + 4];
                bl[0] = Kl[rn * ASTR + kk + tig];
                bl[1] = Kl[rn * ASTR + kk + tig + 4];
                mma_bf16(S[nf], ql, bh);
                mma_bf16(S[nf], qh, bl);
                mma_bf16(S[nf], qh, bh);
            }
        }

        // ---- scale + causal mask + online softmax ----
        bool diag = (t == qt);
        float max0 = -1e30f, max1 = -1e30f;
#pragma unroll
        for (int nf = 0; nf < 8; nf++) {
            int colb = j0 + nf * 8 + 2 * tig;
            float s0 = S[nf][0] * 0.125f;
            float s1 = S[nf][1] * 0.125f;
            float s2 = S[nf][2] * 0.125f;
            float s3 = S[nf][3] * 0.125f;
            if (diag) {
                if (colb     > rowg0) s0 = -1e30f;
                if (colb + 1 > rowg0) s1 = -1e30f;
                if (colb     > rowg1) s2 = -1e30f;
                if (colb + 1 > rowg1) s3 = -1e30f;
            }
            S[nf][0] = s0; S[nf][1] = s1; S[nf][2] = s2; S[nf][3] = s3;
            max0 = fmaxf(max0, fmaxf(s0, s1));
            max1 = fmaxf(max1, fmaxf(s2, s3));
        }
        max0 = fmaxf(max0, __shfl_xor_sync(0xffffffffu, max0, 1));
        max0 = fmaxf(max0, __shfl_xor_sync(0xffffffffu, max0, 2));
        max1 = fmaxf(max1, __shfl_xor_sync(0xffffffffu, max1, 1));
        max1 = fmaxf(max1, __shfl_xor_sync(0xffffffffu, max1, 2));

        float mn0 = fmaxf(m0, max0), mn1 = fmaxf(m1, max1);
        float corr0 = __expf(m0 - mn0), corr1 = __expf(m1 - mn1);
        float ls0 = 0.f, ls1 = 0.f;
#pragma unroll
        for (int nf = 0; nf < 8; nf++) {
            int w = nf * 4 + tig;
            float p0 = __expf(S[nf][0] - mn0);
            float p1 = __expf(S[nf][1] - mn0);
            float p2 = __expf(S[nf][2] - mn1);
            float p3 = __expf(S[nf][3] - mn1);
            ls0 += p0 + p1; ls1 += p2 + p3;
            uint32_t wh, wl;
            bsplit2_fast(p0, p1, wh, wl);
            Ph[gid * ASTR + w] = wh; Pl[gid * ASTR + w] = wl;
            bsplit2_fast(p2, p3, wh, wl);
            Ph[(gid + 8) * ASTR + w] = wh; Pl[(gid + 8) * ASTR + w] = wl;
        }
        ls0 += __shfl_xor_sync(0xffffffffu, ls0, 1);
        ls0 += __shfl_xor_sync(0xffffffffu, ls0, 2);
        ls1 += __shfl_xor_sync(0xffffffffu, ls1, 1);
        ls1 += __shfl_xor_sync(0xffffffffu, ls1, 2);
        l0 = l0 * corr0 + ls0;
        l1 = l1 * corr1 + ls1;
        m0 = mn0; m1 = mn1;

#pragma unroll
        for (int df = 0; df < 8; df++) {
            o[df][0] *= corr0; o[df][1] *= corr0;
            o[df][2] *= corr1; o[df][3] *= corr1;
        }
        __syncwarp();

        // ---- o += P V (split-bf16); A = P (warp-private), B = V^T ----
#pragma unroll
        for (int ch = 0; ch < 4; ch++) {
            int kk = ch * 8;
            uint32_t ph[4], pl[4];
            ph[0] = Ph[gid * ASTR + kk + tig];
            ph[1] = Ph[(gid + 8) * ASTR + kk + tig];
            ph[2] = Ph[gid * ASTR + kk + tig + 4];
            ph[3] = Ph[(gid + 8) * ASTR + kk + tig + 4];
            pl[0] = Pl[gid * ASTR + kk + tig];
            pl[1] = Pl[(gid + 8) * ASTR + kk + tig];
            pl[2] = Pl[gid * ASTR + kk + tig + 4];
            pl[3] = Pl[(gid + 8) * ASTR + kk + tig + 4];
#pragma unroll
            for (int df = 0; df < 8; df++) {
                int dn = df * 8 + gid;
                uint32_t vh[2], vl[2];
                vh[0] = Vh[dn * ASTR + kk + tig];
                vh[1] = Vh[dn * ASTR + kk + tig + 4];
                vl[0] = Vl[dn * ASTR + kk + tig];
                vl[1] = Vl[dn * ASTR + kk + tig + 4];
                mma_bf16(o[df], pl, vh);
                mma_bf16(o[df], ph, vl);
                mma_bf16(o[df], ph, vh);
            }
        }
    }

    float inv0 = 1.f / l0, inv1 = 1.f / l1;
    float* op0 = out + (long)rowg0 * C + h * HD;
    float* op1 = out + (long)rowg1 * C + h * HD;
#pragma unroll
    for (int df = 0; df < 8; df++) {
        int colb = df * 8 + 2 * tig;
        *(float2*)&op0[colb] = make_float2(o[df][0] * inv0, o[df][1] * inv0);
        *(float2*)&op1[colb] = make_float2(o[df][2] * inv1, o[df][3] * inv1);
    }
}

// ---------------- MoE gate: logits + top-2 + softmax ----------------
__global__ __launch_bounds__(256) void gate_kernel(const float* __restrict__ xn,
                                                   const float* __restrict__ gw,
                                                   int* __restrict__ tope,
                                                   float* __restrict__ tops)
{
    int t = blockIdx.x;
    int w = threadIdx.x >> 5, lane = threadIdx.x & 31;
    const float* x  = xn + (long)t * C;
    const float* gr = gw + (long)w * C;
    float s = 0.f;
    for (int c = lane * 4; c < C; c += 128) {
        float4 a = *(const float4*)&x[c];
        float4 b = *(const float4*)&gr[c];
        s += a.x * b.x + a.y * b.y + a.z * b.z + a.w * b.w;
    }
#pragma unroll
    for (int off = 16; off; off >>= 1) s += __shfl_xor_sync(0xffffffffu, s, off);
    __shared__ float lg[NE];
    if (lane == 0) lg[w] = s;
    __syncthreads();
    if (threadIdx.x == 0) {
        int i0 = 0;
#pragma unroll
        for (int e2 = 1; e2 < NE; e2++) if (lg[e2] > lg[i0]) i0 = e2;
        int i1 = (i0 == 0) ? 1 : 0;
#pragma unroll
        for (int e2 = 0; e2 < NE; e2++) if (e2 != i0 && lg[e2] > lg[i1]) i1 = e2;
        float ex = __expf(lg[i1] - lg[i0]);
        float s0 = 1.f / (1.f + ex);
        tope[t * 2]     = i0; tope[t * 2 + 1] = i1;
        tops[t * 2]     = s0; tops[t * 2 + 1] = 1.f - s0;
    }
}

// ---------------- routing compaction (single block; int atomics only) --------
__global__ void scatter_kernel(const int* __restrict__ tope)
{
    __shared__ int cnt[NE];
    __shared__ int off[NE + 1];
    int tid = threadIdx.x;
    if (tid < NE) cnt[tid] = 0;
    __syncthreads();
    for (int p = tid; p < P; p += 256) atomicAdd(&cnt[tope[p]], 1);
    __syncthreads();
    if (tid == 0) {
        off[0] = 0;
        for (int e = 0; e < NE; e++) off[e + 1] = off[e] + cnt[e];
        for (int e = 0; e <= NE; e++) g_off[e] = off[e];
    }
    __syncthreads();
    if (tid < NE) cnt[tid] = off[tid];
    __syncthreads();
    for (int p = tid; p < P; p += 256) {
        int e2  = tope[p];
        int pos = atomicAdd(&cnt[e2], 1);
        g_pairtok[pos] = p >> 1;   // token index
        g_tokpos[p] = pos;
    }
}

// ---------------- MoE combine: x += s0*y[p0] + s1*y[p1] ----------------
__global__ __launch_bounds__(192) void combine_kernel(
    const float* __restrict__ ybuf, const float* __restrict__ tops,
    const int* __restrict__ tokpos, float* x)
{
    int t = blockIdx.x;
    int c = threadIdx.x * 4;
    int p0 = tokpos[t * 2], p1 = tokpos[t * 2 + 1];
    float w0 = tops[t * 2], w1 = tops[t * 2 + 1];
    float4 a  = *(const float4*)&ybuf[(long)p0 * C + c];
    float4 b  = *(const float4*)&ybuf[(long)p1 * C + c];
    float4 xv = *(float4*)&x[(long)t * C + c];
    xv.x += w0 * a.x + w1 * b.x;
    xv.y += w0 * a.y + w1 * b.y;
    xv.z += w0 * a.z + w1 * b.z;
    xv.w += w0 * a.w + w1 * b.w;
    *(float4*)&x[(long)t * C + c] = xv;
}

// ---------------- lm head: logits[v] = dot(x_last, wte[v]) ----------------
__global__ __launch_bounds__(256) void lmhead_kernel(
    const float* __restrict__ xn, const float* __restrict__ wte,
    float* __restrict__ out)
{
    __shared__ float4 xs[C / 4];
    const float* x = xn + (long)(T - 1) * C;
    for (int ii = threadIdx.x; ii < C / 4; ii += 256) xs[ii] = *(const float4*)&x[ii * 4];
    __syncthreads();
    int w = threadIdx.x >> 5, lane = threadIdx.x & 31;
    int v = blockIdx.x * 8 + w;
    if (v >= V) return;
    const float* wr = wte + (long)v * C;
    float s = 0.f;
    for (int c = lane; c < C / 4; c += 32) {
        float4 a = *(const float4*)&wr[c * 4];
        float4 b = xs[c];
        s += a.x * b.x + a.y * b.y + a.z * b.z + a.w * b.w;
    }
#pragma unroll
    for (int off = 16; off; off >>= 1) s += __shfl_xor_sync(0xffffffffu, s, off);
    if (lane == 0) out[v] = s;
}

// ---------------- launch ----------------
extern "C" void kernel_launch(void* const* d_in, const int* in_sizes, int n_in,
                              void* d_out, int out_size)
{
    const int*   idx   = (const int*)d_in[0];
    const float* wte   = (const float*)d_in[1];
    const float* wpe   = (const float*)d_in[2];
    const float* ln1g  = (const float*)d_in[3];
    const float* qkvw  = (const float*)d_in[4];
    const float* projw = (const float*)d_in[5];
    const float* ln2g  = (const float*)d_in[6];
    const float* gatew = (const float*)d_in[7];
    const float* w1    = (const float*)d_in[8];
    const float* w2    = (const float*)d_in[9];
    const float* lnfg  = (const float*)d_in[10];
    float* out = (float*)d_out;

    float *p_x, *p_xn, *p_qkv, *p_attno, *p_h, *p_y, *p_tops;
    int *p_tope, *p_tokpos, *p_pairtok, *p_off;
    cudaGetSymbolAddress((void**)&p_x,       g_x);
    cudaGetSymbolAddress((void**)&p_xn,      g_xn);
    cudaGetSymbolAddress((void**)&p_qkv,     g_qkv);
    cudaGetSymbolAddress((void**)&p_attno,   g_attno);
    cudaGetSymbolAddress((void**)&p_h,       g_h);
    cudaGetSymbolAddress((void**)&p_y,       g_y);
    cudaGetSymbolAddress((void**)&p_tops,    g_tops);
    cudaGetSymbolAddress((void**)&p_tope,    g_tope);
    cudaGetSymbolAddress((void**)&p_tokpos,  g_tokpos);
    cudaGetSymbolAddress((void**)&p_pairtok, g_pairtok);
    cudaGetSymbolAddress((void**)&p_off,     g_off);

    cudaFuncSetAttribute(attn_kernel,
                         cudaFuncAttributeMaxDynamicSharedMemorySize, ATTN_SMEM);

    embed_kernel<<<T, C / 4>>>(idx, wte, wpe, p_x);

    for (int l = 0; l < 2; l++) {
        layernorm_kernel<<<T, 256>>>(p_x, p_xn, ln1g + (long)l * C, 0);
        sgemm_kernel<<<dim3(3 * C / BN, T / BM, 1), 256>>>(
            p_xn, C, qkvw + (long)l * 3 * C * C, 0, 3 * C, C,
            p_qkv, 3 * C, nullptr, nullptr, nullptr, T, 0);
        attn_kernel<<<dim3(T / 64, NH), 128, ATTN_SMEM>>>(p_qkv, p_attno);
        sgemm_kernel<<<dim3(C / BN, T / BM, 1), 256>>>(
            p_attno, C, projw + (long)l * C * C, 0, C, C,
            p_x, C, p_x, nullptr, nullptr, T, 0);

        layernorm_kernel<<<T, 256>>>(p_x, p_xn, ln2g + (long)l * C, 0);
        gate_kernel<<<T, 256>>>(p_xn, gatew + (long)l * NE * C, p_tope, p_tops);
        scatter_kernel<<<1, 256>>>(p_tope);
        sgemm_kernel<<<dim3(C4 / BN, P / BM, NE), 256>>>(
            p_xn, C, w1 + (long)l * NE * C4 * C, (long)C4 * C, C4, C,
            p_h, C4, nullptr, p_off, p_pairtok, 0, 1);
        sgemm_kernel<<<dim3(C / BN, P / BM, NE), 256>>>(
            p_h, C4, w2 + (long)l * NE * C * C4, (long)C * C4, C, C4,
            p_y, C, nullptr, p_off, nullptr, 0, 0);
        combine_kernel<<<T, C / 4>>>(p_y, p_tops, p_tokpos, p_x);
    }

    layernorm_kernel<<<1, 256>>>(p_x, p_xn, lnfg, T - 1);
    lmhead_kernel<<<(V + 7) / 8, 256>>>(p_xn, wte, out);
}

// round 16
// speedup vs baseline: 3.2827x; 1.0241x over previous
#include <cuda_runtime.h>
#include <cuda_bf16.h>
#include <cstdint>

namespace {
constexpr int T  = 1024;
constexpr int C  = 768;
constexpr int NH = 12;
constexpr int HD = 64;
constexpr int NE = 8;
constexpr int V  = 50257;
constexpr int C4 = 3072;
constexpr int P  = 2048;   // token-expert pairs (T * topK)
// bf16 attn smem: 6 tile buffers [64][36] words + 8 P buffers [16][36] words
constexpr int ATTN_SMEM = (6 * 64 * 36 + 8 * 16 * 36) * 4;   // 73728 B
}

// ---------------- scratch (device globals; no allocation) ----------------
__device__ float g_x[T * C];
__device__ float g_xn[T * C];
__device__ float g_qkv[T * 3 * C];
__device__ float g_attno[T * C];
__device__ float g_h[P * C4];     // 25 MB
__device__ float g_y[P * C];
__device__ int   g_tope[P];
__device__ float g_tops[P];
__device__ int   g_tokpos[P];
__device__ int   g_pairtok[P];
__device__ int   g_off[NE + 1];

// ---------------- embed: x = wte[idx] + wpe ----------------
__global__ void embed_kernel(const int* __restrict__ idx,
                             const float* __restrict__ wte,
                             const float* __restrict__ wpe,
                             float* __restrict__ x)
{
    int t = blockIdx.x;
    int c = threadIdx.x * 4;
    int tok = idx[t];
    float4 a = *(const float4*)&wte[(long)tok * C + c];
    float4 b = *(const float4*)&wpe[(long)t * C + c];
    float4 r = make_float4(a.x + b.x, a.y + b.y, a.z + b.z, a.w + b.w);
    *(float4*)&x[(long)t * C + c] = r;
}

// ---------------- layernorm (gamma only, eps 1e-5) ----------------
__global__ __launch_bounds__(256) void layernorm_kernel(
    const float* __restrict__ in, float* __restrict__ out,
    const float* __restrict__ g, int rowbase)
{
    int row = rowbase + blockIdx.x;
    const float* x = in + (long)row * C;
    int tid = threadIdx.x;
    __shared__ float red[256];
    float v[3];
    float s = 0.f;
#pragma unroll
    for (int i = 0; i < 3; i++) { v[i] = x[tid + i * 256]; s += v[i]; }
    red[tid] = s; __syncthreads();
    for (int st = 128; st > 0; st >>= 1) { if (tid < st) red[tid] += red[tid + st]; __syncthreads(); }
    float mu = red[0] * (1.f / C);
    __syncthreads();
    float q = 0.f;
#pragma unroll
    for (int i = 0; i < 3; i++) { float d = v[i] - mu; q += d * d; }
    red[tid] = q; __syncthreads();
    for (int st = 128; st > 0; st >>= 1) { if (tid < st) red[tid] += red[tid + st]; __syncthreads(); }
    float var = red[0] * (1.f / C);
    float rstd = rsqrtf(var + 1e-5f);
#pragma unroll
    for (int i = 0; i < 3; i++) {
        int c = tid + i * 256;
        out[(long)row * C + c] = (v[i] - mu) * rstd * g[c];
    }
}

// ---------------- bf16 split helpers ----------------
__device__ __forceinline__ void mma_bf16(float* c, const uint32_t* a, const uint32_t* b) {
    asm volatile(
        "mma.sync.aligned.m16n8k16.row.col.f32.bf16.bf16.f32 "
        "{%0,%1,%2,%3}, {%4,%5,%6,%7}, {%8,%9}, {%0,%1,%2,%3};\n"
        : "+f"(c[0]), "+f"(c[1]), "+f"(c[2]), "+f"(c[3])
        : "r"(a[0]), "r"(a[1]), "r"(a[2]), "r"(a[3]),
          "r"(b[0]), "r"(b[1]));
}

// Fast split of two adjacent k floats into packed bf16x2 hi and lo words.
// hi = truncated high 16 bits (1 PRMT for the pair); lo = x - hi (exact), packed by cvt.
// x0 -> low half of word, x1 -> high half.
__device__ __forceinline__ void bsplit2_fast(float x0, float x1, uint32_t& wh, uint32_t& wl) {
    uint32_t u0 = __float_as_uint(x0), u1 = __float_as_uint(x1);
    uint32_t h;
    asm("prmt.b32 %0, %1, %2, 0x7632;" : "=r"(h) : "r"(u0), "r"(u1));
    float l0 = x0 - __uint_as_float(u0 & 0xffff0000u);
    float l1 = x1 - __uint_as_float(u1 & 0xffff0000u);
    uint32_t l;
    asm("cvt.rn.bf16x2.f32 %0, %1, %2;" : "=r"(l) : "f"(l1), "f"(l0));
    wh = h; wl = l;
}

// ---------------- split-bf16 tensor-core GEMM ----------------
// 128x128 tiles, register prefetch + DOUBLE-BUFFERED smem stages (1 sync/stage).
// out[m, n] = sum_k A[row(m), k] * B[e][n, k]   (B row-major [N, K])
// A = Ah + Al, B = Bh + Bl (bf16 each); C = Al*Bh + Ah*Bl + Ah*Bh.
constexpr int BM = 128, BN = 128, BKF = 32;   // k floats per stage (16 words)
constexpr int SSTR = 20;                       // smem row stride (words)
constexpr int ABUF = 128 * SSTR;               // one operand array (words)
constexpr int BUFSZ = 4 * ABUF;                // Ah|Al|Bh|Bl (words)
constexpr int SGEMM_SMEM = 2 * BUFSZ * 4;      // bytes (81920)

__device__ __forceinline__ void cvt_store_stage(
    uint32_t* __restrict__ buf, int lrow0, int lw,
    const float4 (&pa)[2][2], const float4 (&pb)[2][2])
{
#pragma unroll
    for (int i = 0; i < 2; i++) {
        int row = lrow0 + i * 64;
        uint4 uh, ul;
        bsplit2_fast(pa[i][0].x, pa[i][0].y, uh.x, ul.x);
        bsplit2_fast(pa[i][0].z, pa[i][0].w, uh.y, ul.y);
        bsplit2_fast(pa[i][1].x, pa[i][1].y, uh.z, ul.z);
        bsplit2_fast(pa[i][1].z, pa[i][1].w, uh.w, ul.w);
        *(uint4*)&buf[row * SSTR + lw]        = uh;   // Ah
        *(uint4*)&buf[ABUF + row * SSTR + lw] = ul;   // Al
        bsplit2_fast(pb[i][0].x, pb[i][0].y, uh.x, ul.x);
        bsplit2_fast(pb[i][0].z, pb[i][0].w, uh.y, ul.y);
        bsplit2_fast(pb[i][1].x, pb[i][1].y, uh.z, ul.z);
        bsplit2_fast(pb[i][1].z, pb[i][1].w, uh.w, ul.w);
        *(uint4*)&buf[2 * ABUF + row * SSTR + lw] = uh;   // Bh
        *(uint4*)&buf[3 * ABUF + row * SSTR + lw] = ul;   // Bl
    }
}

__global__ __launch_bounds__(256) void sgemm_kernel(
    const float* __restrict__ Abase, int lda,
    const float* __restrict__ Bbase, long bstride,
    int N, int K,
    float* Out, int ldo,
    const float* resid,
    const int* __restrict__ offsets,
    const int* __restrict__ gather,
    int M, int dogelu)
{
    extern __shared__ uint32_t sgw[];
    int e = blockIdx.z;
    int rowbase = 0, cnt = M;
    if (offsets) { rowbase = offsets[e]; cnt = offsets[e + 1] - rowbase; }
    int m0 = blockIdx.y * BM;
    if (m0 >= cnt) return;
    int n0 = blockIdx.x * BN;
    const float* B = Bbase + (long)e * bstride;

    int tid  = threadIdx.x;
    int lane = tid & 31, warp = tid >> 5;
    int gid  = lane >> 2, tig = lane & 3;
    int wm   = (warp & 1) * 64;      // warp tile: 64 (m) x 32 (n)
    int wn   = (warp >> 1) * 32;

    // loader: 128 rows x 32 k-floats per operand; 4 threads per row (8 floats each), 2 passes
    int lrow0 = tid >> 2;           // 0..63
    int lw    = (tid & 3) * 4;      // word offset 0/4/8/12
    int lf    = lw * 2;             // float offset 0/8/16/24
    long aof[2]; bool av[2]; long bof[2];
#pragma unroll
    for (int i = 0; i < 2; i++) {
        int row = lrow0 + i * 64;
        int gm  = m0 + row;
        av[i] = gm < cnt;
        int arow = 0;
        if (av[i]) arow = gather ? gather[rowbase + gm] : (rowbase + gm);
        aof[i] = (long)arow * lda + lf;
        bof[i] = (long)(n0 + row) * K + lf;
    }

    float c[4][4][4];
#pragma unroll
    for (int i = 0; i < 4; i++)
#pragma unroll
        for (int j = 0; j < 4; j++)
#pragma unroll
            for (int r = 0; r < 4; r++) c[i][j][r] = 0.f;

    // prefetch stage 0 into registers, store into buffer 0
    float4 pa[2][2], pb[2][2];
#pragma unroll
    for (int i = 0; i < 2; i++) {
        if (av[i]) {
            pa[i][0] = *(const float4*)&Abase[aof[i]];
            pa[i][1] = *(const float4*)&Abase[aof[i] + 4];
        } else {
            pa[i][0] = pa[i][1] = make_float4(0.f, 0.f, 0.f, 0.f);
        }
        pb[i][0] = *(const float4*)&B[bof[i]];
        pb[i][1] = *(const float4*)&B[bof[i] + 4];
    }
    cvt_store_stage(sgw, lrow0, lw, pa, pb);
    __syncthreads();

    int nst = K / BKF;
    for (int s = 0; s < nst; s++) {
        uint32_t* cur = sgw + (s & 1) * BUFSZ;
        uint32_t* nxt = sgw + ((s + 1) & 1) * BUFSZ;

        // prefetch next stage into registers (latency hidden by MMAs below)
        int kn = (s + 1) * BKF;
        if (s + 1 < nst) {
#pragma unroll
            for (int i = 0; i < 2; i++) {
                if (av[i]) {
                    pa[i][0] = *(const float4*)&Abase[aof[i] + kn];
                    pa[i][1] = *(const float4*)&Abase[aof[i] + kn + 4];
                }
                pb[i][0] = *(const float4*)&B[bof[i] + kn];
                pb[i][1] = *(const float4*)&B[bof[i] + kn + 4];
            }
        }

        // two k16 MMA steps (word offsets 0 and 8) on current buffer
#pragma unroll
        for (int kk = 0; kk < 16; kk += 8) {
            uint32_t ah[4][4], al[4][4], bh[4][2], bl[4][2];
#pragma unroll
            for (int i = 0; i < 4; i++) {
                int r0 = (wm + i * 16 + gid) * SSTR;
                ah[i][0] = cur[r0 + kk + tig];
                ah[i][1] = cur[r0 + 8 * SSTR + kk + tig];
                ah[i][2] = cur[r0 + kk + tig + 4];
                ah[i][3] = cur[r0 + 8 * SSTR + kk + tig + 4];
                al[i][0] = cur[ABUF + r0 + kk + tig];
                al[i][1] = cur[ABUF + r0 + 8 * SSTR + kk + tig];
                al[i][2] = cur[ABUF + r0 + kk + tig + 4];
                al[i][3] = cur[ABUF + r0 + 8 * SSTR + kk + tig + 4];
            }
#pragma unroll
            for (int j = 0; j < 4; j++) {
                int rn = (wn + j * 8 + gid) * SSTR;
                bh[j][0] = cur[2 * ABUF + rn + kk + tig];
                bh[j][1] = cur[2 * ABUF + rn + kk + tig + 4];
                bl[j][0] = cur[3 * ABUF + rn + kk + tig];
                bl[j][1] = cur[3 * ABUF + rn + kk + tig + 4];
            }
#pragma unroll
            for (int i = 0; i < 4; i++)
#pragma unroll
                for (int j = 0; j < 4; j++) {
                    mma_bf16(c[i][j], al[i], bh[j]);   // small terms first
                    mma_bf16(c[i][j], ah[i], bl[j]);
                    mma_bf16(c[i][j], ah[i], bh[j]);
                }
        }

        // convert + store next stage into the other buffer
        if (s + 1 < nst)
            cvt_store_stage(nxt, lrow0, lw, pa, pb);
        __syncthreads();
    }

    // epilogue: c[i][j] = {(gid, 2tig), (gid, 2tig+1), (gid+8, 2tig), (gid+8, 2tig+1)}
#pragma unroll
    for (int i = 0; i < 4; i++) {
#pragma unroll
        for (int half = 0; half < 2; half++) {
            int gm = m0 + wm + i * 16 + gid + half * 8;
            if (gm >= cnt) continue;
            long orow = rowbase + gm;
#pragma unroll
            for (int j = 0; j < 4; j++) {
                int col = n0 + wn + j * 8 + 2 * tig;
                float v0 = c[i][j][half * 2];
                float v1 = c[i][j][half * 2 + 1];
                if (dogelu) {
                    v0 = 0.5f * v0 * (1.f + erff(v0 * 0.70710678118654752f));
                    v1 = 0.5f * v1 * (1.f + erff(v1 * 0.70710678118654752f));
                }
                if (resid) {
                    float2 rv = *(const float2*)&resid[orow * ldo + col];
                    v0 += rv.x; v1 += rv.y;
                }
                float2 r2 = make_float2(v0, v1);
                *(float2*)&Out[orow * ldo + col] = r2;
            }
        }
    }
}

// ---------------- tensor-core flash attention (split-bf16) ----------------
// block = (64-query tile, head), 4 warps; warp w owns query rows 16w..16w+15.
// All smem packed bf16x2 hi/lo; S and P·V via m16n8k16 with 2-term compensation.
constexpr int ASTR = 36;   // word stride: uint4-aligned, conflict-free frag loads

__global__ __launch_bounds__(128) void attn_kernel(const float* __restrict__ qkv,
                                                   float* __restrict__ out)
{
    extern __shared__ uint32_t smw[];
    uint32_t* Qh = smw;                 // [64][ASTR]
    uint32_t* Ql = Qh + 64 * ASTR;
    uint32_t* Kh = Ql + 64 * ASTR;
    uint32_t* Kl = Kh + 64 * ASTR;
    uint32_t* Vh = Kl + 64 * ASTR;      // transposed [d][j-pair word]
    uint32_t* Vl = Vh + 64 * ASTR;

    int h    = blockIdx.y;
    int qt   = (int)gridDim.x - 1 - (int)blockIdx.x;   // big tiles first
    int tid  = threadIdx.x;
    int warp = tid >> 5, lane = tid & 31;
    int gid  = lane >> 2, tig = lane & 3;

    uint32_t* Ph = Vl + 64 * ASTR + warp * (16 * ASTR);              // [16][ASTR]
    uint32_t* Pl = Vl + 64 * ASTR + 4 * (16 * ASTR) + warp * (16 * ASTR);

    // load Q tile (64 x 64) -> packed hi/lo
    {
        int row  = tid >> 1;
        int half = tid & 1;
        const float* qr = qkv + (long)(qt * 64 + row) * (3 * C) + h * HD + half * 32;
#pragma unroll
        for (int d = 0; d < 32; d += 8) {
            float4 a = *(const float4*)&qr[d];
            float4 b = *(const float4*)&qr[d + 4];
            uint4 uh, ul;
            bsplit2_fast(a.x, a.y, uh.x, ul.x);
            bsplit2_fast(a.z, a.w, uh.y, ul.y);
            bsplit2_fast(b.x, b.y, uh.z, ul.z);
            bsplit2_fast(b.z, b.w, uh.w, ul.w);
            int w = half * 16 + d / 2;
            *(uint4*)&Qh[row * ASTR + w] = uh;
            *(uint4*)&Ql[row * ASTR + w] = ul;
        }
    }

    float o[8][4];
#pragma unroll
    for (int df = 0; df < 8; df++)
#pragma unroll
        for (int r = 0; r < 4; r++) o[df][r] = 0.f;
    float m0 = -1e30f, m1 = -1e30f, l0 = 0.f, l1 = 0.f;

    int rowg0 = qt * 64 + warp * 16 + gid;
    int rowg1 = rowg0 + 8;

    int ntiles = qt + 1;
    for (int t = 0; t < ntiles; t++) {
        int j0 = t * 64;
        __syncthreads();   // prev tile's MMA reads done (and Q ready at t=0)
        {
            // K: 2 threads per row, 32 dims each
            int row  = tid >> 1;
            int half = tid & 1;
            const float* kr = qkv + (long)(j0 + row) * (3 * C) + C + h * HD + half * 32;
#pragma unroll
            for (int d = 0; d < 32; d += 8) {
                float4 a = *(const float4*)&kr[d];
                float4 b = *(const float4*)&kr[d + 4];
                uint4 uh, ul;
                bsplit2_fast(a.x, a.y, uh.x, ul.x);
                bsplit2_fast(a.z, a.w, uh.y, ul.y);
                bsplit2_fast(b.x, b.y, uh.z, ul.z);
                bsplit2_fast(b.z, b.w, uh.w, ul.w);
                int w = half * 16 + d / 2;
                *(uint4*)&Kh[row * ASTR + w] = uh;
                *(uint4*)&Kl[row * ASTR + w] = ul;
            }
            // V transposed: thread owns j-pair jp, dim group a4 (+16i)
            int jp = tid >> 2;            // 0..31 -> keys 2jp, 2jp+1
            int a4 = (tid & 3) * 4;
            const float* v0 = qkv + (long)(j0 + 2 * jp) * (3 * C) + 2 * C + h * HD;
            const float* v1 = v0 + 3 * C;
#pragma unroll
            for (int i = 0; i < 4; i++) {
                int db = a4 + i * 16;
                float4 x = *(const float4*)&v0[db];
                float4 y = *(const float4*)&v1[db];
                uint32_t wh, wl;
                bsplit2_fast(x.x, y.x, wh, wl); Vh[(db + 0) * ASTR + jp] = wh; Vl[(db + 0) * ASTR + jp] = wl;
                bsplit2_fast(x.y, y.y, wh, wl); Vh[(db + 1) * ASTR + jp] = wh; Vl[(db + 1) * ASTR + jp] = wl;
                bsplit2_fast(x.z, y.z, wh, wl); Vh[(db + 2) * ASTR + jp] = wh; Vl[(db + 2) * ASTR + jp] = wl;
                bsplit2_fast(x.w, y.w, wh, wl); Vh[(db + 3) * ASTR + jp] = wh; Vl[(db + 3) * ASTR + jp] = wl;
            }
        }
        __syncthreads();

        // ---- S = Q K^T (split-bf16) ----
        float S[8][4];
#pragma unroll
        for (int nf = 0; nf < 8; nf++)
#pragma unroll
            for (int r = 0; r < 4; r++) S[nf][r] = 0.f;

        int r0 = warp * 16 + gid;
#pragma unroll
        for (int ch = 0; ch < 4; ch++) {
            int kk = ch * 8;
            uint32_t qh[4], ql[4];
            qh[0] = Qh[r0 * ASTR + kk + tig];
            qh[1] = Qh[(r0 + 8) * ASTR + kk + tig];
            qh[2] = Qh[r0 * ASTR + kk + tig + 4];
            qh[3] = Qh[(r0 + 8) * ASTR + kk + tig + 4];
            ql[0] = Ql[r0 * ASTR + kk + tig];
            ql[1] = Ql[(r0 + 8) * ASTR + kk + tig];
            ql[2] = Ql[r0 * ASTR + kk + tig + 4];
            ql[3] = Ql[(r0 + 8) * ASTR + kk + tig + 4];
#pragma unroll
            for (int nf = 0; nf < 8; nf++) {
                int rn = nf * 8 + gid;
                uint32_t bh[2], bl[2];
                bh[0] = Kh[rn * ASTR + kk + tig];
                bh[1] = Kh[rn * ASTR + kk + tig + 4];
                bl[0] = Kl[rn * ASTR + kk + tig];
                bl[1] = Kl[rn * ASTR + kk + tig + 4];
                mma_bf16(S[nf], ql, bh);
                mma_bf16(S[nf], qh, bl);
                mma_bf16(S[nf], qh, bh);
            }
        }

        // ---- scale + causal mask + online softmax ----
        bool diag = (t == qt);
        float max0 = -1e30f, max1 = -1e30f;
#pragma unroll
        for (int nf = 0; nf < 8; nf++) {
            int colb = j0 + nf * 8 + 2 * tig;
            float s0 = S[nf][0] * 0.125f;
            float s1 = S[nf][1] * 0.125f;
            float s2 = S[nf][2] * 0.125f;
            float s3 = S[nf][3] * 0.125f;
            if (diag) {
                if (colb     > rowg0) s0 = -1e30f;
                if (colb + 1 > rowg0) s1 = -1e30f;
                if (colb     > rowg1) s2 = -1e30f;
                if (colb + 1 > rowg1) s3 = -1e30f;
            }
            S[nf][0] = s0; S[nf][1] = s1; S[nf][2] = s2; S[nf][3] = s3;
            max0 = fmaxf(max0, fmaxf(s0, s1));
            max1 = fmaxf(max1, fmaxf(s2, s3));
        }
        max0 = fmaxf(max0, __shfl_xor_sync(0xffffffffu, max0, 1));
        max0 = fmaxf(max0, __shfl_xor_sync(0xffffffffu, max0, 2));
        max1 = fmaxf(max1, __shfl_xor_sync(0xffffffffu, max1, 1));
        max1 = fmaxf(max1, __shfl_xor_sync(0xffffffffu, max1, 2));

        float mn0 = fmaxf(m0, max0), mn1 = fmaxf(m1, max1);
        float corr0 = __expf(m0 - mn0), corr1 = __expf(m1 - mn1);
        float ls0 = 0.f, ls1 = 0.f;
#pragma unroll
        for (int nf = 0; nf < 8; nf++) {
            int w = nf * 4 + tig;
            float p0 = __expf(S[nf][0] - mn0);
            float p1 = __expf(S[nf][1] - mn0);
            float p2 = __expf(S[nf][2] - mn1);
            float p3 = __expf(S[nf][3] - mn1);
            ls0 += p0 + p1; ls1 += p2 + p3;
            uint32_t wh, wl;
            bsplit2_fast(p0, p1, wh, wl);
            Ph[gid * ASTR + w] = wh; Pl[gid * ASTR + w] = wl;
            bsplit2_fast(p2, p3, wh, wl);
            Ph[(gid + 8) * ASTR + w] = wh; Pl[(gid + 8) * ASTR + w] = wl;
        }
        ls0 += __shfl_xor_sync(0xffffffffu, ls0, 1);
        ls0 += __shfl_xor_sync(0xffffffffu, ls0, 2);
        ls1 += __shfl_xor_sync(0xffffffffu, ls1, 1);
        ls1 += __shfl_xor_sync(0xffffffffu, ls1, 2);
        l0 = l0 * corr0 + ls0;
        l1 = l1 * corr1 + ls1;
        m0 = mn0; m1 = mn1;

#pragma unroll
        for (int df = 0; df < 8; df++) {
            o[df][0] *= corr0; o[df][1] *= corr0;
            o[df][2] *= corr1; o[df][3] *= corr1;
        }
        __syncwarp();

        // ---- o += P V (split-bf16); A = P (warp-private), B = V^T ----
#pragma unroll
        for (int ch = 0; ch < 4; ch++) {
            int kk = ch * 8;
            uint32_t ph[4], pl[4];
            ph[0] = Ph[gid * ASTR + kk + tig];
            ph[1] = Ph[(gid + 8) * ASTR + kk + tig];
            ph[2] = Ph[gid * ASTR + kk + tig + 4];
            ph[3] = Ph[(gid + 8) * ASTR + kk + tig + 4];
            pl[0] = Pl[gid * ASTR + kk + tig];
            pl[1] = Pl[(gid + 8) * ASTR + kk + tig];
            pl[2] = Pl[gid * ASTR + kk + tig + 4];
            pl[3] = Pl[(gid + 8) * ASTR + kk + tig + 4];
#pragma unroll
            for (int df = 0; df < 8; df++) {
                int dn = df * 8 + gid;
                uint32_t vh[2], vl[2];
                vh[0] = Vh[dn * ASTR + kk + tig];
                vh[1] = Vh[dn * ASTR + kk + tig + 4];
                vl[0] = Vl[dn * ASTR + kk + tig];
                vl[1] = Vl[dn * ASTR + kk + tig + 4];
                mma_bf16(o[df], pl, vh);
                mma_bf16(o[df], ph, vl);
                mma_bf16(o[df], ph, vh);
            }
        }
    }

    float inv0 = 1.f / l0, inv1 = 1.f / l1;
    float* op0 = out + (long)rowg0 * C + h * HD;
    float* op1 = out + (long)rowg1 * C + h * HD;
#pragma unroll
    for (int df = 0; df < 8; df++) {
        int colb = df * 8 + 2 * tig;
        *(float2*)&op0[colb] = make_float2(o[df][0] * inv0, o[df][1] * inv0);
        *(float2*)&op1[colb] = make_float2(o[df][2] * inv1, o[df][3] * inv1);
    }
}

// ---------------- MoE gate: logits + top-2 + softmax ----------------
__global__ __launch_bounds__(256) void gate_kernel(const float* __restrict__ xn,
                                                   const float* __restrict__ gw,
                                                   int* __restrict__ tope,
                                                   float* __restrict__ tops)
{
    int t = blockIdx.x;
    int w = threadIdx.x >> 5, lane = threadIdx.x & 31;
    const float* x  = xn + (long)t * C;
    const float* gr = gw + (long)w * C;
    float s = 0.f;
    for (int c = lane * 4; c < C; c += 128) {
        float4 a = *(const float4*)&x[c];
        float4 b = *(const float4*)&gr[c];
        s += a.x * b.x + a.y * b.y + a.z * b.z + a.w * b.w;
    }
#pragma unroll
    for (int off = 16; off; off >>= 1) s += __shfl_xor_sync(0xffffffffu, s, off);
    __shared__ float lg[NE];
    if (lane == 0) lg[w] = s;
    __syncthreads();
    if (threadIdx.x == 0) {
        int i0 = 0;
#pragma unroll
        for (int e2 = 1; e2 < NE; e2++) if (lg[e2] > lg[i0]) i0 = e2;
        int i1 = (i0 == 0) ? 1 : 0;
#pragma unroll
        for (int e2 = 0; e2 < NE; e2++) if (e2 != i0 && lg[e2] > lg[i1]) i1 = e2;
        float ex = __expf(lg[i1] - lg[i0]);
        float s0 = 1.f / (1.f + ex);
        tope[t * 2]     = i0; tope[t * 2 + 1] = i1;
        tops[t * 2]     = s0; tops[t * 2 + 1] = 1.f - s0;
    }
}

// ---------------- routing compaction (single block; int atomics only) --------
__global__ void scatter_kernel(const int* __restrict__ tope)
{
    __shared__ int cnt[NE];
    __shared__ int off[NE + 1];
    int tid = threadIdx.x;
    if (tid < NE) cnt[tid] = 0;
    __syncthreads();
    for (int p = tid; p < P; p += 256) atomicAdd(&cnt[tope[p]], 1);
    __syncthreads();
    if (tid == 0) {
        off[0] = 0;
        for (int e = 0; e < NE; e++) off[e + 1] = off[e] + cnt[e];
        for (int e = 0; e <= NE; e++) g_off[e] = off[e];
    }
    __syncthreads();
    if (tid < NE) cnt[tid] = off[tid];
    __syncthreads();
    for (int p = tid; p < P; p += 256) {
        int e2  = tope[p];
        int pos = atomicAdd(&cnt[e2], 1);
        g_pairtok[pos] = p >> 1;   // token index
        g_tokpos[p] = pos;
    }
}

// ---------------- MoE combine: x += s0*y[p0] + s1*y[p1] ----------------
__global__ __launch_bounds__(192) void combine_kernel(
    const float* __restrict__ ybuf, const float* __restrict__ tops,
    const int* __restrict__ tokpos, float* x)
{
    int t = blockIdx.x;
    int c = threadIdx.x * 4;
    int p0 = tokpos[t * 2], p1 = tokpos[t * 2 + 1];
    float w0 = tops[t * 2], w1 = tops[t * 2 + 1];
    float4 a  = *(const float4*)&ybuf[(long)p0 * C + c];
    float4 b  = *(const float4*)&ybuf[(long)p1 * C + c];
    float4 xv = *(float4*)&x[(long)t * C + c];
    xv.x += w0 * a.x + w1 * b.x;
    xv.y += w0 * a.y + w1 * b.y;
    xv.z += w0 * a.z + w1 * b.z;
    xv.w += w0 * a.w + w1 * b.w;
    *(float4*)&x[(long)t * C + c] = xv;
}

// ---------------- lm head: logits[v] = dot(x_last, wte[v]) ----------------
__global__ __launch_bounds__(256) void lmhead_kernel(
    const float* __restrict__ xn, const float* __restrict__ wte,
    float* __restrict__ out)
{
    __shared__ float4 xs[C / 4];
    const float* x = xn + (long)(T - 1) * C;
    for (int ii = threadIdx.x; ii < C / 4; ii += 256) xs[ii] = *(const float4*)&x[ii * 4];
    __syncthreads();
    int w = threadIdx.x >> 5, lane = threadIdx.x & 31;
    int v = blockIdx.x * 8 + w;
    if (v >= V) return;
    const float* wr = wte + (long)v * C;
    float s = 0.f;
    for (int c = lane; c < C / 4; c += 32) {
        float4 a = *(const float4*)&wr[c * 4];
        float4 b = xs[c];
        s += a.x * b.x + a.y * b.y + a.z * b.z + a.w * b.w;
    }
#pragma unroll
    for (int off = 16; off; off >>= 1) s += __shfl_xor_sync(0xffffffffu, s, off);
    if (lane == 0) out[v] = s;
}

// ---------------- launch ----------------
extern "C" void kernel_launch(void* const* d_in, const int* in_sizes, int n_in,
                              void* d_out, int out_size)
{
    const int*   idx   = (const int*)d_in[0];
    const float* wte   = (const float*)d_in[1];
    const float* wpe   = (const float*)d_in[2];
    const float* ln1g  = (const float*)d_in[3];
    const float* qkvw  = (const float*)d_in[4];
    const float* projw = (const float*)d_in[5];
    const float* ln2g  = (const float*)d_in[6];
    const float* gatew = (const float*)d_in[7];
    const float* w1    = (const float*)d_in[8];
    const float* w2    = (const float*)d_in[9];
    const float* lnfg  = (const float*)d_in[10];
    float* out = (float*)d_out;

    float *p_x, *p_xn, *p_qkv, *p_attno, *p_h, *p_y, *p_tops;
    int *p_tope, *p_tokpos, *p_pairtok, *p_off;
    cudaGetSymbolAddress((void**)&p_x,       g_x);
    cudaGetSymbolAddress((void**)&p_xn,      g_xn);
    cudaGetSymbolAddress((void**)&p_qkv,     g_qkv);
    cudaGetSymbolAddress((void**)&p_attno,   g_attno);
    cudaGetSymbolAddress((void**)&p_h,       g_h);
    cudaGetSymbolAddress((void**)&p_y,       g_y);
    cudaGetSymbolAddress((void**)&p_tops,    g_tops);
    cudaGetSymbolAddress((void**)&p_tope,    g_tope);
    cudaGetSymbolAddress((void**)&p_tokpos,  g_tokpos);
    cudaGetSymbolAddress((void**)&p_pairtok, g_pairtok);
    cudaGetSymbolAddress((void**)&p_off,     g_off);

    cudaFuncSetAttribute(attn_kernel,
                         cudaFuncAttributeMaxDynamicSharedMemorySize, ATTN_SMEM);
    cudaFuncSetAttribute(sgemm_kernel,
                         cudaFuncAttributeMaxDynamicSharedMemorySize, SGEMM_SMEM);

    embed_kernel<<<T, C / 4>>>(idx, wte, wpe, p_x);

    for (int l = 0; l < 2; l++) {
        layernorm_kernel<<<T, 256>>>(p_x, p_xn, ln1g + (long)l * C, 0);
        sgemm_kernel<<<dim3(3 * C / BN, T / BM, 1), 256, SGEMM_SMEM>>>(
            p_xn, C, qkvw + (long)l * 3 * C * C, 0, 3 * C, C,
            p_qkv, 3 * C, nullptr, nullptr, nullptr, T, 0);
        attn_kernel<<<dim3(T / 64, NH), 128, ATTN_SMEM>>>(p_qkv, p_attno);
        sgemm_kernel<<<dim3(C / BN, T / BM, 1), 256, SGEMM_SMEM>>>(
            p_attno, C, projw + (long)l * C * C, 0, C, C,
            p_x, C, p_x, nullptr, nullptr, T, 0);

        layernorm_kernel<<<T, 256>>>(p_x, p_xn, ln2g + (long)l * C, 0);
        gate_kernel<<<T, 256>>>(p_xn, gatew + (long)l * NE * C, p_tope, p_tops);
        scatter_kernel<<<1, 256>>>(p_tope);
        sgemm_kernel<<<dim3(C4 / BN, P / BM, NE), 256, SGEMM_SMEM>>>(
            p_xn, C, w1 + (long)l * NE * C4 * C, (long)C4 * C, C4, C,
            p_h, C4, nullptr, p_off, p_pairtok, 0, 1);
        sgemm_kernel<<<dim3(C / BN, P / BM, NE), 256, SGEMM_SMEM>>>(
            p_h, C4, w2 + (long)l * NE * C * C4, (long)C * C4, C, C4,
            p_y, C, nullptr, p_off, nullptr, 0, 0);
        combine_kernel<<<T, C / 4>>>(p_y, p_tops, p_tokpos, p_x);
    }

    layernorm_kernel<<<1, 256>>>(p_x, p_xn, lnfg, T - 1);
    lmhead_kernel<<<(V + 7) / 8, 256>>>(p_xn, wte, out);
}

// round 17
// speedup vs baseline: 3.3804x; 1.0298x over previous
#include <cuda_runtime.h>
#include <cuda_bf16.h>
#include <cstdint>

namespace {
constexpr int T  = 1024;
constexpr int C  = 768;
constexpr int NH = 12;
constexpr int HD = 64;
constexpr int NE = 8;
constexpr int V  = 50257;
constexpr int C4 = 3072;
constexpr int P  = 2048;   // token-expert pairs (T * topK)
constexpr int KSPL = 4;    // split-K factor for skinny GEMMs
// bf16 attn smem: 6 tile buffers [64][36] words + 8 P buffers [16][36] words
constexpr int ATTN_SMEM = (6 * 64 * 36 + 8 * 16 * 36) * 4;   // 73728 B
}

// ---------------- scratch (device globals; no allocation) ----------------
__device__ float g_x[T * C];
__device__ float g_xn[T * C];
__device__ float g_qkv[T * 3 * C];
__device__ float g_attno[T * C];
__device__ float g_h[P * C4];        // 25 MB
__device__ float g_y[P * C];
__device__ float g_part[KSPL * P * C];   // split-K partials (25 MB)
__device__ int   g_tope[P];
__device__ float g_tops[P];
__device__ int   g_tokpos[P];
__device__ int   g_pairtok[P];
__device__ int   g_off[NE + 1];

// ---------------- embed: x = wte[idx] + wpe ----------------
__global__ void embed_kernel(const int* __restrict__ idx,
                             const float* __restrict__ wte,
                             const float* __restrict__ wpe,
                             float* __restrict__ x)
{
    int t = blockIdx.x;
    int c = threadIdx.x * 4;
    int tok = idx[t];
    float4 a = *(const float4*)&wte[(long)tok * C + c];
    float4 b = *(const float4*)&wpe[(long)t * C + c];
    float4 r = make_float4(a.x + b.x, a.y + b.y, a.z + b.z, a.w + b.w);
    *(float4*)&x[(long)t * C + c] = r;
}

// ---------------- layernorm (gamma only, eps 1e-5) ----------------
__global__ __launch_bounds__(256) void layernorm_kernel(
    const float* __restrict__ in, float* __restrict__ out,
    const float* __restrict__ g, int rowbase)
{
    int row = rowbase + blockIdx.x;
    const float* x = in + (long)row * C;
    int tid = threadIdx.x;
    __shared__ float red[256];
    float v[3];
    float s = 0.f;
#pragma unroll
    for (int i = 0; i < 3; i++) { v[i] = x[tid + i * 256]; s += v[i]; }
    red[tid] = s; __syncthreads();
    for (int st = 128; st > 0; st >>= 1) { if (tid < st) red[tid] += red[tid + st]; __syncthreads(); }
    float mu = red[0] * (1.f / C);
    __syncthreads();
    float q = 0.f;
#pragma unroll
    for (int i = 0; i < 3; i++) { float d = v[i] - mu; q += d * d; }
    red[tid] = q; __syncthreads();
    for (int st = 128; st > 0; st >>= 1) { if (tid < st) red[tid] += red[tid + st]; __syncthreads(); }
    float var = red[0] * (1.f / C);
    float rstd = rsqrtf(var + 1e-5f);
#pragma unroll
    for (int i = 0; i < 3; i++) {
        int c = tid + i * 256;
        out[(long)row * C + c] = (v[i] - mu) * rstd * g[c];
    }
}

// ---------------- bf16 split helpers ----------------
__device__ __forceinline__ void mma_bf16(float* c, const uint32_t* a, const uint32_t* b) {
    asm volatile(
        "mma.sync.aligned.m16n8k16.row.col.f32.bf16.bf16.f32 "
        "{%0,%1,%2,%3}, {%4,%5,%6,%7}, {%8,%9}, {%0,%1,%2,%3};\n"
        : "+f"(c[0]), "+f"(c[1]), "+f"(c[2]), "+f"(c[3])
        : "r"(a[0]), "r"(a[1]), "r"(a[2]), "r"(a[3]),
          "r"(b[0]), "r"(b[1]));
}

// Fast split of two adjacent k floats into packed bf16x2 hi and lo words.
__device__ __forceinline__ void bsplit2_fast(float x0, float x1, uint32_t& wh, uint32_t& wl) {
    uint32_t u0 = __float_as_uint(x0), u1 = __float_as_uint(x1);
    uint32_t h;
    asm("prmt.b32 %0, %1, %2, 0x7632;" : "=r"(h) : "r"(u0), "r"(u1));
    float l0 = x0 - __uint_as_float(u0 & 0xffff0000u);
    float l1 = x1 - __uint_as_float(u1 & 0xffff0000u);
    uint32_t l;
    asm("cvt.rn.bf16x2.f32 %0, %1, %2;" : "=r"(l) : "f"(l1), "f"(l0));
    wh = h; wl = l;
}

// ---------------- split-bf16 tensor-core GEMM ----------------
// 128x128 tiles, register prefetch + double-buffered smem stages.
// out[m, n] = sum_k A[row(m), k] * B[e][n, k]   (B row-major [N, K])
// ksplit > 1: blockIdx.z = e*ksplit + kc; chunk kc covers K/ksplit k's and
// writes raw partials to partial + kc*pstride (no gelu/resid).
constexpr int BM = 128, BN = 128, BKF = 32;   // k floats per stage (16 words)
constexpr int SSTR = 20;                       // smem row stride (words)
constexpr int ABUF = 128 * SSTR;               // one operand array (words)
constexpr int BUFSZ = 4 * ABUF;                // Ah|Al|Bh|Bl (words)
constexpr int SGEMM_SMEM = 2 * BUFSZ * 4;      // bytes (81920)

__device__ __forceinline__ void cvt_store_stage(
    uint32_t* __restrict__ buf, int lrow0, int lw,
    const float4 (&pa)[2][2], const float4 (&pb)[2][2])
{
#pragma unroll
    for (int i = 0; i < 2; i++) {
        int row = lrow0 + i * 64;
        uint4 uh, ul;
        bsplit2_fast(pa[i][0].x, pa[i][0].y, uh.x, ul.x);
        bsplit2_fast(pa[i][0].z, pa[i][0].w, uh.y, ul.y);
        bsplit2_fast(pa[i][1].x, pa[i][1].y, uh.z, ul.z);
        bsplit2_fast(pa[i][1].z, pa[i][1].w, uh.w, ul.w);
        *(uint4*)&buf[row * SSTR + lw]        = uh;   // Ah
        *(uint4*)&buf[ABUF + row * SSTR + lw] = ul;   // Al
        bsplit2_fast(pb[i][0].x, pb[i][0].y, uh.x, ul.x);
        bsplit2_fast(pb[i][0].z, pb[i][0].w, uh.y, ul.y);
        bsplit2_fast(pb[i][1].x, pb[i][1].y, uh.z, ul.z);
        bsplit2_fast(pb[i][1].z, pb[i][1].w, uh.w, ul.w);
        *(uint4*)&buf[2 * ABUF + row * SSTR + lw] = uh;   // Bh
        *(uint4*)&buf[3 * ABUF + row * SSTR + lw] = ul;   // Bl
    }
}

__global__ __launch_bounds__(256) void sgemm_kernel(
    const float* __restrict__ Abase, int lda,
    const float* __restrict__ Bbase, long bstride,
    int N, int K,
    float* Out, int ldo,
    const float* resid,
    const int* __restrict__ offsets,
    const int* __restrict__ gather,
    int M, int dogelu,
    int ksplit, float* partial, long pstride)
{
    extern __shared__ uint32_t sgw[];
    int zz = blockIdx.z;
    int e  = zz / ksplit;
    int kc = zz - e * ksplit;
    int rowbase = 0, cnt = M;
    if (offsets) { rowbase = offsets[e]; cnt = offsets[e + 1] - rowbase; }
    int m0 = blockIdx.y * BM;
    if (m0 >= cnt) return;
    int n0 = blockIdx.x * BN;
    const float* B = Bbase + (long)e * bstride;

    int kchunk = K / ksplit;
    int kbeg   = kc * kchunk;

    int tid  = threadIdx.x;
    int lane = tid & 31, warp = tid >> 5;
    int gid  = lane >> 2, tig = lane & 3;
    int wm   = (warp & 1) * 64;      // warp tile: 64 (m) x 32 (n)
    int wn   = (warp >> 1) * 32;

    int lrow0 = tid >> 2;           // 0..63
    int lw    = (tid & 3) * 4;      // word offset 0/4/8/12
    int lf    = lw * 2;             // float offset 0/8/16/24
    long aof[2]; bool av[2]; long bof[2];
#pragma unroll
    for (int i = 0; i < 2; i++) {
        int row = lrow0 + i * 64;
        int gm  = m0 + row;
        av[i] = gm < cnt;
        int arow = 0;
        if (av[i]) arow = gather ? gather[rowbase + gm] : (rowbase + gm);
        aof[i] = (long)arow * lda + lf + kbeg;
        bof[i] = (long)(n0 + row) * K + lf + kbeg;
    }

    float c[4][4][4];
#pragma unroll
    for (int i = 0; i < 4; i++)
#pragma unroll
        for (int j = 0; j < 4; j++)
#pragma unroll
            for (int r = 0; r < 4; r++) c[i][j][r] = 0.f;

    // prefetch stage 0, store into buffer 0
    float4 pa[2][2], pb[2][2];
#pragma unroll
    for (int i = 0; i < 2; i++) {
        if (av[i]) {
            pa[i][0] = *(const float4*)&Abase[aof[i]];
            pa[i][1] = *(const float4*)&Abase[aof[i] + 4];
        } else {
            pa[i][0] = pa[i][1] = make_float4(0.f, 0.f, 0.f, 0.f);
        }
        pb[i][0] = *(const float4*)&B[bof[i]];
        pb[i][1] = *(const float4*)&B[bof[i] + 4];
    }
    cvt_store_stage(sgw, lrow0, lw, pa, pb);
    __syncthreads();

    int nst = kchunk / BKF;
    for (int s = 0; s < nst; s++) {
        uint32_t* cur = sgw + (s & 1) * BUFSZ;
        uint32_t* nxt = sgw + ((s + 1) & 1) * BUFSZ;

        int kn = (s + 1) * BKF;
        if (s + 1 < nst) {
#pragma unroll
            for (int i = 0; i < 2; i++) {
                if (av[i]) {
                    pa[i][0] = *(const float4*)&Abase[aof[i] + kn];
                    pa[i][1] = *(const float4*)&Abase[aof[i] + kn + 4];
                }
                pb[i][0] = *(const float4*)&B[bof[i] + kn];
                pb[i][1] = *(const float4*)&B[bof[i] + kn + 4];
            }
        }

#pragma unroll
        for (int kk = 0; kk < 16; kk += 8) {
            uint32_t ah[4][4], al[4][4], bh[4][2], bl[4][2];
#pragma unroll
            for (int i = 0; i < 4; i++) {
                int r0 = (wm + i * 16 + gid) * SSTR;
                ah[i][0] = cur[r0 + kk + tig];
                ah[i][1] = cur[r0 + 8 * SSTR + kk + tig];
                ah[i][2] = cur[r0 + kk + tig + 4];
                ah[i][3] = cur[r0 + 8 * SSTR + kk + tig + 4];
                al[i][0] = cur[ABUF + r0 + kk + tig];
                al[i][1] = cur[ABUF + r0 + 8 * SSTR + kk + tig];
                al[i][2] = cur[ABUF + r0 + kk + tig + 4];
                al[i][3] = cur[ABUF + r0 + 8 * SSTR + kk + tig + 4];
            }
#pragma unroll
            for (int j = 0; j < 4; j++) {
                int rn = (wn + j * 8 + gid) * SSTR;
                bh[j][0] = cur[2 * ABUF + rn + kk + tig];
                bh[j][1] = cur[2 * ABUF + rn + kk + tig + 4];
                bl[j][0] = cur[3 * ABUF + rn + kk + tig];
                bl[j][1] = cur[3 * ABUF + rn + kk + tig + 4];
            }
#pragma unroll
            for (int i = 0; i < 4; i++)
#pragma unroll
                for (int j = 0; j < 4; j++) {
                    mma_bf16(c[i][j], al[i], bh[j]);   // small terms first
                    mma_bf16(c[i][j], ah[i], bl[j]);
                    mma_bf16(c[i][j], ah[i], bh[j]);
                }
        }

        if (s + 1 < nst)
            cvt_store_stage(nxt, lrow0, lw, pa, pb);
        __syncthreads();
    }

    float* outp = (ksplit > 1) ? (partial + kc * pstride) : Out;
    bool raw = (ksplit > 1);

    // epilogue: c[i][j] = {(gid, 2tig), (gid, 2tig+1), (gid+8, 2tig), (gid+8, 2tig+1)}
#pragma unroll
    for (int i = 0; i < 4; i++) {
#pragma unroll
        for (int half = 0; half < 2; half++) {
            int gm = m0 + wm + i * 16 + gid + half * 8;
            if (gm >= cnt) continue;
            long orow = rowbase + gm;
#pragma unroll
            for (int j = 0; j < 4; j++) {
                int col = n0 + wn + j * 8 + 2 * tig;
                float v0 = c[i][j][half * 2];
                float v1 = c[i][j][half * 2 + 1];
                if (!raw) {
                    if (dogelu) {
                        v0 = 0.5f * v0 * (1.f + erff(v0 * 0.70710678118654752f));
                        v1 = 0.5f * v1 * (1.f + erff(v1 * 0.70710678118654752f));
                    }
                    if (resid) {
                        float2 rv = *(const float2*)&resid[orow * ldo + col];
                        v0 += rv.x; v1 += rv.y;
                    }
                }
                float2 r2 = make_float2(v0, v1);
                *(float2*)&outp[orow * ldo + col] = r2;
            }
        }
    }
}

// ---------------- split-K reduce: out = [out +] sum of KSPL slices ----------
__global__ __launch_bounds__(256) void reduce_kernel(
    const float* __restrict__ part, long slice, float* __restrict__ out, int addout)
{
    long i = ((long)blockIdx.x * 256 + threadIdx.x) * 4;
    float4 s0 = *(const float4*)&part[i];
    float4 s1 = *(const float4*)&part[slice + i];
    float4 s2 = *(const float4*)&part[2 * slice + i];
    float4 s3 = *(const float4*)&part[3 * slice + i];
    float4 r;
    r.x = (s0.x + s1.x) + (s2.x + s3.x);
    r.y = (s0.y + s1.y) + (s2.y + s3.y);
    r.z = (s0.z + s1.z) + (s2.z + s3.z);
    r.w = (s0.w + s1.w) + (s2.w + s3.w);
    if (addout) {
        float4 o = *(const float4*)&out[i];
        r.x += o.x; r.y += o.y; r.z += o.z; r.w += o.w;
    }
    *(float4*)&out[i] = r;
}

// ---------------- tensor-core flash attention (split-bf16) ----------------
constexpr int ASTR = 36;   // word stride: uint4-aligned, conflict-free frag loads

__global__ __launch_bounds__(128) void attn_kernel(const float* __restrict__ qkv,
                                                   float* __restrict__ out)
{
    extern __shared__ uint32_t smw[];
    uint32_t* Qh = smw;                 // [64][ASTR]
    uint32_t* Ql = Qh + 64 * ASTR;
    uint32_t* Kh = Ql + 64 * ASTR;
    uint32_t* Kl = Kh + 64 * ASTR;
    uint32_t* Vh = Kl + 64 * ASTR;      // transposed [d][j-pair word]
    uint32_t* Vl = Vh + 64 * ASTR;

    int h    = blockIdx.y;
    int qt   = (int)gridDim.x - 1 - (int)blockIdx.x;   // big tiles first
    int tid  = threadIdx.x;
    int warp = tid >> 5, lane = tid & 31;
    int gid  = lane >> 2, tig = lane & 3;

    uint32_t* Ph = Vl + 64 * ASTR + warp * (16 * ASTR);              // [16][ASTR]
    uint32_t* Pl = Vl + 64 * ASTR + 4 * (16 * ASTR) + warp * (16 * ASTR);

    // load Q tile (64 x 64) -> packed hi/lo
    {
        int row  = tid >> 1;
        int half = tid & 1;
        const float* qr = qkv + (long)(qt * 64 + row) * (3 * C) + h * HD + half * 32;
#pragma unroll
        for (int d = 0; d < 32; d += 8) {
            float4 a = *(const float4*)&qr[d];
            float4 b = *(const float4*)&qr[d + 4];
            uint4 uh, ul;
            bsplit2_fast(a.x, a.y, uh.x, ul.x);
            bsplit2_fast(a.z, a.w, uh.y, ul.y);
            bsplit2_fast(b.x, b.y, uh.z, ul.z);
            bsplit2_fast(b.z, b.w, uh.w, ul.w);
            int w = half * 16 + d / 2;
            *(uint4*)&Qh[row * ASTR + w] = uh;
            *(uint4*)&Ql[row * ASTR + w] = ul;
        }
    }

    float o[8][4];
#pragma unroll
    for (int df = 0; df < 8; df++)
#pragma unroll
        for (int r = 0; r < 4; r++) o[df][r] = 0.f;
    float m0 = -1e30f, m1 = -1e30f, l0 = 0.f, l1 = 0.f;

    int rowg0 = qt * 64 + warp * 16 + gid;
    int rowg1 = rowg0 + 8;

    int ntiles = qt + 1;
    for (int t = 0; t < ntiles; t++) {
        int j0 = t * 64;
        __syncthreads();   // prev tile's MMA reads done (and Q ready at t=0)
        {
            int row  = tid >> 1;
            int half = tid & 1;
            const float* kr = qkv + (long)(j0 + row) * (3 * C) + C + h * HD + half * 32;
#pragma unroll
            for (int d = 0; d < 32; d += 8) {
                float4 a = *(const float4*)&kr[d];
                float4 b = *(const float4*)&kr[d + 4];
                uint4 uh, ul;
                bsplit2_fast(a.x, a.y, uh.x, ul.x);
                bsplit2_fast(a.z, a.w, uh.y, ul.y);
                bsplit2_fast(b.x, b.y, uh.z, ul.z);
                bsplit2_fast(b.z, b.w, uh.w, ul.w);
                int w = half * 16 + d / 2;
                *(uint4*)&Kh[row * ASTR + w] = uh;
                *(uint4*)&Kl[row * ASTR + w] = ul;
            }
            int jp = tid >> 2;            // 0..31 -> keys 2jp, 2jp+1
            int a4 = (tid & 3) * 4;
            const float* v0 = qkv + (long)(j0 + 2 * jp) * (3 * C) + 2 * C + h * HD;
            const float* v1 = v0 + 3 * C;
#pragma unroll
            for (int i = 0; i < 4; i++) {
                int db = a4 + i * 16;
                float4 x = *(const float4*)&v0[db];
                float4 y = *(const float4*)&v1[db];
                uint32_t wh, wl;
                bsplit2_fast(x.x, y.x, wh, wl); Vh[(db + 0) * ASTR + jp] = wh; Vl[(db + 0) * ASTR + jp] = wl;
                bsplit2_fast(x.y, y.y, wh, wl); Vh[(db + 1) * ASTR + jp] = wh; Vl[(db + 1) * ASTR + jp] = wl;
                bsplit2_fast(x.z, y.z, wh, wl); Vh[(db + 2) * ASTR + jp] = wh; Vl[(db + 2) * ASTR + jp] = wl;
                bsplit2_fast(x.w, y.w, wh, wl); Vh[(db + 3) * ASTR + jp] = wh; Vl[(db + 3) * ASTR + jp] = wl;
            }
        }
        __syncthreads();

        // ---- S = Q K^T (split-bf16) ----
        float S[8][4];
#pragma unroll
        for (int nf = 0; nf < 8; nf++)
#pragma unroll
            for (int r = 0; r < 4; r++) S[nf][r] = 0.f;

        int r0 = warp * 16 + gid;
#pragma unroll
        for (int ch = 0; ch < 4; ch++) {
            int kk = ch * 8;
            uint32_t qh[4], ql[4];
            qh[0] = Qh[r0 * ASTR + kk + tig];
            qh[1] = Qh[(r0 + 8) * ASTR + kk + tig];
            qh[2] = Qh[r0 * ASTR + kk + tig + 4];
            qh[3] = Qh[(r0 + 8) * ASTR + kk + tig + 4];
            ql[0] = Ql[r0 * ASTR + kk + tig];
            ql[1] = Ql[(r0 + 8) * ASTR + kk + tig];
            ql[2] = Ql[r0 * ASTR + kk + tig + 4];
            ql[3] = Ql[(r0 + 8) * ASTR + kk + tig + 4];
#pragma unroll
            for (int nf = 0; nf < 8; nf++) {
                int rn = nf * 8 + gid;
                uint32_t bh[2], bl[2];
                bh[0] = Kh[rn * ASTR + kk + tig];
                bh[1] = Kh[rn * ASTR + kk + tig + 4];
                bl[0] = Kl[rn * ASTR + kk + tig];
                bl[1] = Kl[rn * ASTR + kk + tig + 4];
                mma_bf16(S[nf], ql, bh);
                mma_bf16(S[nf], qh, bl);
                mma_bf16(S[nf], qh, bh);
            }
        }

        // ---- scale + causal mask + online softmax ----
        bool diag = (t == qt);
        float max0 = -1e30f, max1 = -1e30f;
#pragma unroll
        for (int nf = 0; nf < 8; nf++) {
            int colb = j0 + nf * 8 + 2 * tig;
            float s0 = S[nf][0] * 0.125f;
            float s1 = S[nf][1] * 0.125f;
            float s2 = S[nf][2] * 0.125f;
            float s3 = S[nf][3] * 0.125f;
            if (diag) {
                if (colb     > rowg0) s0 = -1e30f;
                if (colb + 1 > rowg0) s1 = -1e30f;
                if (colb     > rowg1) s2 = -1e30f;
                if (colb + 1 > rowg1) s3 = -1e30f;
            }
            S[nf][0] = s0; S[nf][1] = s1; S[nf][2] = s2; S[nf][3] = s3;
            max0 = fmaxf(max0, fmaxf(s0, s1));
            max1 = fmaxf(max1, fmaxf(s2, s3));
        }
        max0 = fmaxf(max0, __shfl_xor_sync(0xffffffffu, max0, 1));
        max0 = fmaxf(max0, __shfl_xor_sync(0xffffffffu, max0, 2));
        max1 = fmaxf(max1, __shfl_xor_sync(0xffffffffu, max1, 1));
        max1 = fmaxf(max1, __shfl_xor_sync(0xffffffffu, max1, 2));

        float mn0 = fmaxf(m0, max0), mn1 = fmaxf(m1, max1);
        float corr0 = __expf(m0 - mn0), corr1 = __expf(m1 - mn1);
        float ls0 = 0.f, ls1 = 0.f;
#pragma unroll
        for (int nf = 0; nf < 8; nf++) {
            int w = nf * 4 + tig;
            float p0 = __expf(S[nf][0] - mn0);
            float p1 = __expf(S[nf][1] - mn0);
            float p2 = __expf(S[nf][2] - mn1);
            float p3 = __expf(S[nf][3] - mn1);
            ls0 += p0 + p1; ls1 += p2 + p3;
            uint32_t wh, wl;
            bsplit2_fast(p0, p1, wh, wl);
            Ph[gid * ASTR + w] = wh; Pl[gid * ASTR + w] = wl;
            bsplit2_fast(p2, p3, wh, wl);
            Ph[(gid + 8) * ASTR + w] = wh; Pl[(gid + 8) * ASTR + w] = wl;
        }
        ls0 += __shfl_xor_sync(0xffffffffu, ls0, 1);
        ls0 += __shfl_xor_sync(0xffffffffu, ls0, 2);
        ls1 += __shfl_xor_sync(0xffffffffu, ls1, 1);
        ls1 += __shfl_xor_sync(0xffffffffu, ls1, 2);
        l0 = l0 * corr0 + ls0;
        l1 = l1 * corr1 + ls1;
        m0 = mn0; m1 = mn1;

#pragma unroll
        for (int df = 0; df < 8; df++) {
            o[df][0] *= corr0; o[df][1] *= corr0;
            o[df][2] *= corr1; o[df][3] *= corr1;
        }
        __syncwarp();

        // ---- o += P V (split-bf16); A = P (warp-private), B = V^T ----
#pragma unroll
        for (int ch = 0; ch < 4; ch++) {
            int kk = ch * 8;
            uint32_t ph[4], pl[4];
            ph[0] = Ph[gid * ASTR + kk + tig];
            ph[1] = Ph[(gid + 8) * ASTR + kk + tig];
            ph[2] = Ph[gid * ASTR + kk + tig + 4];
            ph[3] = Ph[(gid + 8) * ASTR + kk + tig + 4];
            pl[0] = Pl[gid * ASTR + kk + tig];
            pl[1] = Pl[(gid + 8) * ASTR + kk + tig];
            pl[2] = Pl[gid * ASTR + kk + tig + 4];
            pl[3] = Pl[(gid + 8) * ASTR + kk + tig + 4];
#pragma unroll
            for (int df = 0; df < 8; df++) {
                int dn = df * 8 + gid;
                uint32_t vh[2], vl[2];
                vh[0] = Vh[dn * ASTR + kk + tig];
                vh[1] = Vh[dn * ASTR + kk + tig + 4];
                vl[0] = Vl[dn * ASTR + kk + tig];
                vl[1] = Vl[dn * ASTR + kk + tig + 4];
                mma_bf16(o[df], pl, vh);
                mma_bf16(o[df], ph, vl);
                mma_bf16(o[df], ph, vh);
            }
        }
    }

    float inv0 = 1.f / l0, inv1 = 1.f / l1;
    float* op0 = out + (long)rowg0 * C + h * HD;
    float* op1 = out + (long)rowg1 * C + h * HD;
#pragma unroll
    for (int df = 0; df < 8; df++) {
        int colb = df * 8 + 2 * tig;
        *(float2*)&op0[colb] = make_float2(o[df][0] * inv0, o[df][1] * inv0);
        *(float2*)&op1[colb] = make_float2(o[df][2] * inv1, o[df][3] * inv1);
    }
}

// ---------------- MoE gate: logits + top-2 + softmax ----------------
__global__ __launch_bounds__(256) void gate_kernel(const float* __restrict__ xn,
                                                   const float* __restrict__ gw,
                                                   int* __restrict__ tope,
                                                   float* __restrict__ tops)
{
    int t = blockIdx.x;
    int w = threadIdx.x >> 5, lane = threadIdx.x & 31;
    const float* x  = xn + (long)t * C;
    const float* gr = gw + (long)w * C;
    float s = 0.f;
    for (int c = lane * 4; c < C; c += 128) {
        float4 a = *(const float4*)&x[c];
        float4 b = *(const float4*)&gr[c];
        s += a.x * b.x + a.y * b.y + a.z * b.z + a.w * b.w;
    }
#pragma unroll
    for (int off = 16; off; off >>= 1) s += __shfl_xor_sync(0xffffffffu, s, off);
    __shared__ float lg[NE];
    if (lane == 0) lg[w] = s;
    __syncthreads();
    if (threadIdx.x == 0) {
        int i0 = 0;
#pragma unroll
        for (int e2 = 1; e2 < NE; e2++) if (lg[e2] > lg[i0]) i0 = e2;
        int i1 = (i0 == 0) ? 1 : 0;
#pragma unroll
        for (int e2 = 0; e2 < NE; e2++) if (e2 != i0 && lg[e2] > lg[i1]) i1 = e2;
        float ex = __expf(lg[i1] - lg[i0]);
        float s0 = 1.f / (1.f + ex);
        tope[t * 2]     = i0; tope[t * 2 + 1] = i1;
        tops[t * 2]     = s0; tops[t * 2 + 1] = 1.f - s0;
    }
}

// ---------------- routing compaction (single block; int atomics only) --------
__global__ void scatter_kernel(const int* __restrict__ tope)
{
    __shared__ int cnt[NE];
    __shared__ int off[NE + 1];
    int tid = threadIdx.x;
    if (tid < NE) cnt[tid] = 0;
    __syncthreads();
    for (int p = tid; p < P; p += 256) atomicAdd(&cnt[tope[p]], 1);
    __syncthreads();
    if (tid == 0) {
        off[0] = 0;
        for (int e = 0; e < NE; e++) off[e + 1] = off[e] + cnt[e];
        for (int e = 0; e <= NE; e++) g_off[e] = off[e];
    }
    __syncthreads();
    if (tid < NE) cnt[tid] = off[tid];
    __syncthreads();
    for (int p = tid; p < P; p += 256) {
        int e2  = tope[p];
        int pos = atomicAdd(&cnt[e2], 1);
        g_pairtok[pos] = p >> 1;   // token index
        g_tokpos[p] = pos;
    }
}

// ---------------- MoE combine: x += s0*y[p0] + s1*y[p1] ----------------
__global__ __launch_bounds__(192) void combine_kernel(
    const float* __restrict__ ybuf, const float* __restrict__ tops,
    const int* __restrict__ tokpos, float* x)
{
    int t = blockIdx.x;
    int c = threadIdx.x * 4;
    int p0 = tokpos[t * 2], p1 = tokpos[t * 2 + 1];
    float w0 = tops[t * 2], w1 = tops[t * 2 + 1];
    float4 a  = *(const float4*)&ybuf[(long)p0 * C + c];
    float4 b  = *(const float4*)&ybuf[(long)p1 * C + c];
    float4 xv = *(float4*)&x[(long)t * C + c];
    xv.x += w0 * a.x + w1 * b.x;
    xv.y += w0 * a.y + w1 * b.y;
    xv.z += w0 * a.z + w1 * b.z;
    xv.w += w0 * a.w + w1 * b.w;
    *(float4*)&x[(long)t * C + c] = xv;
}

// ---------------- lm head: logits[v] = dot(x_last, wte[v]) ----------------
__global__ __launch_bounds__(256) void lmhead_kernel(
    const float* __restrict__ xn, const float* __restrict__ wte,
    float* __restrict__ out)
{
    __shared__ float4 xs[C / 4];
    const float* x = xn + (long)(T - 1) * C;
    for (int ii = threadIdx.x; ii < C / 4; ii += 256) xs[ii] = *(const float4*)&x[ii * 4];
    __syncthreads();
    int w = threadIdx.x >> 5, lane = threadIdx.x & 31;
    int v = blockIdx.x * 8 + w;
    if (v >= V) return;
    const float* wr = wte + (long)v * C;
    float s = 0.f;
    for (int c = lane; c < C / 4; c += 32) {
        float4 a = *(const float4*)&wr[c * 4];
        float4 b = xs[c];
        s += a.x * b.x + a.y * b.y + a.z * b.z + a.w * b.w;
    }
#pragma unroll
    for (int off = 16; off; off >>= 1) s += __shfl_xor_sync(0xffffffffu, s, off);
    if (lane == 0) out[v] = s;
}

// ---------------- launch ----------------
extern "C" void kernel_launch(void* const* d_in, const int* in_sizes, int n_in,
                              void* d_out, int out_size)
{
    const int*   idx   = (const int*)d_in[0];
    const float* wte   = (const float*)d_in[1];
    const float* wpe   = (const float*)d_in[2];
    const float* ln1g  = (const float*)d_in[3];
    const float* qkvw  = (const float*)d_in[4];
    const float* projw = (const float*)d_in[5];
    const float* ln2g  = (const float*)d_in[6];
    const float* gatew = (const float*)d_in[7];
    const float* w1    = (const float*)d_in[8];
    const float* w2    = (const float*)d_in[9];
    const float* lnfg  = (const float*)d_in[10];
    float* out = (float*)d_out;

    float *p_x, *p_xn, *p_qkv, *p_attno, *p_h, *p_y, *p_part, *p_tops;
    int *p_tope, *p_tokpos, *p_pairtok, *p_off;
    cudaGetSymbolAddress((void**)&p_x,       g_x);
    cudaGetSymbolAddress((void**)&p_xn,      g_xn);
    cudaGetSymbolAddress((void**)&p_qkv,     g_qkv);
    cudaGetSymbolAddress((void**)&p_attno,   g_attno);
    cudaGetSymbolAddress((void**)&p_h,       g_h);
    cudaGetSymbolAddress((void**)&p_y,       g_y);
    cudaGetSymbolAddress((void**)&p_part,    g_part);
    cudaGetSymbolAddress((void**)&p_tops,    g_tops);
    cudaGetSymbolAddress((void**)&p_tope,    g_tope);
    cudaGetSymbolAddress((void**)&p_tokpos,  g_tokpos);
    cudaGetSymbolAddress((void**)&p_pairtok, g_pairtok);
    cudaGetSymbolAddress((void**)&p_off,     g_off);

    cudaFuncSetAttribute(attn_kernel,
                         cudaFuncAttributeMaxDynamicSharedMemorySize, ATTN_SMEM);
    cudaFuncSetAttribute(sgemm_kernel,
                         cudaFuncAttributeMaxDynamicSharedMemorySize, SGEMM_SMEM);

    embed_kernel<<<T, C / 4>>>(idx, wte, wpe, p_x);

    for (int l = 0; l < 2; l++) {
        layernorm_kernel<<<T, 256>>>(p_x, p_xn, ln1g + (long)l * C, 0);
        sgemm_kernel<<<dim3(3 * C / BN, T / BM, 1), 256, SGEMM_SMEM>>>(
            p_xn, C, qkvw + (long)l * 3 * C * C, 0, 3 * C, C,
            p_qkv, 3 * C, nullptr, nullptr, nullptr, T, 0,
            1, nullptr, 0);
        attn_kernel<<<dim3(T / 64, NH), 128, ATTN_SMEM>>>(p_qkv, p_attno);
        // proj: split-K x4 -> partials, then reduce (+residual x)
        sgemm_kernel<<<dim3(C / BN, T / BM, KSPL), 256, SGEMM_SMEM>>>(
            p_attno, C, projw + (long)l * C * C, 0, C, C,
            nullptr, C, nullptr, nullptr, nullptr, T, 0,
            KSPL, p_part, (long)T * C);
        reduce_kernel<<<T * C / 1024, 256>>>(p_part, (long)T * C, p_x, 1);

        layernorm_kernel<<<T, 256>>>(p_x, p_xn, ln2g + (long)l * C, 0);
        gate_kernel<<<T, 256>>>(p_xn, gatew + (long)l * NE * C, p_tope, p_tops);
        scatter_kernel<<<1, 256>>>(p_tope);
        sgemm_kernel<<<dim3(C4 / BN, P / BM, NE), 256, SGEMM_SMEM>>>(
            p_xn, C, w1 + (long)l * NE * C4 * C, (long)C4 * C, C4, C,
            p_h, C4, nullptr, p_off, p_pairtok, 0, 1,
            1, nullptr, 0);
        // w2: split-K x4 -> partials, then reduce into y
        sgemm_kernel<<<dim3(C / BN, P / BM, NE * KSPL), 256, SGEMM_SMEM>>>(
            p_h, C4, w2 + (long)l * NE * C * C4, (long)C * C4, C, C4,
            nullptr, C, nullptr, p_off, nullptr, 0, 0,
            KSPL, p_part, (long)P * C);
        reduce_kernel<<<P * C / 1024, 256>>>(p_part, (long)P * C, p_y, 0);
        combine_kernel<<<T, C / 4>>>(p_y, p_tops, p_tokpos, p_x);
    }

    layernorm_kernel<<<1, 256>>>(p_x, p_xn, lnfg, T - 1);
    lmhead_kernel<<<(V + 7) / 8, 256>>>(p_xn, wte, out);
}